// round 2
// baseline (speedup 1.0000x reference)
#include <cuda_runtime.h>
#include <math.h>

// Problem constants
constexpr int N_B   = 4;
constexpr int SEQ_T = 2048;
constexpr int N_P   = 16;
constexpr int JD    = 256;
constexpr int NH    = 4;
constexpr int DH    = 16;
constexpr int MEMD  = 64;
constexpr int KOUT  = 192;
constexpr int NSEQ  = N_B * N_P;        // 64
constexpr int NT    = NSEQ * SEQ_T;     // 131072 tokens
constexpr int NPAD  = 256;              // padded projection width (200 -> 256)
constexpr float EPS_LN = 1e-5f;

// ---------------- scratch (device globals; allocation-free) ----------------
__device__ float g_wpack[JD * NPAD];                     // [k][n] packed proj weights
__device__ float g_wtr[MEMD * KOUT];                     // out_w transposed [m][k]
__device__ float g_q[(size_t)NSEQ * NH * SEQ_T * DH];
__device__ float g_k[(size_t)NSEQ * NH * SEQ_T * DH];
__device__ float g_v[(size_t)NSEQ * NH * SEQ_T * DH];
__device__ float g_o[(size_t)NSEQ * NH * SEQ_T * DH];
__device__ float g_beta[NSEQ * NH * SEQ_T];
__device__ float g_alpha[NSEQ * NH * SEQ_T];

// ---------------- f32x2 helpers (Blackwell packed fp32) ----------------
__device__ __forceinline__ unsigned long long dup2(float x) {
    unsigned long long r;
    unsigned int xi = __float_as_uint(x);
    asm("mov.b64 %0, {%1, %1};" : "=l"(r) : "r"(xi));
    return r;
}
__device__ __forceinline__ void fma2(unsigned long long& acc, unsigned long long a,
                                     unsigned long long b) {
    asm("fma.rn.f32x2 %0, %1, %2, %0;" : "+l"(acc) : "l"(a), "l"(b));
}
__device__ __forceinline__ float lo32(unsigned long long v) {
    return __uint_as_float((unsigned int)(v & 0xffffffffull));
}
__device__ __forceinline__ float hi32(unsigned long long v) {
    return __uint_as_float((unsigned int)(v >> 32));
}

__device__ __forceinline__ float sigm(float x) { return 1.0f / (1.0f + expf(-x)); }

// ---------------- kernel 0a: pack projection weights into [k][n] ----------------
__global__ void pack_w(const float* __restrict__ Wq, const float* __restrict__ Wk,
                       const float* __restrict__ Wv, const float* __restrict__ Wbw,
                       const float* __restrict__ Waw) {
    int idx = blockIdx.x * blockDim.x + threadIdx.x;
    if (idx >= JD * NPAD) return;
    int k = idx / NPAD;
    int n = idx % NPAD;
    float val = 0.0f;
    if (n < 64)        val = Wq[n * JD + k];
    else if (n < 128)  val = Wk[(n - 64) * JD + k];
    else if (n < 192)  val = Wv[(n - 128) * JD + k];
    else if (n < 196)  val = Wbw[(n - 192) * JD + k];
    else if (n < 200)  val = Waw[(n - 196) * JD + k];
    g_wpack[idx] = val;
}

// ---------------- kernel 0b: transpose out_w to [m][k] ----------------
__global__ void pack_outw(const float* __restrict__ out_w) {
    int idx = blockIdx.x * blockDim.x + threadIdx.x;
    if (idx >= KOUT * MEMD) return;
    int k = idx / MEMD;
    int m = idx % MEMD;
    g_wtr[m * KOUT + k] = out_w[idx];
}

// ---------------- kernel 1: fused projection GEMM + epilogue ----------------
// BM=64, BN=256 (full width), BK=16, 256 threads.
// Thread tile: 4 rows x 16 cols, where the 16 cols = one head slice (tx):
//   tx 0-3: q heads, 4-7: k heads, 8-11: v heads, 12: gates, 13-15: padding.
// LN / k-normalize / sigmoid gates run in registers, then scatter to
// g_q/g_k/g_v/g_beta/g_alpha in scan layout. No g_proj round-trip.
__global__ __launch_bounds__(256, 2) void gemm_fused(
        const float* __restrict__ X,
        const float* __restrict__ curv, const float* __restrict__ ent,
        const float* __restrict__ Wbb,  const float* __restrict__ Wab,
        const float* __restrict__ curv_w, const float* __restrict__ ent_w,
        const float* __restrict__ lnqw, const float* __restrict__ lnqb,
        const float* __restrict__ lnkw, const float* __restrict__ lnkb) {
    __shared__ float As[16][68];          // [kk][row], padded stride (16B-aligned)
    __shared__ float Bs[16 * 256];        // [kk][c*64 + tx*4 + e] chunk-interleaved

    int tid = threadIdx.x;
    int tx = tid & 15;                    // col segment (head slice)
    int ty = tid >> 4;                    // row group of 4
    int m0 = blockIdx.x * 64;

    unsigned long long acc[4][8];
#pragma unroll
    for (int r = 0; r < 4; r++)
#pragma unroll
        for (int p = 0; p < 8; p++) acc[r][p] = 0ull;

    // A-staging indices: f = tid -> row = f>>2, kq = f&3 (one float4 per thread)
    int arow = tid >> 2;
    int akq = tid & 3;

    for (int k0 = 0; k0 < JD; k0 += 16) {
        __syncthreads();
        {   // stage A (transpose to k-major)
            float4 av = *(const float4*)(X + (size_t)(m0 + arow) * JD + k0 + akq * 4);
            As[akq * 4 + 0][arow] = av.x;
            As[akq * 4 + 1][arow] = av.y;
            As[akq * 4 + 2][arow] = av.z;
            As[akq * 4 + 3][arow] = av.w;
        }
        // stage B, chunk-interleaved: global col j = btx*16 + bc*4 + e
#pragma unroll
        for (int r = 0; r < 4; r++) {
            int f = tid + 256 * r;
            int btx = f & 15;
            int bc = (f >> 4) & 3;
            int bkk = f >> 6;
            float4 bv = *(const float4*)(g_wpack + (size_t)(k0 + bkk) * NPAD + btx * 16 + bc * 4);
            *(float4*)(&Bs[bkk * 256 + bc * 64 + btx * 4]) = bv;
        }
        __syncthreads();
#pragma unroll
        for (int kk = 0; kk < 16; kk++) {
            float4 a = *(const float4*)(&As[kk][ty * 4]);   // broadcast within half-warp
            unsigned long long ad[4];
            ad[0] = dup2(a.x); ad[1] = dup2(a.y); ad[2] = dup2(a.z); ad[3] = dup2(a.w);
            unsigned long long b[8];
#pragma unroll
            for (int c = 0; c < 4; c++) {
                const unsigned long long* bp =
                    (const unsigned long long*)(&Bs[kk * 256 + c * 64 + tx * 4]);
                b[c * 2 + 0] = bp[0];
                b[c * 2 + 1] = bp[1];
            }
#pragma unroll
            for (int r = 0; r < 4; r++)
#pragma unroll
                for (int p = 0; p < 8; p++) fma2(acc[r][p], ad[r], b[p]);
        }
    }

    // ---------------- fused epilogue (registers only) ----------------
    if (tx >= 13) return;

    if (tx < 4) {
        // q head h = tx : LayerNorm
        float w16[16], b16[16];
#pragma unroll
        for (int i = 0; i < 16; i++) { w16[i] = __ldg(lnqw + i); b16[i] = __ldg(lnqb + i); }
#pragma unroll
        for (int r = 0; r < 4; r++) {
            float y[16];
#pragma unroll
            for (int p = 0; p < 8; p++) { y[p * 2] = lo32(acc[r][p]); y[p * 2 + 1] = hi32(acc[r][p]); }
            float s = 0.0f;
#pragma unroll
            for (int i = 0; i < 16; i++) s += y[i];
            float mean = s * 0.0625f;
            float var = 0.0f;
#pragma unroll
            for (int i = 0; i < 16; i++) { float d = y[i] - mean; var = fmaf(d, d, var); }
            var *= 0.0625f;
            float inv = rsqrtf(var + EPS_LN);
#pragma unroll
            for (int i = 0; i < 16; i++) y[i] = fmaf((y[i] - mean) * inv, w16[i], b16[i]);
            int mt = m0 + ty * 4 + r;
            int n = mt >> 11, t = mt & 2047;
            size_t base = ((size_t)(n * NH + tx) * SEQ_T + t) * DH;
            *(float4*)(g_q + base + 0)  = *(float4*)&y[0];
            *(float4*)(g_q + base + 4)  = *(float4*)&y[4];
            *(float4*)(g_q + base + 8)  = *(float4*)&y[8];
            *(float4*)(g_q + base + 12) = *(float4*)&y[12];
        }
    } else if (tx < 8) {
        // k head h = tx-4 : LayerNorm + L2 normalize
        int h = tx - 4;
        float w16[16], b16[16];
#pragma unroll
        for (int i = 0; i < 16; i++) { w16[i] = __ldg(lnkw + i); b16[i] = __ldg(lnkb + i); }
#pragma unroll
        for (int r = 0; r < 4; r++) {
            float y[16];
#pragma unroll
            for (int p = 0; p < 8; p++) { y[p * 2] = lo32(acc[r][p]); y[p * 2 + 1] = hi32(acc[r][p]); }
            float s = 0.0f;
#pragma unroll
            for (int i = 0; i < 16; i++) s += y[i];
            float mean = s * 0.0625f;
            float var = 0.0f;
#pragma unroll
            for (int i = 0; i < 16; i++) { float d = y[i] - mean; var = fmaf(d, d, var); }
            var *= 0.0625f;
            float inv = rsqrtf(var + EPS_LN);
#pragma unroll
            for (int i = 0; i < 16; i++) y[i] = fmaf((y[i] - mean) * inv, w16[i], b16[i]);
            float nrm = 0.0f;
#pragma unroll
            for (int i = 0; i < 16; i++) nrm = fmaf(y[i], y[i], nrm);
            float rinv = 1.0f / fmaxf(sqrtf(nrm), 1e-12f);
#pragma unroll
            for (int i = 0; i < 16; i++) y[i] *= rinv;
            int mt = m0 + ty * 4 + r;
            int n = mt >> 11, t = mt & 2047;
            size_t base = ((size_t)(n * NH + h) * SEQ_T + t) * DH;
            *(float4*)(g_k + base + 0)  = *(float4*)&y[0];
            *(float4*)(g_k + base + 4)  = *(float4*)&y[4];
            *(float4*)(g_k + base + 8)  = *(float4*)&y[8];
            *(float4*)(g_k + base + 12) = *(float4*)&y[12];
        }
    } else if (tx < 12) {
        // v head h = tx-8 : raw write
        int h = tx - 8;
#pragma unroll
        for (int r = 0; r < 4; r++) {
            float y[16];
#pragma unroll
            for (int p = 0; p < 8; p++) { y[p * 2] = lo32(acc[r][p]); y[p * 2 + 1] = hi32(acc[r][p]); }
            int mt = m0 + ty * 4 + r;
            int n = mt >> 11, t = mt & 2047;
            size_t base = ((size_t)(n * NH + h) * SEQ_T + t) * DH;
            *(float4*)(g_v + base + 0)  = *(float4*)&y[0];
            *(float4*)(g_v + base + 4)  = *(float4*)&y[4];
            *(float4*)(g_v + base + 8)  = *(float4*)&y[8];
            *(float4*)(g_v + base + 12) = *(float4*)&y[12];
        }
    } else {
        // tx == 12: gates. cols 192..207 -> beta_pre = e==h, alpha_pre = e==4+h
#pragma unroll
        for (int r = 0; r < 4; r++) {
            float y[16];
#pragma unroll
            for (int p = 0; p < 8; p++) { y[p * 2] = lo32(acc[r][p]); y[p * 2 + 1] = hi32(acc[r][p]); }
            int mt = m0 + ty * 4 + r;
            int n = mt >> 11, t = mt & 2047;
            int b = n >> 4;
            float Kv = fminf(fabsf(__ldg(curv + b)), 10.0f);
            float Sv = fminf(fmaxf(__ldg(ent + b), 0.0f), 5.0f);
#pragma unroll
            for (int h = 0; h < 4; h++) {
                float be = sigm(y[h] + __ldg(Wbb + h));
                be = sigm(fmaf(Kv, __ldg(curv_w + h), be));
                float al = sigm(y[4 + h] + __ldg(Wab + h));
                al = sigm(fmaf(Sv, __ldg(ent_w + h), al));
                g_beta[(n * NH + h) * SEQ_T + t] = be;
                g_alpha[(n * NH + h) * SEQ_T + t] = al;
            }
        }
    }
}

// ---------------- kernel 3: sequential delta-rule scan ----------------
__global__ __launch_bounds__(32) void scan_kernel() {
    __shared__ float sk[2][64][16];
    __shared__ float sv[2][64][16];
    __shared__ float sq[2][64][16];
    __shared__ float sb[2][64];
    __shared__ float sa[2][64];

    int g = threadIdx.x >> 4;
    int lane = threadIdx.x & 15;
    int rec = blockIdx.x * 2 + g;
    size_t base = (size_t)rec * SEQ_T * DH;

    float M[16];
#pragma unroll
    for (int j = 0; j < 16; j++) M[j] = 0.0f;

    for (int c = 0; c < SEQ_T / 64; c++) {
        int t0 = c * 64;
        __syncwarp();
#pragma unroll
        for (int r = 0; r < 16; r++) {
            int f = threadIdx.x + 32 * r;
            int gg = f >> 8;
            int e = f & 255;
            size_t src = ((size_t)(blockIdx.x * 2 + gg) * SEQ_T + t0) * DH;
            ((float4*)&sk[gg][0][0])[e] = ((const float4*)(g_k + src))[e];
            ((float4*)&sv[gg][0][0])[e] = ((const float4*)(g_v + src))[e];
            ((float4*)&sq[gg][0][0])[e] = ((const float4*)(g_q + src))[e];
        }
#pragma unroll
        for (int r = 0; r < 4; r++) {
            int f = threadIdx.x + 32 * r;
            int gg = f >> 6;
            int e = f & 63;
            sb[gg][e] = g_beta[(blockIdx.x * 2 + gg) * SEQ_T + t0 + e];
            sa[gg][e] = g_alpha[(blockIdx.x * 2 + gg) * SEQ_T + t0 + e];
        }
        __syncwarp();

        for (int s = 0; s < 64; s++) {
            float kr[16], qr[16];
            *(float4*)&kr[0]  = *(const float4*)&sk[g][s][0];
            *(float4*)&kr[4]  = *(const float4*)&sk[g][s][4];
            *(float4*)&kr[8]  = *(const float4*)&sk[g][s][8];
            *(float4*)&kr[12] = *(const float4*)&sk[g][s][12];
            *(float4*)&qr[0]  = *(const float4*)&sq[g][s][0];
            *(float4*)&qr[4]  = *(const float4*)&sq[g][s][4];
            *(float4*)&qr[8]  = *(const float4*)&sq[g][s][8];
            *(float4*)&qr[12] = *(const float4*)&sq[g][s][12];
            float vi = sv[g][s][lane];
            float be = sb[g][s];
            float al = sa[g][s];

            float p0 = M[0] * kr[0], p1 = M[1] * kr[1];
            float p2 = M[2] * kr[2], p3 = M[3] * kr[3];
#pragma unroll
            for (int j = 4; j < 16; j += 4) {
                p0 = fmaf(M[j + 0], kr[j + 0], p0);
                p1 = fmaf(M[j + 1], kr[j + 1], p1);
                p2 = fmaf(M[j + 2], kr[j + 2], p2);
                p3 = fmaf(M[j + 3], kr[j + 3], p3);
            }
            float mk = (p0 + p1) + (p2 + p3);
            float cc = fmaf(be, vi, -al * mk);

            float o0 = 0.0f, o1 = 0.0f, o2 = 0.0f, o3 = 0.0f;
#pragma unroll
            for (int j = 0; j < 16; j += 4) {
                M[j + 0] = fmaf(cc, kr[j + 0], M[j + 0]); o0 = fmaf(M[j + 0], qr[j + 0], o0);
                M[j + 1] = fmaf(cc, kr[j + 1], M[j + 1]); o1 = fmaf(M[j + 1], qr[j + 1], o1);
                M[j + 2] = fmaf(cc, kr[j + 2], M[j + 2]); o2 = fmaf(M[j + 2], qr[j + 2], o2);
                M[j + 3] = fmaf(cc, kr[j + 3], M[j + 3]); o3 = fmaf(M[j + 3], qr[j + 3], o3);
            }
            g_o[base + (size_t)(t0 + s) * DH + lane] = (o0 + o1) + (o2 + o3);
        }
    }
}

// ---------------- kernel 4: output projection + permuted write ----------------
__global__ __launch_bounds__(192) void final_proj(const float* __restrict__ out_b,
                                                  float* __restrict__ out) {
    __shared__ float so[64][20];
    int n = blockIdx.x;
    int tbase = blockIdx.y * 128;
    int kk = threadIdx.x;
    float bias = out_b[kk];
    int b = n >> 4;
    int p = n & 15;

    for (int tile = 0; tile < 8; tile++) {
        int t0 = tbase + tile * 16;
        __syncthreads();
#pragma unroll
        for (int r = 0; r < 6; r++) {
            int e = kk + 192 * r;
            if (e < 1024) {
                int h = e >> 8;
                int tt = (e >> 4) & 15;
                int i = e & 15;
                so[h * 16 + i][tt] =
                    g_o[((size_t)(n * NH + h) * SEQ_T + t0 + tt) * DH + i];
            }
        }
        __syncthreads();

        float acc[16];
#pragma unroll
        for (int tt = 0; tt < 16; tt++) acc[tt] = 0.0f;
#pragma unroll 4
        for (int m = 0; m < 64; m++) {
            float w = g_wtr[m * KOUT + kk];
            float4 o0 = *(const float4*)&so[m][0];
            float4 o1 = *(const float4*)&so[m][4];
            float4 o2 = *(const float4*)&so[m][8];
            float4 o3 = *(const float4*)&so[m][12];
            acc[0]  = fmaf(w, o0.x, acc[0]);  acc[1]  = fmaf(w, o0.y, acc[1]);
            acc[2]  = fmaf(w, o0.z, acc[2]);  acc[3]  = fmaf(w, o0.w, acc[3]);
            acc[4]  = fmaf(w, o1.x, acc[4]);  acc[5]  = fmaf(w, o1.y, acc[5]);
            acc[6]  = fmaf(w, o1.z, acc[6]);  acc[7]  = fmaf(w, o1.w, acc[7]);
            acc[8]  = fmaf(w, o2.x, acc[8]);  acc[9]  = fmaf(w, o2.y, acc[9]);
            acc[10] = fmaf(w, o2.z, acc[10]); acc[11] = fmaf(w, o2.w, acc[11]);
            acc[12] = fmaf(w, o3.x, acc[12]); acc[13] = fmaf(w, o3.y, acc[13]);
            acc[14] = fmaf(w, o3.z, acc[14]); acc[15] = fmaf(w, o3.w, acc[15]);
        }
#pragma unroll
        for (int tt = 0; tt < 16; tt++) {
            out[(((size_t)b * SEQ_T + t0 + tt) * N_P + p) * KOUT + kk] = acc[tt] + bias;
        }
    }
}

// ---------------- launch ----------------
extern "C" void kernel_launch(void* const* d_in, const int* in_sizes, int n_in,
                              void* d_out, int out_size) {
    const float* joint  = (const float*)d_in[0];
    const float* curvat = (const float*)d_in[1];
    const float* entrop = (const float*)d_in[2];
    const float* Wq     = (const float*)d_in[3];
    const float* Wk     = (const float*)d_in[4];
    const float* Wv     = (const float*)d_in[5];
    const float* Wbw    = (const float*)d_in[6];
    const float* Wbb    = (const float*)d_in[7];
    const float* Waw    = (const float*)d_in[8];
    const float* Wab    = (const float*)d_in[9];
    const float* curv_w = (const float*)d_in[10];
    const float* ent_w  = (const float*)d_in[11];
    const float* out_w  = (const float*)d_in[12];
    const float* out_b  = (const float*)d_in[13];
    const float* lnqw   = (const float*)d_in[14];
    const float* lnqb   = (const float*)d_in[15];
    const float* lnkw   = (const float*)d_in[16];
    const float* lnkb   = (const float*)d_in[17];
    float* out = (float*)d_out;

    pack_w<<<(JD * NPAD + 255) / 256, 256>>>(Wq, Wk, Wv, Wbw, Waw);
    pack_outw<<<(KOUT * MEMD + 255) / 256, 256>>>(out_w);
    gemm_fused<<<NT / 64, 256>>>(joint, curvat, entrop, Wbb, Wab, curv_w, ent_w,
                                 lnqw, lnqb, lnkw, lnkb);
    scan_kernel<<<(NSEQ * NH) / 2, 32>>>();
    final_proj<<<dim3(NSEQ, SEQ_T / 128), 192>>>(out_b, out);
}

// round 3
// speedup vs baseline: 1.1347x; 1.1347x over previous
#include <cuda_runtime.h>
#include <math.h>

// Problem constants
constexpr int N_B   = 4;
constexpr int SEQ_T = 2048;
constexpr int N_P   = 16;
constexpr int JD    = 256;
constexpr int NH    = 4;
constexpr int DH    = 16;
constexpr int MEMD  = 64;
constexpr int KOUT  = 192;
constexpr int NSEQ  = N_B * N_P;        // 64
constexpr int NT    = NSEQ * SEQ_T;     // 131072 tokens
constexpr int NPAD  = 256;
constexpr float EPS_LN = 1e-5f;

// chunked-scan constants
constexpr int CH   = 128;               // chunk length
constexpr int NCH  = SEQ_T / CH;        // 16 chunks
constexpr int NREC = NSEQ * NH;         // 256 recurrences
constexpr int NGRP = NREC * NCH;        // 4096 (rec, chunk) tasks

// ---------------- scratch (device globals; allocation-free) ----------------
__device__ float g_wpack[JD * NPAD];
__device__ float g_wtr[MEMD * KOUT];
__device__ float g_q[(size_t)NREC * SEQ_T * DH];
__device__ float g_k[(size_t)NREC * SEQ_T * DH];
__device__ float g_v[(size_t)NREC * SEQ_T * DH];
__device__ float g_o[(size_t)NREC * SEQ_T * DH];
__device__ float g_beta[NREC * SEQ_T];
__device__ float g_alpha[NREC * SEQ_T];
__device__ float g_P[(size_t)NGRP * 256];   // per-chunk transition matrices
__device__ float g_R[(size_t)NGRP * 256];   // per-chunk inhomogeneous terms
__device__ float g_S[(size_t)NGRP * 256];   // per-chunk entering states

// ---------------- f32x2 helpers (Blackwell packed fp32) ----------------
__device__ __forceinline__ unsigned long long dup2(float x) {
    unsigned long long r;
    unsigned int xi = __float_as_uint(x);
    asm("mov.b64 %0, {%1, %1};" : "=l"(r) : "r"(xi));
    return r;
}
__device__ __forceinline__ unsigned long long pack2(float lo, float hi) {
    unsigned long long r;
    asm("mov.b64 %0, {%1, %2};" : "=l"(r) : "f"(lo), "f"(hi));
    return r;
}
__device__ __forceinline__ void fma2(unsigned long long& acc, unsigned long long a,
                                     unsigned long long b) {
    asm("fma.rn.f32x2 %0, %1, %2, %0;" : "+l"(acc) : "l"(a), "l"(b));
}
__device__ __forceinline__ unsigned long long mul2(unsigned long long a, unsigned long long b) {
    unsigned long long r;
    asm("mul.rn.f32x2 %0, %1, %2;" : "=l"(r) : "l"(a), "l"(b));
    return r;
}
__device__ __forceinline__ unsigned long long add2(unsigned long long a, unsigned long long b) {
    unsigned long long r;
    asm("add.rn.f32x2 %0, %1, %2;" : "=l"(r) : "l"(a), "l"(b));
    return r;
}
__device__ __forceinline__ float lo32(unsigned long long v) {
    return __uint_as_float((unsigned int)(v & 0xffffffffull));
}
__device__ __forceinline__ float hi32(unsigned long long v) {
    return __uint_as_float((unsigned int)(v >> 32));
}
// row(16) . vec(16), both packed as 8 f32x2
__device__ __forceinline__ float dot16(const unsigned long long* A, const unsigned long long* k) {
    unsigned long long c0 = mul2(A[0], k[0]);
    unsigned long long c1 = mul2(A[1], k[1]);
    unsigned long long c2 = mul2(A[2], k[2]);
    unsigned long long c3 = mul2(A[3], k[3]);
    fma2(c0, A[4], k[4]);
    fma2(c1, A[5], k[5]);
    fma2(c2, A[6], k[6]);
    fma2(c3, A[7], k[7]);
    unsigned long long d0 = add2(c0, c1);
    unsigned long long d1 = add2(c2, c3);
    unsigned long long e = add2(d0, d1);
    return lo32(e) + hi32(e);
}

__device__ __forceinline__ float sigm(float x) { return 1.0f / (1.0f + expf(-x)); }

// ---------------- kernel 0a: pack projection weights into [k][n] ----------------
__global__ void pack_w(const float* __restrict__ Wq, const float* __restrict__ Wk,
                       const float* __restrict__ Wv, const float* __restrict__ Wbw,
                       const float* __restrict__ Waw) {
    int idx = blockIdx.x * blockDim.x + threadIdx.x;
    if (idx >= JD * NPAD) return;
    int k = idx / NPAD;
    int n = idx % NPAD;
    float val = 0.0f;
    if (n < 64)        val = Wq[n * JD + k];
    else if (n < 128)  val = Wk[(n - 64) * JD + k];
    else if (n < 192)  val = Wv[(n - 128) * JD + k];
    else if (n < 196)  val = Wbw[(n - 192) * JD + k];
    else if (n < 200)  val = Waw[(n - 196) * JD + k];
    g_wpack[idx] = val;
}

// ---------------- kernel 0b: transpose out_w to [m][k] ----------------
__global__ void pack_outw(const float* __restrict__ out_w) {
    int idx = blockIdx.x * blockDim.x + threadIdx.x;
    if (idx >= KOUT * MEMD) return;
    int k = idx / MEMD;
    int m = idx % MEMD;
    g_wtr[m * KOUT + k] = out_w[idx];
}

// ---------------- kernel 1: fused projection GEMM + epilogue ----------------
__global__ __launch_bounds__(256, 2) void gemm_fused(
        const float* __restrict__ X,
        const float* __restrict__ curv, const float* __restrict__ ent,
        const float* __restrict__ Wbb,  const float* __restrict__ Wab,
        const float* __restrict__ curv_w, const float* __restrict__ ent_w,
        const float* __restrict__ lnqw, const float* __restrict__ lnqb,
        const float* __restrict__ lnkw, const float* __restrict__ lnkb) {
    __shared__ float As[16][68];
    __shared__ float Bs[16 * 256];

    int tid = threadIdx.x;
    int tx = tid & 15;
    int ty = tid >> 4;
    int m0 = blockIdx.x * 64;

    unsigned long long acc[4][8];
#pragma unroll
    for (int r = 0; r < 4; r++)
#pragma unroll
        for (int p = 0; p < 8; p++) acc[r][p] = 0ull;

    int arow = tid >> 2;
    int akq = tid & 3;

    for (int k0 = 0; k0 < JD; k0 += 16) {
        __syncthreads();
        {
            float4 av = *(const float4*)(X + (size_t)(m0 + arow) * JD + k0 + akq * 4);
            As[akq * 4 + 0][arow] = av.x;
            As[akq * 4 + 1][arow] = av.y;
            As[akq * 4 + 2][arow] = av.z;
            As[akq * 4 + 3][arow] = av.w;
        }
#pragma unroll
        for (int r = 0; r < 4; r++) {
            int f = tid + 256 * r;
            int btx = f & 15;
            int bc = (f >> 4) & 3;
            int bkk = f >> 6;
            float4 bv = *(const float4*)(g_wpack + (size_t)(k0 + bkk) * NPAD + btx * 16 + bc * 4);
            *(float4*)(&Bs[bkk * 256 + bc * 64 + btx * 4]) = bv;
        }
        __syncthreads();
#pragma unroll
        for (int kk = 0; kk < 16; kk++) {
            float4 a = *(const float4*)(&As[kk][ty * 4]);
            unsigned long long ad[4];
            ad[0] = dup2(a.x); ad[1] = dup2(a.y); ad[2] = dup2(a.z); ad[3] = dup2(a.w);
            unsigned long long b[8];
#pragma unroll
            for (int c = 0; c < 4; c++) {
                const unsigned long long* bp =
                    (const unsigned long long*)(&Bs[kk * 256 + c * 64 + tx * 4]);
                b[c * 2 + 0] = bp[0];
                b[c * 2 + 1] = bp[1];
            }
#pragma unroll
            for (int r = 0; r < 4; r++)
#pragma unroll
                for (int p = 0; p < 8; p++) fma2(acc[r][p], ad[r], b[p]);
        }
    }

    if (tx >= 13) return;

    if (tx < 4) {
        float w16[16], b16[16];
#pragma unroll
        for (int i = 0; i < 16; i++) { w16[i] = __ldg(lnqw + i); b16[i] = __ldg(lnqb + i); }
#pragma unroll
        for (int r = 0; r < 4; r++) {
            float y[16];
#pragma unroll
            for (int p = 0; p < 8; p++) { y[p * 2] = lo32(acc[r][p]); y[p * 2 + 1] = hi32(acc[r][p]); }
            float s = 0.0f;
#pragma unroll
            for (int i = 0; i < 16; i++) s += y[i];
            float mean = s * 0.0625f;
            float var = 0.0f;
#pragma unroll
            for (int i = 0; i < 16; i++) { float d = y[i] - mean; var = fmaf(d, d, var); }
            var *= 0.0625f;
            float inv = rsqrtf(var + EPS_LN);
#pragma unroll
            for (int i = 0; i < 16; i++) y[i] = fmaf((y[i] - mean) * inv, w16[i], b16[i]);
            int mt = m0 + ty * 4 + r;
            int n = mt >> 11, t = mt & 2047;
            size_t base = ((size_t)(n * NH + tx) * SEQ_T + t) * DH;
            *(float4*)(g_q + base + 0)  = *(float4*)&y[0];
            *(float4*)(g_q + base + 4)  = *(float4*)&y[4];
            *(float4*)(g_q + base + 8)  = *(float4*)&y[8];
            *(float4*)(g_q + base + 12) = *(float4*)&y[12];
        }
    } else if (tx < 8) {
        int h = tx - 4;
        float w16[16], b16[16];
#pragma unroll
        for (int i = 0; i < 16; i++) { w16[i] = __ldg(lnkw + i); b16[i] = __ldg(lnkb + i); }
#pragma unroll
        for (int r = 0; r < 4; r++) {
            float y[16];
#pragma unroll
            for (int p = 0; p < 8; p++) { y[p * 2] = lo32(acc[r][p]); y[p * 2 + 1] = hi32(acc[r][p]); }
            float s = 0.0f;
#pragma unroll
            for (int i = 0; i < 16; i++) s += y[i];
            float mean = s * 0.0625f;
            float var = 0.0f;
#pragma unroll
            for (int i = 0; i < 16; i++) { float d = y[i] - mean; var = fmaf(d, d, var); }
            var *= 0.0625f;
            float inv = rsqrtf(var + EPS_LN);
#pragma unroll
            for (int i = 0; i < 16; i++) y[i] = fmaf((y[i] - mean) * inv, w16[i], b16[i]);
            float nrm = 0.0f;
#pragma unroll
            for (int i = 0; i < 16; i++) nrm = fmaf(y[i], y[i], nrm);
            float rinv = 1.0f / fmaxf(sqrtf(nrm), 1e-12f);
#pragma unroll
            for (int i = 0; i < 16; i++) y[i] *= rinv;
            int mt = m0 + ty * 4 + r;
            int n = mt >> 11, t = mt & 2047;
            size_t base = ((size_t)(n * NH + h) * SEQ_T + t) * DH;
            *(float4*)(g_k + base + 0)  = *(float4*)&y[0];
            *(float4*)(g_k + base + 4)  = *(float4*)&y[4];
            *(float4*)(g_k + base + 8)  = *(float4*)&y[8];
            *(float4*)(g_k + base + 12) = *(float4*)&y[12];
        }
    } else if (tx < 12) {
        int h = tx - 8;
#pragma unroll
        for (int r = 0; r < 4; r++) {
            float y[16];
#pragma unroll
            for (int p = 0; p < 8; p++) { y[p * 2] = lo32(acc[r][p]); y[p * 2 + 1] = hi32(acc[r][p]); }
            int mt = m0 + ty * 4 + r;
            int n = mt >> 11, t = mt & 2047;
            size_t base = ((size_t)(n * NH + h) * SEQ_T + t) * DH;
            *(float4*)(g_v + base + 0)  = *(float4*)&y[0];
            *(float4*)(g_v + base + 4)  = *(float4*)&y[4];
            *(float4*)(g_v + base + 8)  = *(float4*)&y[8];
            *(float4*)(g_v + base + 12) = *(float4*)&y[12];
        }
    } else {
#pragma unroll
        for (int r = 0; r < 4; r++) {
            float y[16];
#pragma unroll
            for (int p = 0; p < 8; p++) { y[p * 2] = lo32(acc[r][p]); y[p * 2 + 1] = hi32(acc[r][p]); }
            int mt = m0 + ty * 4 + r;
            int n = mt >> 11, t = mt & 2047;
            int b = n >> 4;
            float Kv = fminf(fabsf(__ldg(curv + b)), 10.0f);
            float Sv = fminf(fmaxf(__ldg(ent + b), 0.0f), 5.0f);
#pragma unroll
            for (int h = 0; h < 4; h++) {
                float be = sigm(y[h] + __ldg(Wbb + h));
                be = sigm(fmaf(Kv, __ldg(curv_w + h), be));
                float al = sigm(y[4 + h] + __ldg(Wab + h));
                al = sigm(fmaf(Sv, __ldg(ent_w + h), al));
                g_beta[(n * NH + h) * SEQ_T + t] = be;
                g_alpha[(n * NH + h) * SEQ_T + t] = al;
            }
        }
    }
}

// ---------------- kernel 2a: chunked scan phase1 — per-chunk P, R ----------------
// One 16-lane group per (rec, chunk); 8 groups per 128-thread block.
__global__ __launch_bounds__(128) void scan_phase1() {
    __shared__ float sk[8][512];
    __shared__ float sv[8][512];
    __shared__ float sb[8][32];
    __shared__ float sa[8][32];

    int warp = threadIdx.x >> 5;
    int lane = threadIdx.x & 31;
    int g = lane >> 4;
    int row = lane & 15;
    int wg = warp * 2 + g;
    int grp = blockIdx.x * 8 + wg;

    unsigned long long P[8], R[8];
#pragma unroll
    for (int j = 0; j < 8; j++) { P[j] = 0ull; R[j] = 0ull; }
    P[row >> 1] = (row & 1) ? pack2(0.0f, 1.0f) : pack2(1.0f, 0.0f);

    for (int sub = 0; sub < CH / 32; sub++) {
        __syncwarp();
#pragma unroll
        for (int r = 0; r < 8; r++) {
            int f = lane + 32 * r;
            int gg = f >> 7;
            int e = f & 127;
            int grp2 = blockIdx.x * 8 + warp * 2 + gg;
            int rec2 = grp2 >> 4, ch2 = grp2 & 15;
            size_t base4 = ((size_t)rec2 * SEQ_T + ch2 * CH + sub * 32) * 4;
            ((float4*)sk[warp * 2 + gg])[e] = ((const float4*)g_k)[base4 + e];
            ((float4*)sv[warp * 2 + gg])[e] = ((const float4*)g_v)[base4 + e];
        }
#pragma unroll
        for (int r = 0; r < 2; r++) {
            int f = lane + 32 * r;
            int gg = f >> 5;
            int e = f & 31;
            int grp2 = blockIdx.x * 8 + warp * 2 + gg;
            int rec2 = grp2 >> 4, ch2 = grp2 & 15;
            int src = rec2 * SEQ_T + ch2 * CH + sub * 32 + e;
            sb[warp * 2 + gg][e] = g_beta[src];
            sa[warp * 2 + gg][e] = g_alpha[src];
        }
        __syncwarp();

        for (int s = 0; s < 32; s++) {
            unsigned long long kp[8];
            const unsigned long long* kptr = (const unsigned long long*)&sk[wg][s * 16];
#pragma unroll
            for (int j = 0; j < 8; j++) kp[j] = kptr[j];
            float vi = sv[wg][s * 16 + row];
            float be = sb[wg][s];
            float al = sa[wg][s];

            float u = dot16(P, kp);
            float w = dot16(R, kp);
            unsigned long long cu = dup2(-al * u);
            unsigned long long cr = dup2(fmaf(be, vi, -al * w));
#pragma unroll
            for (int j = 0; j < 8; j++) {
                fma2(P[j], cu, kp[j]);
                fma2(R[j], cr, kp[j]);
            }
        }
    }

    size_t obase = ((size_t)grp * 16 + row) * 16;
    unsigned long long* gp = (unsigned long long*)(g_P + obase);
    unsigned long long* gr = (unsigned long long*)(g_R + obase);
#pragma unroll
    for (int j = 0; j < 8; j++) { gp[j] = P[j]; gr[j] = R[j]; }
}

// ---------------- kernel 2b: serial combine — entering states S_c ----------------
// S_enter(0)=0; S_enter(c+1) = S_enter(c) * P_c + R_c. One 16-lane group per rec.
__global__ __launch_bounds__(128) void scan_combine() {
    __shared__ float sp[8][256];
    __shared__ float sr[8][256];

    int warp = threadIdx.x >> 5;
    int lane = threadIdx.x & 31;
    int g = lane >> 4;
    int row = lane & 15;
    int wg = warp * 2 + g;
    int rec = blockIdx.x * 8 + wg;

    unsigned long long S[8];
#pragma unroll
    for (int j = 0; j < 8; j++) S[j] = 0ull;

    for (int c = 0; c < NCH; c++) {
        size_t sbase = (((size_t)rec * NCH + c) * 16 + row) * 16;
        unsigned long long* gs = (unsigned long long*)(g_S + sbase);
#pragma unroll
        for (int j = 0; j < 8; j++) gs[j] = S[j];

        __syncwarp();
#pragma unroll
        for (int r = 0; r < 4; r++) {
            int f = lane + 32 * r;
            int gg = f >> 6;
            int e = f & 63;
            int rec2 = blockIdx.x * 8 + warp * 2 + gg;
            size_t base4 = ((size_t)rec2 * NCH + c) * 64;
            ((float4*)sp[warp * 2 + gg])[e] = ((const float4*)g_P)[base4 + e];
            ((float4*)sr[warp * 2 + gg])[e] = ((const float4*)g_R)[base4 + e];
        }
        __syncwarp();

        unsigned long long accm[8];
        const unsigned long long* rrow = (const unsigned long long*)&sr[wg][row * 16];
#pragma unroll
        for (int j = 0; j < 8; j++) accm[j] = rrow[j];
#pragma unroll
        for (int l = 0; l < 16; l++) {
            float sl = (l & 1) ? hi32(S[l >> 1]) : lo32(S[l >> 1]);
            unsigned long long sd = dup2(sl);
            const unsigned long long* prow = (const unsigned long long*)&sp[wg][l * 16];
#pragma unroll
            for (int j = 0; j < 8; j++) fma2(accm[j], sd, prow[j]);
        }
#pragma unroll
        for (int j = 0; j < 8; j++) S[j] = accm[j];
    }
}

// ---------------- kernel 2c: chunked scan phase3 — outputs ----------------
__global__ __launch_bounds__(128) void scan_phase3() {
    __shared__ float sk[8][512];
    __shared__ float sq[8][512];
    __shared__ float sv[8][512];
    __shared__ float sb[8][32];
    __shared__ float sa[8][32];

    int warp = threadIdx.x >> 5;
    int lane = threadIdx.x & 31;
    int g = lane >> 4;
    int row = lane & 15;
    int wg = warp * 2 + g;
    int grp = blockIdx.x * 8 + wg;

    unsigned long long M[8];
    {
        size_t sbase = ((size_t)grp * 16 + row) * 16;
        const unsigned long long* gs = (const unsigned long long*)(g_S + sbase);
#pragma unroll
        for (int j = 0; j < 8; j++) M[j] = gs[j];
    }

    for (int sub = 0; sub < CH / 32; sub++) {
        __syncwarp();
#pragma unroll
        for (int r = 0; r < 8; r++) {
            int f = lane + 32 * r;
            int gg = f >> 7;
            int e = f & 127;
            int grp2 = blockIdx.x * 8 + warp * 2 + gg;
            int rec2 = grp2 >> 4, ch2 = grp2 & 15;
            size_t base4 = ((size_t)rec2 * SEQ_T + ch2 * CH + sub * 32) * 4;
            ((float4*)sk[warp * 2 + gg])[e] = ((const float4*)g_k)[base4 + e];
            ((float4*)sq[warp * 2 + gg])[e] = ((const float4*)g_q)[base4 + e];
            ((float4*)sv[warp * 2 + gg])[e] = ((const float4*)g_v)[base4 + e];
        }
#pragma unroll
        for (int r = 0; r < 2; r++) {
            int f = lane + 32 * r;
            int gg = f >> 5;
            int e = f & 31;
            int grp2 = blockIdx.x * 8 + warp * 2 + gg;
            int rec2 = grp2 >> 4, ch2 = grp2 & 15;
            int src = rec2 * SEQ_T + ch2 * CH + sub * 32 + e;
            sb[warp * 2 + gg][e] = g_beta[src];
            sa[warp * 2 + gg][e] = g_alpha[src];
        }
        __syncwarp();

        for (int s = 0; s < 32; s++) {
            unsigned long long kp[8], qp[8];
            const unsigned long long* kptr = (const unsigned long long*)&sk[wg][s * 16];
            const unsigned long long* qptr = (const unsigned long long*)&sq[wg][s * 16];
#pragma unroll
            for (int j = 0; j < 8; j++) { kp[j] = kptr[j]; qp[j] = qptr[j]; }
            float vi = sv[wg][s * 16 + row];
            float be = sb[wg][s];
            float al = sa[wg][s];

            float mk = dot16(M, kp);
            unsigned long long cd = dup2(fmaf(be, vi, -al * mk));
#pragma unroll
            for (int j = 0; j < 8; j++) fma2(M[j], cd, kp[j]);
            float o = dot16(M, qp);
            sv[wg][s * 16 + row] = o;   // overwrite v slot with output
        }
        __syncwarp();
        // bulk-store outputs
#pragma unroll
        for (int r = 0; r < 8; r++) {
            int f = lane + 32 * r;
            int gg = f >> 7;
            int e = f & 127;
            int grp2 = blockIdx.x * 8 + warp * 2 + gg;
            int rec2 = grp2 >> 4, ch2 = grp2 & 15;
            size_t base4 = ((size_t)rec2 * SEQ_T + ch2 * CH + sub * 32) * 4;
            ((float4*)g_o)[base4 + e] = ((const float4*)sv[warp * 2 + gg])[e];
        }
    }
}

// ---------------- kernel 4: output projection + permuted write ----------------
__global__ __launch_bounds__(192) void final_proj(const float* __restrict__ out_b,
                                                  float* __restrict__ out) {
    __shared__ float so[64][20];
    int n = blockIdx.x;
    int tbase = blockIdx.y * 128;
    int kk = threadIdx.x;
    float bias = out_b[kk];
    int b = n >> 4;
    int p = n & 15;

    for (int tile = 0; tile < 8; tile++) {
        int t0 = tbase + tile * 16;
        __syncthreads();
#pragma unroll
        for (int r = 0; r < 6; r++) {
            int e = kk + 192 * r;
            if (e < 1024) {
                int h = e >> 8;
                int tt = (e >> 4) & 15;
                int i = e & 15;
                so[h * 16 + i][tt] =
                    g_o[((size_t)(n * NH + h) * SEQ_T + t0 + tt) * DH + i];
            }
        }
        __syncthreads();

        float acc[16];
#pragma unroll
        for (int tt = 0; tt < 16; tt++) acc[tt] = 0.0f;
#pragma unroll 4
        for (int m = 0; m < 64; m++) {
            float w = g_wtr[m * KOUT + kk];
            float4 o0 = *(const float4*)&so[m][0];
            float4 o1 = *(const float4*)&so[m][4];
            float4 o2 = *(const float4*)&so[m][8];
            float4 o3 = *(const float4*)&so[m][12];
            acc[0]  = fmaf(w, o0.x, acc[0]);  acc[1]  = fmaf(w, o0.y, acc[1]);
            acc[2]  = fmaf(w, o0.z, acc[2]);  acc[3]  = fmaf(w, o0.w, acc[3]);
            acc[4]  = fmaf(w, o1.x, acc[4]);  acc[5]  = fmaf(w, o1.y, acc[5]);
            acc[6]  = fmaf(w, o1.z, acc[6]);  acc[7]  = fmaf(w, o1.w, acc[7]);
            acc[8]  = fmaf(w, o2.x, acc[8]);  acc[9]  = fmaf(w, o2.y, acc[9]);
            acc[10] = fmaf(w, o2.z, acc[10]); acc[11] = fmaf(w, o2.w, acc[11]);
            acc[12] = fmaf(w, o3.x, acc[12]); acc[13] = fmaf(w, o3.y, acc[13]);
            acc[14] = fmaf(w, o3.z, acc[14]); acc[15] = fmaf(w, o3.w, acc[15]);
        }
#pragma unroll
        for (int tt = 0; tt < 16; tt++) {
            out[(((size_t)b * SEQ_T + t0 + tt) * N_P + p) * KOUT + kk] = acc[tt] + bias;
        }
    }
}

// ---------------- launch ----------------
extern "C" void kernel_launch(void* const* d_in, const int* in_sizes, int n_in,
                              void* d_out, int out_size) {
    const float* joint  = (const float*)d_in[0];
    const float* curvat = (const float*)d_in[1];
    const float* entrop = (const float*)d_in[2];
    const float* Wq     = (const float*)d_in[3];
    const float* Wk     = (const float*)d_in[4];
    const float* Wv     = (const float*)d_in[5];
    const float* Wbw    = (const float*)d_in[6];
    const float* Wbb    = (const float*)d_in[7];
    const float* Waw    = (const float*)d_in[8];
    const float* Wab    = (const float*)d_in[9];
    const float* curv_w = (const float*)d_in[10];
    const float* ent_w  = (const float*)d_in[11];
    const float* out_w  = (const float*)d_in[12];
    const float* out_b  = (const float*)d_in[13];
    const float* lnqw   = (const float*)d_in[14];
    const float* lnqb   = (const float*)d_in[15];
    const float* lnkw   = (const float*)d_in[16];
    const float* lnkb   = (const float*)d_in[17];
    float* out = (float*)d_out;

    pack_w<<<(JD * NPAD + 255) / 256, 256>>>(Wq, Wk, Wv, Wbw, Waw);
    pack_outw<<<(KOUT * MEMD + 255) / 256, 256>>>(out_w);
    gemm_fused<<<NT / 64, 256>>>(joint, curvat, entrop, Wbb, Wab, curv_w, ent_w,
                                 lnqw, lnqb, lnkw, lnkb);
    scan_phase1<<<NGRP / 8, 128>>>();
    scan_combine<<<NREC / 8, 128>>>();
    scan_phase3<<<NGRP / 8, 128>>>();
    final_proj<<<dim3(NSEQ, SEQ_T / 128), 192>>>(out_b, out);
}

// round 4
// speedup vs baseline: 1.2696x; 1.1189x over previous
#include <cuda_runtime.h>
#include <cuda_bf16.h>
#include <math.h>

// Problem constants
constexpr int N_B   = 4;
constexpr int SEQ_T = 2048;
constexpr int N_P   = 16;
constexpr int JD    = 256;
constexpr int NH    = 4;
constexpr int DH    = 16;
constexpr int MEMD  = 64;
constexpr int KOUT  = 192;
constexpr int NSEQ  = N_B * N_P;        // 64
constexpr int NT    = NSEQ * SEQ_T;     // 131072 tokens
constexpr float EPS_LN = 1e-5f;

// chunked-scan constants
constexpr int CH   = 128;
constexpr int NCH  = SEQ_T / CH;        // 16
constexpr int NREC = NSEQ * NH;         // 256
constexpr int NGRP = NREC * NCH;        // 4096

// GEMM constants
constexpr int ABS = 20;                 // padded word stride for A/B smem rows
constexpr int GEMM_SMEM = 66560;        // max(51200 A+B, 64*260*4 C)

// ---------------- scratch (device globals; allocation-free) ----------------
__device__ unsigned int g_wh[256 * 128];     // W hi bf16 pairs, [n][c] (k=2c,2c+1)
__device__ unsigned int g_wl[256 * 128];     // W lo bf16 pairs
__device__ float g_wtr[MEMD * KOUT];
__device__ float g_q[(size_t)NREC * SEQ_T * DH];
__device__ float g_k[(size_t)NREC * SEQ_T * DH];
__device__ float g_v[(size_t)NREC * SEQ_T * DH];
__device__ float g_o[(size_t)NREC * SEQ_T * DH];
__device__ float g_beta[NREC * SEQ_T];
__device__ float g_alpha[NREC * SEQ_T];
__device__ float g_P[(size_t)NGRP * 256];
__device__ float g_R[(size_t)NGRP * 256];
__device__ float g_S[(size_t)NGRP * 256];

// ---------------- f32x2 helpers (Blackwell packed fp32) ----------------
__device__ __forceinline__ unsigned long long dup2(float x) {
    unsigned long long r;
    unsigned int xi = __float_as_uint(x);
    asm("mov.b64 %0, {%1, %1};" : "=l"(r) : "r"(xi));
    return r;
}
__device__ __forceinline__ unsigned long long pack2(float lo, float hi) {
    unsigned long long r;
    asm("mov.b64 %0, {%1, %2};" : "=l"(r) : "f"(lo), "f"(hi));
    return r;
}
__device__ __forceinline__ void fma2(unsigned long long& acc, unsigned long long a,
                                     unsigned long long b) {
    asm("fma.rn.f32x2 %0, %1, %2, %0;" : "+l"(acc) : "l"(a), "l"(b));
}
__device__ __forceinline__ unsigned long long mul2(unsigned long long a, unsigned long long b) {
    unsigned long long r;
    asm("mul.rn.f32x2 %0, %1, %2;" : "=l"(r) : "l"(a), "l"(b));
    return r;
}
__device__ __forceinline__ unsigned long long add2(unsigned long long a, unsigned long long b) {
    unsigned long long r;
    asm("add.rn.f32x2 %0, %1, %2;" : "=l"(r) : "l"(a), "l"(b));
    return r;
}
__device__ __forceinline__ float lo32(unsigned long long v) {
    return __uint_as_float((unsigned int)(v & 0xffffffffull));
}
__device__ __forceinline__ float hi32(unsigned long long v) {
    return __uint_as_float((unsigned int)(v >> 32));
}
__device__ __forceinline__ float dot16(const unsigned long long* A, const unsigned long long* k) {
    unsigned long long c0 = mul2(A[0], k[0]);
    unsigned long long c1 = mul2(A[1], k[1]);
    unsigned long long c2 = mul2(A[2], k[2]);
    unsigned long long c3 = mul2(A[3], k[3]);
    fma2(c0, A[4], k[4]);
    fma2(c1, A[5], k[5]);
    fma2(c2, A[6], k[6]);
    fma2(c3, A[7], k[7]);
    unsigned long long d0 = add2(c0, c1);
    unsigned long long d1 = add2(c2, c3);
    unsigned long long e = add2(d0, d1);
    return lo32(e) + hi32(e);
}

__device__ __forceinline__ float sigm(float x) { return 1.0f / (1.0f + expf(-x)); }

// ---------------- bf16 split helpers ----------------
__device__ __forceinline__ void split_pair(float x, float y,
                                           unsigned int& hw, unsigned int& lw) {
    __nv_bfloat16 hx = __float2bfloat16(x);
    __nv_bfloat16 hy = __float2bfloat16(y);
    float rx = x - __bfloat162float(hx);
    float ry = y - __bfloat162float(hy);
    __nv_bfloat16 lx = __float2bfloat16(rx);
    __nv_bfloat16 ly = __float2bfloat16(ry);
    hw = ((unsigned int)__bfloat16_as_ushort(hy) << 16) | __bfloat16_as_ushort(hx);
    lw = ((unsigned int)__bfloat16_as_ushort(ly) << 16) | __bfloat16_as_ushort(lx);
}

// ---------------- mma m16n8k16 bf16 ----------------
__device__ __forceinline__ void mma_bf16(float* c, const unsigned int* a,
                                         unsigned int b0, unsigned int b1) {
    asm volatile(
        "mma.sync.aligned.m16n8k16.row.col.f32.bf16.bf16.f32 "
        "{%0,%1,%2,%3}, {%4,%5,%6,%7}, {%8,%9}, {%0,%1,%2,%3};"
        : "+f"(c[0]), "+f"(c[1]), "+f"(c[2]), "+f"(c[3])
        : "r"(a[0]), "r"(a[1]), "r"(a[2]), "r"(a[3]), "r"(b0), "r"(b1));
}

// ---------------- kernel 0a: split projection weights to bf16 hi/lo ----------------
__global__ void pack_wbf(const float* __restrict__ Wq, const float* __restrict__ Wk,
                         const float* __restrict__ Wv, const float* __restrict__ Wbw,
                         const float* __restrict__ Waw) {
    int idx = blockIdx.x * blockDim.x + threadIdx.x;
    if (idx >= 256 * 128) return;
    int n = idx >> 7;
    int c = idx & 127;
    int k0 = 2 * c;
    float x = 0.0f, y = 0.0f;
    if (n < 64)        { x = Wq[n * JD + k0];        y = Wq[n * JD + k0 + 1]; }
    else if (n < 128)  { x = Wk[(n-64) * JD + k0];   y = Wk[(n-64) * JD + k0 + 1]; }
    else if (n < 192)  { x = Wv[(n-128) * JD + k0];  y = Wv[(n-128) * JD + k0 + 1]; }
    else if (n < 196)  { x = Wbw[(n-192) * JD + k0]; y = Wbw[(n-192) * JD + k0 + 1]; }
    else if (n < 200)  { x = Waw[(n-196) * JD + k0]; y = Waw[(n-196) * JD + k0 + 1]; }
    unsigned int hw, lw;
    split_pair(x, y, hw, lw);
    g_wh[idx] = hw;
    g_wl[idx] = lw;
}

// ---------------- kernel 0b: transpose out_w to [m][k] ----------------
__global__ void pack_outw(const float* __restrict__ out_w) {
    int idx = blockIdx.x * blockDim.x + threadIdx.x;
    if (idx >= KOUT * MEMD) return;
    int k = idx / MEMD;
    int m = idx % MEMD;
    g_wtr[m * KOUT + k] = out_w[idx];
}

// ---------------- kernel 1: tensor-core projection GEMM + fused epilogue ----------
// BM=64, BN=256, K=256, KC=32 chunks. 256 threads = 8 warps (wm 0-1, wn 0-3),
// warp tile 32x64 via m16n8k16. bf16 hi/lo split: C = Ah*Bh + (Ah*Bl + Al*Bh).
// Result staged in smem (reusing A/B buffers), then LN/norm/gate epilogue.
__global__ __launch_bounds__(256, 1) void gemm_tc(
        const float* __restrict__ X,
        const float* __restrict__ curv, const float* __restrict__ ent,
        const float* __restrict__ Wbb,  const float* __restrict__ Wab,
        const float* __restrict__ curv_w, const float* __restrict__ ent_w,
        const float* __restrict__ lnqw, const float* __restrict__ lnqb,
        const float* __restrict__ lnkw, const float* __restrict__ lnkb) {
    extern __shared__ char dsmem[];
    unsigned int* As = (unsigned int*)dsmem;                 // [2][64][ABS]
    unsigned int* Bs = As + 2 * 64 * ABS;                    // [2][256][ABS]
    float* Cs = (float*)dsmem;                               // [64][260] (aliases A/B)

    int tid = threadIdx.x;
    int lane = tid & 31;
    int warp = tid >> 5;
    int wm = warp & 1;           // M half
    int wn = warp >> 1;          // N quarter
    int g = lane >> 2;           // group row 0-7
    int tg = lane & 3;           // thread-in-group 0-3
    int m0 = blockIdx.x * 64;

    float acc[2][8][4];          // Ah*Bh
    float accc[2][8][4];         // Ah*Bl + Al*Bh
#pragma unroll
    for (int mt = 0; mt < 2; mt++)
#pragma unroll
        for (int nt = 0; nt < 8; nt++)
#pragma unroll
            for (int i = 0; i < 4; i++) { acc[mt][nt][i] = 0.0f; accc[mt][nt][i] = 0.0f; }

    for (int kc = 0; kc < 8; kc++) {
        __syncthreads();
        // stage A: fp32 global -> bf16 hi/lo pairs in smem (64 rows x 16 words)
#pragma unroll
        for (int r = 0; r < 2; r++) {
            int f = tid + 256 * r;          // [0,512)
            int m = f >> 3;                 // row
            int q = f & 7;                  // float4 within chunk (k = 4q..4q+3)
            float4 xv = *(const float4*)(X + (size_t)(m0 + m) * JD + kc * 32 + q * 4);
            unsigned int h0, l0, h1, l1;
            split_pair(xv.x, xv.y, h0, l0);
            split_pair(xv.z, xv.w, h1, l1);
            *(uint2*)(&As[m * ABS + 2 * q]) = make_uint2(h0, h1);
            *(uint2*)(&As[64 * ABS + m * ABS + 2 * q]) = make_uint2(l0, l1);
        }
        // stage B: prepped bf16 pairs (256 n x 16 words, hi & lo)
#pragma unroll
        for (int r = 0; r < 4; r++) {
            int f = tid + 256 * r;          // [0,1024)
            int n = f >> 2;
            int cq = f & 3;
            uint4 bh = *(const uint4*)(g_wh + n * 128 + kc * 16 + cq * 4);
            uint4 bl = *(const uint4*)(g_wl + n * 128 + kc * 16 + cq * 4);
            *(uint4*)(&Bs[n * ABS + cq * 4]) = bh;
            *(uint4*)(&Bs[256 * ABS + n * ABS + cq * 4]) = bl;
        }
        __syncthreads();

#pragma unroll
        for (int kt = 0; kt < 2; kt++) {
            int c0 = kt * 8 + tg;
            unsigned int ah[2][4], al[2][4];
#pragma unroll
            for (int mt = 0; mt < 2; mt++) {
                int mrow = wm * 32 + mt * 16 + g;
                ah[mt][0] = As[mrow * ABS + c0];
                ah[mt][1] = As[(mrow + 8) * ABS + c0];
                ah[mt][2] = As[mrow * ABS + c0 + 4];
                ah[mt][3] = As[(mrow + 8) * ABS + c0 + 4];
                al[mt][0] = As[64 * ABS + mrow * ABS + c0];
                al[mt][1] = As[64 * ABS + (mrow + 8) * ABS + c0];
                al[mt][2] = As[64 * ABS + mrow * ABS + c0 + 4];
                al[mt][3] = As[64 * ABS + (mrow + 8) * ABS + c0 + 4];
            }
#pragma unroll
            for (int nt = 0; nt < 8; nt++) {
                int ncol = wn * 64 + nt * 8 + g;
                unsigned int bh0 = Bs[ncol * ABS + c0];
                unsigned int bh1 = Bs[ncol * ABS + c0 + 4];
                unsigned int bl0 = Bs[256 * ABS + ncol * ABS + c0];
                unsigned int bl1 = Bs[256 * ABS + ncol * ABS + c0 + 4];
#pragma unroll
                for (int mt = 0; mt < 2; mt++) {
                    mma_bf16(acc[mt][nt], ah[mt], bh0, bh1);
                    mma_bf16(accc[mt][nt], ah[mt], bl0, bl1);
                    mma_bf16(accc[mt][nt], al[mt], bh0, bh1);
                }
            }
        }
    }

    // stage C into smem (aliases A/B staging)
    __syncthreads();
#pragma unroll
    for (int mt = 0; mt < 2; mt++) {
#pragma unroll
        for (int nt = 0; nt < 8; nt++) {
            int row = wm * 32 + mt * 16 + g;
            int col = wn * 64 + nt * 8 + 2 * tg;
            Cs[row * 260 + col]       = acc[mt][nt][0] + accc[mt][nt][0];
            Cs[row * 260 + col + 1]   = acc[mt][nt][1] + accc[mt][nt][1];
            Cs[(row + 8) * 260 + col]     = acc[mt][nt][2] + accc[mt][nt][2];
            Cs[(row + 8) * 260 + col + 1] = acc[mt][nt][3] + accc[mt][nt][3];
        }
    }
    __syncthreads();

    // ---------------- fused epilogue (from Cs) ----------------
    int tx = tid & 15;           // head slice
    int ty = tid >> 4;           // row group of 4
    if (tx >= 13) return;

    if (tx < 4) {
        float w16[16], b16[16];
#pragma unroll
        for (int i = 0; i < 16; i++) { w16[i] = __ldg(lnqw + i); b16[i] = __ldg(lnqb + i); }
#pragma unroll
        for (int r = 0; r < 4; r++) {
            float y[16];
            const float* crow = Cs + (ty * 4 + r) * 260 + tx * 16;
            *(float4*)&y[0]  = *(const float4*)(crow + 0);
            *(float4*)&y[4]  = *(const float4*)(crow + 4);
            *(float4*)&y[8]  = *(const float4*)(crow + 8);
            *(float4*)&y[12] = *(const float4*)(crow + 12);
            float s = 0.0f;
#pragma unroll
            for (int i = 0; i < 16; i++) s += y[i];
            float mean = s * 0.0625f;
            float var = 0.0f;
#pragma unroll
            for (int i = 0; i < 16; i++) { float d = y[i] - mean; var = fmaf(d, d, var); }
            var *= 0.0625f;
            float inv = rsqrtf(var + EPS_LN);
#pragma unroll
            for (int i = 0; i < 16; i++) y[i] = fmaf((y[i] - mean) * inv, w16[i], b16[i]);
            int mt = m0 + ty * 4 + r;
            int n = mt >> 11, t = mt & 2047;
            size_t base = ((size_t)(n * NH + tx) * SEQ_T + t) * DH;
            *(float4*)(g_q + base + 0)  = *(float4*)&y[0];
            *(float4*)(g_q + base + 4)  = *(float4*)&y[4];
            *(float4*)(g_q + base + 8)  = *(float4*)&y[8];
            *(float4*)(g_q + base + 12) = *(float4*)&y[12];
        }
    } else if (tx < 8) {
        int h = tx - 4;
        float w16[16], b16[16];
#pragma unroll
        for (int i = 0; i < 16; i++) { w16[i] = __ldg(lnkw + i); b16[i] = __ldg(lnkb + i); }
#pragma unroll
        for (int r = 0; r < 4; r++) {
            float y[16];
            const float* crow = Cs + (ty * 4 + r) * 260 + tx * 16;
            *(float4*)&y[0]  = *(const float4*)(crow + 0);
            *(float4*)&y[4]  = *(const float4*)(crow + 4);
            *(float4*)&y[8]  = *(const float4*)(crow + 8);
            *(float4*)&y[12] = *(const float4*)(crow + 12);
            float s = 0.0f;
#pragma unroll
            for (int i = 0; i < 16; i++) s += y[i];
            float mean = s * 0.0625f;
            float var = 0.0f;
#pragma unroll
            for (int i = 0; i < 16; i++) { float d = y[i] - mean; var = fmaf(d, d, var); }
            var *= 0.0625f;
            float inv = rsqrtf(var + EPS_LN);
#pragma unroll
            for (int i = 0; i < 16; i++) y[i] = fmaf((y[i] - mean) * inv, w16[i], b16[i]);
            float nrm = 0.0f;
#pragma unroll
            for (int i = 0; i < 16; i++) nrm = fmaf(y[i], y[i], nrm);
            float rinv = 1.0f / fmaxf(sqrtf(nrm), 1e-12f);
#pragma unroll
            for (int i = 0; i < 16; i++) y[i] *= rinv;
            int mt = m0 + ty * 4 + r;
            int n = mt >> 11, t = mt & 2047;
            size_t base = ((size_t)(n * NH + h) * SEQ_T + t) * DH;
            *(float4*)(g_k + base + 0)  = *(float4*)&y[0];
            *(float4*)(g_k + base + 4)  = *(float4*)&y[4];
            *(float4*)(g_k + base + 8)  = *(float4*)&y[8];
            *(float4*)(g_k + base + 12) = *(float4*)&y[12];
        }
    } else if (tx < 12) {
        int h = tx - 8;
#pragma unroll
        for (int r = 0; r < 4; r++) {
            float y[16];
            const float* crow = Cs + (ty * 4 + r) * 260 + tx * 16;
            *(float4*)&y[0]  = *(const float4*)(crow + 0);
            *(float4*)&y[4]  = *(const float4*)(crow + 4);
            *(float4*)&y[8]  = *(const float4*)(crow + 8);
            *(float4*)&y[12] = *(const float4*)(crow + 12);
            int mt = m0 + ty * 4 + r;
            int n = mt >> 11, t = mt & 2047;
            size_t base = ((size_t)(n * NH + h) * SEQ_T + t) * DH;
            *(float4*)(g_v + base + 0)  = *(float4*)&y[0];
            *(float4*)(g_v + base + 4)  = *(float4*)&y[4];
            *(float4*)(g_v + base + 8)  = *(float4*)&y[8];
            *(float4*)(g_v + base + 12) = *(float4*)&y[12];
        }
    } else {
#pragma unroll
        for (int r = 0; r < 4; r++) {
            float y[8];
            const float* crow = Cs + (ty * 4 + r) * 260 + tx * 16;
            *(float4*)&y[0] = *(const float4*)(crow + 0);
            *(float4*)&y[4] = *(const float4*)(crow + 4);
            int mt = m0 + ty * 4 + r;
            int n = mt >> 11, t = mt & 2047;
            int b = n >> 4;
            float Kv = fminf(fabsf(__ldg(curv + b)), 10.0f);
            float Sv = fminf(fmaxf(__ldg(ent + b), 0.0f), 5.0f);
#pragma unroll
            for (int h = 0; h < 4; h++) {
                float be = sigm(y[h] + __ldg(Wbb + h));
                be = sigm(fmaf(Kv, __ldg(curv_w + h), be));
                float al = sigm(y[4 + h] + __ldg(Wab + h));
                al = sigm(fmaf(Sv, __ldg(ent_w + h), al));
                g_beta[(n * NH + h) * SEQ_T + t] = be;
                g_alpha[(n * NH + h) * SEQ_T + t] = al;
            }
        }
    }
}

// ---------------- kernel 2a: chunked scan phase1 — per-chunk P, R ----------------
__global__ __launch_bounds__(128) void scan_phase1() {
    __shared__ float sk[8][512];
    __shared__ float sv[8][512];
    __shared__ float sb[8][32];
    __shared__ float sa[8][32];

    int warp = threadIdx.x >> 5;
    int lane = threadIdx.x & 31;
    int g = lane >> 4;
    int row = lane & 15;
    int wg = warp * 2 + g;
    int grp = blockIdx.x * 8 + wg;

    unsigned long long P[8], R[8];
#pragma unroll
    for (int j = 0; j < 8; j++) { P[j] = 0ull; R[j] = 0ull; }
    P[row >> 1] = (row & 1) ? pack2(0.0f, 1.0f) : pack2(1.0f, 0.0f);

    for (int sub = 0; sub < CH / 32; sub++) {
        __syncwarp();
#pragma unroll
        for (int r = 0; r < 8; r++) {
            int f = lane + 32 * r;
            int gg = f >> 7;
            int e = f & 127;
            int grp2 = blockIdx.x * 8 + warp * 2 + gg;
            int rec2 = grp2 >> 4, ch2 = grp2 & 15;
            size_t base4 = ((size_t)rec2 * SEQ_T + ch2 * CH + sub * 32) * 4;
            ((float4*)sk[warp * 2 + gg])[e] = ((const float4*)g_k)[base4 + e];
            ((float4*)sv[warp * 2 + gg])[e] = ((const float4*)g_v)[base4 + e];
        }
#pragma unroll
        for (int r = 0; r < 2; r++) {
            int f = lane + 32 * r;
            int gg = f >> 5;
            int e = f & 31;
            int grp2 = blockIdx.x * 8 + warp * 2 + gg;
            int rec2 = grp2 >> 4, ch2 = grp2 & 15;
            int src = rec2 * SEQ_T + ch2 * CH + sub * 32 + e;
            sb[warp * 2 + gg][e] = g_beta[src];
            sa[warp * 2 + gg][e] = g_alpha[src];
        }
        __syncwarp();

        for (int s = 0; s < 32; s++) {
            unsigned long long kp[8];
            const unsigned long long* kptr = (const unsigned long long*)&sk[wg][s * 16];
#pragma unroll
            for (int j = 0; j < 8; j++) kp[j] = kptr[j];
            float vi = sv[wg][s * 16 + row];
            float be = sb[wg][s];
            float al = sa[wg][s];

            float u = dot16(P, kp);
            float w = dot16(R, kp);
            unsigned long long cu = dup2(-al * u);
            unsigned long long cr = dup2(fmaf(be, vi, -al * w));
#pragma unroll
            for (int j = 0; j < 8; j++) {
                fma2(P[j], cu, kp[j]);
                fma2(R[j], cr, kp[j]);
            }
        }
    }

    size_t obase = ((size_t)grp * 16 + row) * 16;
    unsigned long long* gp = (unsigned long long*)(g_P + obase);
    unsigned long long* gr = (unsigned long long*)(g_R + obase);
#pragma unroll
    for (int j = 0; j < 8; j++) { gp[j] = P[j]; gr[j] = R[j]; }
}

// ---------------- kernel 2b: serial combine — entering states S_c ----------------
__global__ __launch_bounds__(128) void scan_combine() {
    __shared__ float sp[8][256];
    __shared__ float sr[8][256];

    int warp = threadIdx.x >> 5;
    int lane = threadIdx.x & 31;
    int g = lane >> 4;
    int row = lane & 15;
    int wg = warp * 2 + g;
    int rec = blockIdx.x * 8 + wg;

    unsigned long long S[8];
#pragma unroll
    for (int j = 0; j < 8; j++) S[j] = 0ull;

    for (int c = 0; c < NCH; c++) {
        size_t sbase = (((size_t)rec * NCH + c) * 16 + row) * 16;
        unsigned long long* gs = (unsigned long long*)(g_S + sbase);
#pragma unroll
        for (int j = 0; j < 8; j++) gs[j] = S[j];

        __syncwarp();
#pragma unroll
        for (int r = 0; r < 4; r++) {
            int f = lane + 32 * r;
            int gg = f >> 6;
            int e = f & 63;
            int rec2 = blockIdx.x * 8 + warp * 2 + gg;
            size_t base4 = ((size_t)rec2 * NCH + c) * 64;
            ((float4*)sp[warp * 2 + gg])[e] = ((const float4*)g_P)[base4 + e];
            ((float4*)sr[warp * 2 + gg])[e] = ((const float4*)g_R)[base4 + e];
        }
        __syncwarp();

        unsigned long long accm[8];
        const unsigned long long* rrow = (const unsigned long long*)&sr[wg][row * 16];
#pragma unroll
        for (int j = 0; j < 8; j++) accm[j] = rrow[j];
#pragma unroll
        for (int l = 0; l < 16; l++) {
            float sl = (l & 1) ? hi32(S[l >> 1]) : lo32(S[l >> 1]);
            unsigned long long sd = dup2(sl);
            const unsigned long long* prow = (const unsigned long long*)&sp[wg][l * 16];
#pragma unroll
            for (int j = 0; j < 8; j++) fma2(accm[j], sd, prow[j]);
        }
#pragma unroll
        for (int j = 0; j < 8; j++) S[j] = accm[j];
    }
}

// ---------------- kernel 2c: chunked scan phase3 — outputs ----------------
__global__ __launch_bounds__(128) void scan_phase3() {
    __shared__ float sk[8][512];
    __shared__ float sq[8][512];
    __shared__ float sv[8][512];
    __shared__ float sb[8][32];
    __shared__ float sa[8][32];

    int warp = threadIdx.x >> 5;
    int lane = threadIdx.x & 31;
    int g = lane >> 4;
    int row = lane & 15;
    int wg = warp * 2 + g;
    int grp = blockIdx.x * 8 + wg;

    unsigned long long M[8];
    {
        size_t sbase = ((size_t)grp * 16 + row) * 16;
        const unsigned long long* gs = (const unsigned long long*)(g_S + sbase);
#pragma unroll
        for (int j = 0; j < 8; j++) M[j] = gs[j];
    }

    for (int sub = 0; sub < CH / 32; sub++) {
        __syncwarp();
#pragma unroll
        for (int r = 0; r < 8; r++) {
            int f = lane + 32 * r;
            int gg = f >> 7;
            int e = f & 127;
            int grp2 = blockIdx.x * 8 + warp * 2 + gg;
            int rec2 = grp2 >> 4, ch2 = grp2 & 15;
            size_t base4 = ((size_t)rec2 * SEQ_T + ch2 * CH + sub * 32) * 4;
            ((float4*)sk[warp * 2 + gg])[e] = ((const float4*)g_k)[base4 + e];
            ((float4*)sq[warp * 2 + gg])[e] = ((const float4*)g_q)[base4 + e];
            ((float4*)sv[warp * 2 + gg])[e] = ((const float4*)g_v)[base4 + e];
        }
#pragma unroll
        for (int r = 0; r < 2; r++) {
            int f = lane + 32 * r;
            int gg = f >> 5;
            int e = f & 31;
            int grp2 = blockIdx.x * 8 + warp * 2 + gg;
            int rec2 = grp2 >> 4, ch2 = grp2 & 15;
            int src = rec2 * SEQ_T + ch2 * CH + sub * 32 + e;
            sb[warp * 2 + gg][e] = g_beta[src];
            sa[warp * 2 + gg][e] = g_alpha[src];
        }
        __syncwarp();

        for (int s = 0; s < 32; s++) {
            unsigned long long kp[8], qp[8];
            const unsigned long long* kptr = (const unsigned long long*)&sk[wg][s * 16];
            const unsigned long long* qptr = (const unsigned long long*)&sq[wg][s * 16];
#pragma unroll
            for (int j = 0; j < 8; j++) { kp[j] = kptr[j]; qp[j] = qptr[j]; }
            float vi = sv[wg][s * 16 + row];
            float be = sb[wg][s];
            float al = sa[wg][s];

            float mk = dot16(M, kp);
            unsigned long long cd = dup2(fmaf(be, vi, -al * mk));
#pragma unroll
            for (int j = 0; j < 8; j++) fma2(M[j], cd, kp[j]);
            float o = dot16(M, qp);
            sv[wg][s * 16 + row] = o;
        }
        __syncwarp();
#pragma unroll
        for (int r = 0; r < 8; r++) {
            int f = lane + 32 * r;
            int gg = f >> 7;
            int e = f & 127;
            int grp2 = blockIdx.x * 8 + warp * 2 + gg;
            int rec2 = grp2 >> 4, ch2 = grp2 & 15;
            size_t base4 = ((size_t)rec2 * SEQ_T + ch2 * CH + sub * 32) * 4;
            ((float4*)g_o)[base4 + e] = ((const float4*)sv[warp * 2 + gg])[e];
        }
    }
}

// ---------------- kernel 4: output projection + permuted write ----------------
__global__ __launch_bounds__(192) void final_proj(const float* __restrict__ out_b,
                                                  float* __restrict__ out) {
    __shared__ float so[64][20];
    int n = blockIdx.x;
    int tbase = blockIdx.y * 128;
    int kk = threadIdx.x;
    float bias = out_b[kk];
    int b = n >> 4;
    int p = n & 15;

    for (int tile = 0; tile < 8; tile++) {
        int t0 = tbase + tile * 16;
        __syncthreads();
#pragma unroll
        for (int r = 0; r < 6; r++) {
            int e = kk + 192 * r;
            if (e < 1024) {
                int h = e >> 8;
                int tt = (e >> 4) & 15;
                int i = e & 15;
                so[h * 16 + i][tt] =
                    g_o[((size_t)(n * NH + h) * SEQ_T + t0 + tt) * DH + i];
            }
        }
        __syncthreads();

        float acc[16];
#pragma unroll
        for (int tt = 0; tt < 16; tt++) acc[tt] = 0.0f;
#pragma unroll 4
        for (int m = 0; m < 64; m++) {
            float w = g_wtr[m * KOUT + kk];
            float4 o0 = *(const float4*)&so[m][0];
            float4 o1 = *(const float4*)&so[m][4];
            float4 o2 = *(const float4*)&so[m][8];
            float4 o3 = *(const float4*)&so[m][12];
            acc[0]  = fmaf(w, o0.x, acc[0]);  acc[1]  = fmaf(w, o0.y, acc[1]);
            acc[2]  = fmaf(w, o0.z, acc[2]);  acc[3]  = fmaf(w, o0.w, acc[3]);
            acc[4]  = fmaf(w, o1.x, acc[4]);  acc[5]  = fmaf(w, o1.y, acc[5]);
            acc[6]  = fmaf(w, o1.z, acc[6]);  acc[7]  = fmaf(w, o1.w, acc[7]);
            acc[8]  = fmaf(w, o2.x, acc[8]);  acc[9]  = fmaf(w, o2.y, acc[9]);
            acc[10] = fmaf(w, o2.z, acc[10]); acc[11] = fmaf(w, o2.w, acc[11]);
            acc[12] = fmaf(w, o3.x, acc[12]); acc[13] = fmaf(w, o3.y, acc[13]);
            acc[14] = fmaf(w, o3.z, acc[14]); acc[15] = fmaf(w, o3.w, acc[15]);
        }
#pragma unroll
        for (int tt = 0; tt < 16; tt++) {
            out[(((size_t)b * SEQ_T + t0 + tt) * N_P + p) * KOUT + kk] = acc[tt] + bias;
        }
    }
}

// ---------------- launch ----------------
extern "C" void kernel_launch(void* const* d_in, const int* in_sizes, int n_in,
                              void* d_out, int out_size) {
    const float* joint  = (const float*)d_in[0];
    const float* curvat = (const float*)d_in[1];
    const float* entrop = (const float*)d_in[2];
    const float* Wq     = (const float*)d_in[3];
    const float* Wk     = (const float*)d_in[4];
    const float* Wv     = (const float*)d_in[5];
    const float* Wbw    = (const float*)d_in[6];
    const float* Wbb    = (const float*)d_in[7];
    const float* Waw    = (const float*)d_in[8];
    const float* Wab    = (const float*)d_in[9];
    const float* curv_w = (const float*)d_in[10];
    const float* ent_w  = (const float*)d_in[11];
    const float* out_w  = (const float*)d_in[12];
    const float* out_b  = (const float*)d_in[13];
    const float* lnqw   = (const float*)d_in[14];
    const float* lnqb   = (const float*)d_in[15];
    const float* lnkw   = (const float*)d_in[16];
    const float* lnkb   = (const float*)d_in[17];
    float* out = (float*)d_out;

    cudaFuncSetAttribute(gemm_tc, cudaFuncAttributeMaxDynamicSharedMemorySize, GEMM_SMEM);

    pack_wbf<<<(256 * 128 + 255) / 256, 256>>>(Wq, Wk, Wv, Wbw, Waw);
    pack_outw<<<(KOUT * MEMD + 255) / 256, 256>>>(out_w);
    gemm_tc<<<NT / 64, 256, GEMM_SMEM>>>(joint, curvat, entrop, Wbb, Wab,
                                         curv_w, ent_w, lnqw, lnqb, lnkw, lnkb);
    scan_phase1<<<NGRP / 8, 128>>>();
    scan_combine<<<NREC / 8, 128>>>();
    scan_phase3<<<NGRP / 8, 128>>>();
    final_proj<<<dim3(NSEQ, SEQ_T / 128), 192>>>(out_b, out);
}

// round 6
// speedup vs baseline: 1.5918x; 1.2538x over previous
#include <cuda_runtime.h>
#include <cuda_bf16.h>
#include <math.h>

// Problem constants
constexpr int N_B   = 4;
constexpr int SEQ_T = 2048;
constexpr int N_P   = 16;
constexpr int JD    = 256;
constexpr int NH    = 4;
constexpr int DH    = 16;
constexpr int MEMD  = 64;
constexpr int KOUT  = 192;
constexpr int NSEQ  = N_B * N_P;        // 64
constexpr int NT    = NSEQ * SEQ_T;     // 131072 tokens
constexpr float EPS_LN = 1e-5f;

// chunked-scan constants
constexpr int CH   = 128;
constexpr int NCH  = SEQ_T / CH;        // 16
constexpr int NREC = NSEQ * NH;         // 256
constexpr int NGRP = NREC * NCH;        // 4096

// GEMM constants
constexpr int ABS = 20;                 // padded word stride for A/B smem rows

// ---------------- scratch (device globals; allocation-free) ----------------
__device__ unsigned int g_wh[256 * 128];     // W hi bf16 pairs, [n][c] (k=2c,2c+1)
__device__ unsigned int g_wl[256 * 128];     // W lo bf16 pairs
__device__ float g_wtr[MEMD * KOUT];
__device__ float g_q[(size_t)NREC * SEQ_T * DH];
__device__ float g_k[(size_t)NREC * SEQ_T * DH];
__device__ float g_v[(size_t)NREC * SEQ_T * DH];
__device__ float g_o[(size_t)NREC * SEQ_T * DH];
__device__ float g_beta[NREC * SEQ_T];
__device__ float g_alpha[NREC * SEQ_T];
__device__ float g_P[(size_t)NGRP * 256];
__device__ float g_R[(size_t)NGRP * 256];
__device__ float g_S[(size_t)NGRP * 256];

// ---------------- f32x2 helpers ----------------
__device__ __forceinline__ unsigned long long dup2(float x) {
    unsigned long long r;
    unsigned int xi = __float_as_uint(x);
    asm("mov.b64 %0, {%1, %1};" : "=l"(r) : "r"(xi));
    return r;
}
__device__ __forceinline__ unsigned long long pack2(float lo, float hi) {
    unsigned long long r;
    asm("mov.b64 %0, {%1, %2};" : "=l"(r) : "f"(lo), "f"(hi));
    return r;
}
__device__ __forceinline__ void fma2(unsigned long long& acc, unsigned long long a,
                                     unsigned long long b) {
    asm("fma.rn.f32x2 %0, %1, %2, %0;" : "+l"(acc) : "l"(a), "l"(b));
}
__device__ __forceinline__ unsigned long long mul2(unsigned long long a, unsigned long long b) {
    unsigned long long r;
    asm("mul.rn.f32x2 %0, %1, %2;" : "=l"(r) : "l"(a), "l"(b));
    return r;
}
__device__ __forceinline__ unsigned long long add2(unsigned long long a, unsigned long long b) {
    unsigned long long r;
    asm("add.rn.f32x2 %0, %1, %2;" : "=l"(r) : "l"(a), "l"(b));
    return r;
}
__device__ __forceinline__ float lo32(unsigned long long v) {
    return __uint_as_float((unsigned int)(v & 0xffffffffull));
}
__device__ __forceinline__ float hi32(unsigned long long v) {
    return __uint_as_float((unsigned int)(v >> 32));
}
__device__ __forceinline__ float dot16(const unsigned long long* A, const unsigned long long* k) {
    unsigned long long c0 = mul2(A[0], k[0]);
    unsigned long long c1 = mul2(A[1], k[1]);
    unsigned long long c2 = mul2(A[2], k[2]);
    unsigned long long c3 = mul2(A[3], k[3]);
    fma2(c0, A[4], k[4]);
    fma2(c1, A[5], k[5]);
    fma2(c2, A[6], k[6]);
    fma2(c3, A[7], k[7]);
    unsigned long long d0 = add2(c0, c1);
    unsigned long long d1 = add2(c2, c3);
    unsigned long long e = add2(d0, d1);
    return lo32(e) + hi32(e);
}
__device__ __forceinline__ float sigm(float x) { return 1.0f / (1.0f + expf(-x)); }

// ---------------- bf16 split ----------------
__device__ __forceinline__ void split_pair(float x, float y,
                                           unsigned int& hw, unsigned int& lw) {
    __nv_bfloat16 hx = __float2bfloat16(x);
    __nv_bfloat16 hy = __float2bfloat16(y);
    float rx = x - __bfloat162float(hx);
    float ry = y - __bfloat162float(hy);
    __nv_bfloat16 lx = __float2bfloat16(rx);
    __nv_bfloat16 ly = __float2bfloat16(ry);
    hw = ((unsigned int)__bfloat16_as_ushort(hy) << 16) | __bfloat16_as_ushort(hx);
    lw = ((unsigned int)__bfloat16_as_ushort(ly) << 16) | __bfloat16_as_ushort(lx);
}

// ---------------- mma m16n8k16 bf16 ----------------
__device__ __forceinline__ void mma_bf16(float* c, const unsigned int* a,
                                         unsigned int b0, unsigned int b1) {
    asm volatile(
        "mma.sync.aligned.m16n8k16.row.col.f32.bf16.bf16.f32 "
        "{%0,%1,%2,%3}, {%4,%5,%6,%7}, {%8,%9}, {%0,%1,%2,%3};"
        : "+f"(c[0]), "+f"(c[1]), "+f"(c[2]), "+f"(c[3])
        : "r"(a[0]), "r"(a[1]), "r"(a[2]), "r"(a[3]), "r"(b0), "r"(b1));
}

// ---------------- kernel 0a: split projection weights to bf16 hi/lo ----------------
__global__ void pack_wbf(const float* __restrict__ Wq, const float* __restrict__ Wk,
                         const float* __restrict__ Wv, const float* __restrict__ Wbw,
                         const float* __restrict__ Waw) {
    int idx = blockIdx.x * blockDim.x + threadIdx.x;
    if (idx >= 256 * 128) return;
    int n = idx >> 7;
    int c = idx & 127;
    int k0 = 2 * c;
    float x = 0.0f, y = 0.0f;
    if (n < 64)        { x = Wq[n * JD + k0];        y = Wq[n * JD + k0 + 1]; }
    else if (n < 128)  { x = Wk[(n-64) * JD + k0];   y = Wk[(n-64) * JD + k0 + 1]; }
    else if (n < 192)  { x = Wv[(n-128) * JD + k0];  y = Wv[(n-128) * JD + k0 + 1]; }
    else if (n < 196)  { x = Wbw[(n-192) * JD + k0]; y = Wbw[(n-192) * JD + k0 + 1]; }
    else if (n < 200)  { x = Waw[(n-196) * JD + k0]; y = Waw[(n-196) * JD + k0 + 1]; }
    unsigned int hw, lw;
    split_pair(x, y, hw, lw);
    g_wh[idx] = hw;
    g_wl[idx] = lw;
}

// ---------------- kernel 0b: transpose out_w (half range; launched twice) --------
__global__ void pack_outw(const float* __restrict__ out_w, int off) {
    int idx = off + blockIdx.x * blockDim.x + threadIdx.x;
    if (idx >= KOUT * MEMD) return;
    int k = idx / MEMD;
    int m = idx % MEMD;
    g_wtr[m * KOUT + k] = out_w[idx];
}

// ---------------- kernel 1: tensor-core projection GEMM + fused epilogue ----------
// BM=64, BN=128 (grid.y selects cols 0-127 / 128-255), BK=32 x 8 chunks.
// 8 warps (wm 0-1 x wn 0-3), warp tile 32x32, m16n8k16. All 3 bf16-split chains
// (AhBh + AhBl + AlBh) accumulate into ONE fp32 accumulator (32 regs/thread).
__global__ __launch_bounds__(256) void gemm_tc2(
        const float* __restrict__ X,
        const float* __restrict__ curv, const float* __restrict__ ent,
        const float* __restrict__ Wbb,  const float* __restrict__ Wab,
        const float* __restrict__ curv_w, const float* __restrict__ ent_w,
        const float* __restrict__ lnqw, const float* __restrict__ lnqb,
        const float* __restrict__ lnkw, const float* __restrict__ lnkb) {
    __shared__ __align__(16) char smbuf[33792];
    unsigned int* As = (unsigned int*)smbuf;            // [2][64][ABS] hi/lo
    unsigned int* Bs = As + 2 * 64 * ABS;               // [2][128][ABS]
    float* Cs = (float*)smbuf;                          // [64][132] (aliases A/B)

    int tid = threadIdx.x;
    int lane = tid & 31;
    int warp = tid >> 5;
    int wm = warp & 1;
    int wn = warp >> 1;          // 0-3
    int g = lane >> 2;
    int tg = lane & 3;
    int m0 = blockIdx.x * 64;
    int n0 = blockIdx.y * 128;   // weight-column base

    float acc[2][4][4];
#pragma unroll
    for (int mt = 0; mt < 2; mt++)
#pragma unroll
        for (int nt = 0; nt < 4; nt++)
#pragma unroll
            for (int i = 0; i < 4; i++) acc[mt][nt][i] = 0.0f;

    for (int kc = 0; kc < 8; kc++) {
        __syncthreads();
        // stage A: fp32 -> bf16 hi/lo pairs (64 rows x 16 words)
#pragma unroll
        for (int r = 0; r < 2; r++) {
            int f = tid + 256 * r;          // [0,512)
            int m = f >> 3;
            int q = f & 7;
            float4 xv = *(const float4*)(X + (size_t)(m0 + m) * JD + kc * 32 + q * 4);
            unsigned int h0, l0, h1, l1;
            split_pair(xv.x, xv.y, h0, l0);
            split_pair(xv.z, xv.w, h1, l1);
            *(uint2*)(&As[m * ABS + 2 * q]) = make_uint2(h0, h1);
            *(uint2*)(&As[64 * ABS + m * ABS + 2 * q]) = make_uint2(l0, l1);
        }
        // stage B: prepped bf16 pairs (128 n x 16 words, hi & lo)
#pragma unroll
        for (int r = 0; r < 2; r++) {
            int f = tid + 256 * r;          // [0,512)
            int n = f >> 2;
            int cq = f & 3;
            uint4 bh = *(const uint4*)(g_wh + (n0 + n) * 128 + kc * 16 + cq * 4);
            uint4 bl = *(const uint4*)(g_wl + (n0 + n) * 128 + kc * 16 + cq * 4);
            *(uint4*)(&Bs[n * ABS + cq * 4]) = bh;
            *(uint4*)(&Bs[128 * ABS + n * ABS + cq * 4]) = bl;
        }
        __syncthreads();

#pragma unroll
        for (int kt = 0; kt < 2; kt++) {
            int c0 = kt * 8 + tg;
            unsigned int ah[2][4], al[2][4];
#pragma unroll
            for (int mt = 0; mt < 2; mt++) {
                int mrow = wm * 32 + mt * 16 + g;
                ah[mt][0] = As[mrow * ABS + c0];
                ah[mt][1] = As[(mrow + 8) * ABS + c0];
                ah[mt][2] = As[mrow * ABS + c0 + 4];
                ah[mt][3] = As[(mrow + 8) * ABS + c0 + 4];
                al[mt][0] = As[64 * ABS + mrow * ABS + c0];
                al[mt][1] = As[64 * ABS + (mrow + 8) * ABS + c0];
                al[mt][2] = As[64 * ABS + mrow * ABS + c0 + 4];
                al[mt][3] = As[64 * ABS + (mrow + 8) * ABS + c0 + 4];
            }
#pragma unroll
            for (int nt = 0; nt < 4; nt++) {
                int ncol = wn * 32 + nt * 8 + g;
                unsigned int bh0 = Bs[ncol * ABS + c0];
                unsigned int bh1 = Bs[ncol * ABS + c0 + 4];
                unsigned int bl0 = Bs[128 * ABS + ncol * ABS + c0];
                unsigned int bl1 = Bs[128 * ABS + ncol * ABS + c0 + 4];
#pragma unroll
                for (int mt = 0; mt < 2; mt++) {
                    mma_bf16(acc[mt][nt], ah[mt], bh0, bh1);
                    mma_bf16(acc[mt][nt], ah[mt], bl0, bl1);
                    mma_bf16(acc[mt][nt], al[mt], bh0, bh1);
                }
            }
        }
    }

    // stage C into smem (aliases A/B staging)
    __syncthreads();
#pragma unroll
    for (int mt = 0; mt < 2; mt++) {
#pragma unroll
        for (int nt = 0; nt < 4; nt++) {
            int row = wm * 32 + mt * 16 + g;
            int col = wn * 32 + nt * 8 + 2 * tg;
            Cs[row * 132 + col]           = acc[mt][nt][0];
            Cs[row * 132 + col + 1]       = acc[mt][nt][1];
            Cs[(row + 8) * 132 + col]     = acc[mt][nt][2];
            Cs[(row + 8) * 132 + col + 1] = acc[mt][nt][3];
        }
    }
    __syncthreads();

    // ---------------- fused epilogue ----------------
    // 256 threads: tx = col slice (8 x 16 cols), ty = row pair (32 x 2 rows)
    int tx = tid & 7;
    int ty = tid >> 3;

#pragma unroll
    for (int rr = 0; rr < 2; rr++) {
        int row = ty * 2 + rr;
        int mtok = m0 + row;
        int n = mtok >> 11, t = mtok & 2047;
        const float* crow = Cs + row * 132 + tx * 16;

        if (blockIdx.y == 0) {
            float y[16];
            *(float4*)&y[0]  = *(const float4*)(crow + 0);
            *(float4*)&y[4]  = *(const float4*)(crow + 4);
            *(float4*)&y[8]  = *(const float4*)(crow + 8);
            *(float4*)&y[12] = *(const float4*)(crow + 12);
            float s = 0.0f;
#pragma unroll
            for (int i = 0; i < 16; i++) s += y[i];
            float mean = s * 0.0625f;
            float var = 0.0f;
#pragma unroll
            for (int i = 0; i < 16; i++) { float d = y[i] - mean; var = fmaf(d, d, var); }
            var *= 0.0625f;
            float inv = rsqrtf(var + EPS_LN);
            if (tx < 4) {
                // q head tx: LayerNorm
#pragma unroll
                for (int i = 0; i < 16; i++)
                    y[i] = fmaf((y[i] - mean) * inv, __ldg(lnqw + i), __ldg(lnqb + i));
                size_t base = ((size_t)(n * NH + tx) * SEQ_T + t) * DH;
                *(float4*)(g_q + base + 0)  = *(float4*)&y[0];
                *(float4*)(g_q + base + 4)  = *(float4*)&y[4];
                *(float4*)(g_q + base + 8)  = *(float4*)&y[8];
                *(float4*)(g_q + base + 12) = *(float4*)&y[12];
            } else {
                // k head tx-4: LayerNorm + L2 normalize
                int h = tx - 4;
#pragma unroll
                for (int i = 0; i < 16; i++)
                    y[i] = fmaf((y[i] - mean) * inv, __ldg(lnkw + i), __ldg(lnkb + i));
                float nrm = 0.0f;
#pragma unroll
                for (int i = 0; i < 16; i++) nrm = fmaf(y[i], y[i], nrm);
                float rinv = 1.0f / fmaxf(sqrtf(nrm), 1e-12f);
#pragma unroll
                for (int i = 0; i < 16; i++) y[i] *= rinv;
                size_t base = ((size_t)(n * NH + h) * SEQ_T + t) * DH;
                *(float4*)(g_k + base + 0)  = *(float4*)&y[0];
                *(float4*)(g_k + base + 4)  = *(float4*)&y[4];
                *(float4*)(g_k + base + 8)  = *(float4*)&y[8];
                *(float4*)(g_k + base + 12) = *(float4*)&y[12];
            }
        } else {
            if (tx < 4) {
                // v head tx
                float y[16];
                *(float4*)&y[0]  = *(const float4*)(crow + 0);
                *(float4*)&y[4]  = *(const float4*)(crow + 4);
                *(float4*)&y[8]  = *(const float4*)(crow + 8);
                *(float4*)&y[12] = *(const float4*)(crow + 12);
                size_t base = ((size_t)(n * NH + tx) * SEQ_T + t) * DH;
                *(float4*)(g_v + base + 0)  = *(float4*)&y[0];
                *(float4*)(g_v + base + 4)  = *(float4*)&y[4];
                *(float4*)(g_v + base + 8)  = *(float4*)&y[8];
                *(float4*)(g_v + base + 12) = *(float4*)&y[12];
            } else if (tx == 4) {
                // gates: local cols 64-71 = global 192-199
                float y[8];
                *(float4*)&y[0] = *(const float4*)(crow + 0);
                *(float4*)&y[4] = *(const float4*)(crow + 4);
                int b = n >> 4;
                float Kv = fminf(fabsf(__ldg(curv + b)), 10.0f);
                float Sv = fminf(fmaxf(__ldg(ent + b), 0.0f), 5.0f);
#pragma unroll
                for (int h = 0; h < 4; h++) {
                    float be = sigm(y[h] + __ldg(Wbb + h));
                    be = sigm(fmaf(Kv, __ldg(curv_w + h), be));
                    float al = sigm(y[4 + h] + __ldg(Wab + h));
                    al = sigm(fmaf(Sv, __ldg(ent_w + h), al));
                    g_beta[(n * NH + h) * SEQ_T + t] = be;
                    g_alpha[(n * NH + h) * SEQ_T + t] = al;
                }
            }
        }
    }
}

// ---------------- kernel 2a: chunked scan phase1 ----------------
__global__ __launch_bounds__(128) void scan_phase1() {
    __shared__ float sk[8][512];
    __shared__ float sv[8][512];
    __shared__ float sb[8][32];
    __shared__ float sa[8][32];

    int warp = threadIdx.x >> 5;
    int lane = threadIdx.x & 31;
    int g = lane >> 4;
    int row = lane & 15;
    int wg = warp * 2 + g;
    int grp = blockIdx.x * 8 + wg;

    unsigned long long P[8], R[8];
#pragma unroll
    for (int j = 0; j < 8; j++) { P[j] = 0ull; R[j] = 0ull; }
    P[row >> 1] = (row & 1) ? pack2(0.0f, 1.0f) : pack2(1.0f, 0.0f);

    for (int sub = 0; sub < CH / 32; sub++) {
        __syncwarp();
#pragma unroll
        for (int r = 0; r < 8; r++) {
            int f = lane + 32 * r;
            int gg = f >> 7;
            int e = f & 127;
            int grp2 = blockIdx.x * 8 + warp * 2 + gg;
            int rec2 = grp2 >> 4, ch2 = grp2 & 15;
            size_t base4 = ((size_t)rec2 * SEQ_T + ch2 * CH + sub * 32) * 4;
            ((float4*)sk[warp * 2 + gg])[e] = ((const float4*)g_k)[base4 + e];
            ((float4*)sv[warp * 2 + gg])[e] = ((const float4*)g_v)[base4 + e];
        }
#pragma unroll
        for (int r = 0; r < 2; r++) {
            int f = lane + 32 * r;
            int gg = f >> 5;
            int e = f & 31;
            int grp2 = blockIdx.x * 8 + warp * 2 + gg;
            int rec2 = grp2 >> 4, ch2 = grp2 & 15;
            int src = rec2 * SEQ_T + ch2 * CH + sub * 32 + e;
            sb[warp * 2 + gg][e] = g_beta[src];
            sa[warp * 2 + gg][e] = g_alpha[src];
        }
        __syncwarp();

        for (int s = 0; s < 32; s++) {
            unsigned long long kp[8];
            const unsigned long long* kptr = (const unsigned long long*)&sk[wg][s * 16];
#pragma unroll
            for (int j = 0; j < 8; j++) kp[j] = kptr[j];
            float vi = sv[wg][s * 16 + row];
            float be = sb[wg][s];
            float al = sa[wg][s];

            float u = dot16(P, kp);
            float w = dot16(R, kp);
            unsigned long long cu = dup2(-al * u);
            unsigned long long cr = dup2(fmaf(be, vi, -al * w));
#pragma unroll
            for (int j = 0; j < 8; j++) {
                fma2(P[j], cu, kp[j]);
                fma2(R[j], cr, kp[j]);
            }
        }
    }

    size_t obase = ((size_t)grp * 16 + row) * 16;
    unsigned long long* gp = (unsigned long long*)(g_P + obase);
    unsigned long long* gr = (unsigned long long*)(g_R + obase);
#pragma unroll
    for (int j = 0; j < 8; j++) { gp[j] = P[j]; gr[j] = R[j]; }
}

// ---------------- kernel 2b: serial combine ----------------
__global__ __launch_bounds__(128) void scan_combine() {
    __shared__ float sp[8][256];
    __shared__ float sr[8][256];

    int warp = threadIdx.x >> 5;
    int lane = threadIdx.x & 31;
    int g = lane >> 4;
    int row = lane & 15;
    int wg = warp * 2 + g;
    int rec = blockIdx.x * 8 + wg;

    unsigned long long S[8];
#pragma unroll
    for (int j = 0; j < 8; j++) S[j] = 0ull;

    for (int c = 0; c < NCH; c++) {
        size_t sbase = (((size_t)rec * NCH + c) * 16 + row) * 16;
        unsigned long long* gs = (unsigned long long*)(g_S + sbase);
#pragma unroll
        for (int j = 0; j < 8; j++) gs[j] = S[j];

        __syncwarp();
#pragma unroll
        for (int r = 0; r < 4; r++) {
            int f = lane + 32 * r;
            int gg = f >> 6;
            int e = f & 63;
            int rec2 = blockIdx.x * 8 + warp * 2 + gg;
            size_t base4 = ((size_t)rec2 * NCH + c) * 64;
            ((float4*)sp[warp * 2 + gg])[e] = ((const float4*)g_P)[base4 + e];
            ((float4*)sr[warp * 2 + gg])[e] = ((const float4*)g_R)[base4 + e];
        }
        __syncwarp();

        unsigned long long accm[8];
        const unsigned long long* rrow = (const unsigned long long*)&sr[wg][row * 16];
#pragma unroll
        for (int j = 0; j < 8; j++) accm[j] = rrow[j];
#pragma unroll
        for (int l = 0; l < 16; l++) {
            float sl = (l & 1) ? hi32(S[l >> 1]) : lo32(S[l >> 1]);
            unsigned long long sd = dup2(sl);
            const unsigned long long* prow = (const unsigned long long*)&sp[wg][l * 16];
#pragma unroll
            for (int j = 0; j < 8; j++) fma2(accm[j], sd, prow[j]);
        }
#pragma unroll
        for (int j = 0; j < 8; j++) S[j] = accm[j];
    }
}

// ---------------- kernel 2c: chunked scan phase3 ----------------
__global__ __launch_bounds__(128) void scan_phase3() {
    __shared__ float sk[8][512];
    __shared__ float sq[8][512];
    __shared__ float sv[8][512];
    __shared__ float sb[8][32];
    __shared__ float sa[8][32];

    int warp = threadIdx.x >> 5;
    int lane = threadIdx.x & 31;
    int g = lane >> 4;
    int row = lane & 15;
    int wg = warp * 2 + g;
    int grp = blockIdx.x * 8 + wg;

    unsigned long long M[8];
    {
        size_t sbase = ((size_t)grp * 16 + row) * 16;
        const unsigned long long* gs = (const unsigned long long*)(g_S + sbase);
#pragma unroll
        for (int j = 0; j < 8; j++) M[j] = gs[j];
    }

    for (int sub = 0; sub < CH / 32; sub++) {
        __syncwarp();
#pragma unroll
        for (int r = 0; r < 8; r++) {
            int f = lane + 32 * r;
            int gg = f >> 7;
            int e = f & 127;
            int grp2 = blockIdx.x * 8 + warp * 2 + gg;
            int rec2 = grp2 >> 4, ch2 = grp2 & 15;
            size_t base4 = ((size_t)rec2 * SEQ_T + ch2 * CH + sub * 32) * 4;
            ((float4*)sk[warp * 2 + gg])[e] = ((const float4*)g_k)[base4 + e];
            ((float4*)sq[warp * 2 + gg])[e] = ((const float4*)g_q)[base4 + e];
            ((float4*)sv[warp * 2 + gg])[e] = ((const float4*)g_v)[base4 + e];
        }
#pragma unroll
        for (int r = 0; r < 2; r++) {
            int f = lane + 32 * r;
            int gg = f >> 5;
            int e = f & 31;
            int grp2 = blockIdx.x * 8 + warp * 2 + gg;
            int rec2 = grp2 >> 4, ch2 = grp2 & 15;
            int src = rec2 * SEQ_T + ch2 * CH + sub * 32 + e;
            sb[warp * 2 + gg][e] = g_beta[src];
            sa[warp * 2 + gg][e] = g_alpha[src];
        }
        __syncwarp();

        for (int s = 0; s < 32; s++) {
            unsigned long long kp[8], qp[8];
            const unsigned long long* kptr = (const unsigned long long*)&sk[wg][s * 16];
            const unsigned long long* qptr = (const unsigned long long*)&sq[wg][s * 16];
#pragma unroll
            for (int j = 0; j < 8; j++) { kp[j] = kptr[j]; qp[j] = qptr[j]; }
            float vi = sv[wg][s * 16 + row];
            float be = sb[wg][s];
            float al = sa[wg][s];

            float mk = dot16(M, kp);
            unsigned long long cd = dup2(fmaf(be, vi, -al * mk));
#pragma unroll
            for (int j = 0; j < 8; j++) fma2(M[j], cd, kp[j]);
            float o = dot16(M, qp);
            sv[wg][s * 16 + row] = o;
        }
        __syncwarp();
#pragma unroll
        for (int r = 0; r < 8; r++) {
            int f = lane + 32 * r;
            int gg = f >> 7;
            int e = f & 127;
            int grp2 = blockIdx.x * 8 + warp * 2 + gg;
            int rec2 = grp2 >> 4, ch2 = grp2 & 15;
            size_t base4 = ((size_t)rec2 * SEQ_T + ch2 * CH + sub * 32) * 4;
            ((float4*)g_o)[base4 + e] = ((const float4*)sv[warp * 2 + gg])[e];
        }
    }
}

// ---------------- kernel 4: output projection + permuted write ----------------
__global__ __launch_bounds__(192) void final_proj(const float* __restrict__ out_b,
                                                  float* __restrict__ out) {
    __shared__ float so[64][20];
    int n = blockIdx.x;
    int tbase = blockIdx.y * 128;
    int kk = threadIdx.x;
    float bias = out_b[kk];
    int b = n >> 4;
    int p = n & 15;

    for (int tile = 0; tile < 8; tile++) {
        int t0 = tbase + tile * 16;
        __syncthreads();
#pragma unroll
        for (int r = 0; r < 6; r++) {
            int e = kk + 192 * r;
            if (e < 1024) {
                int h = e >> 8;
                int tt = (e >> 4) & 15;
                int i = e & 15;
                so[h * 16 + i][tt] =
                    g_o[((size_t)(n * NH + h) * SEQ_T + t0 + tt) * DH + i];
            }
        }
        __syncthreads();

        float acc[16];
#pragma unroll
        for (int tt = 0; tt < 16; tt++) acc[tt] = 0.0f;
#pragma unroll 4
        for (int m = 0; m < 64; m++) {
            float w = g_wtr[m * KOUT + kk];
            float4 o0 = *(const float4*)&so[m][0];
            float4 o1 = *(const float4*)&so[m][4];
            float4 o2 = *(const float4*)&so[m][8];
            float4 o3 = *(const float4*)&so[m][12];
            acc[0]  = fmaf(w, o0.x, acc[0]);  acc[1]  = fmaf(w, o0.y, acc[1]);
            acc[2]  = fmaf(w, o0.z, acc[2]);  acc[3]  = fmaf(w, o0.w, acc[3]);
            acc[4]  = fmaf(w, o1.x, acc[4]);  acc[5]  = fmaf(w, o1.y, acc[5]);
            acc[6]  = fmaf(w, o1.z, acc[6]);  acc[7]  = fmaf(w, o1.w, acc[7]);
            acc[8]  = fmaf(w, o2.x, acc[8]);  acc[9]  = fmaf(w, o2.y, acc[9]);
            acc[10] = fmaf(w, o2.z, acc[10]); acc[11] = fmaf(w, o2.w, acc[11]);
            acc[12] = fmaf(w, o3.x, acc[12]); acc[13] = fmaf(w, o3.y, acc[13]);
            acc[14] = fmaf(w, o3.z, acc[14]); acc[15] = fmaf(w, o3.w, acc[15]);
        }
#pragma unroll
        for (int tt = 0; tt < 16; tt++) {
            out[(((size_t)b * SEQ_T + t0 + tt) * N_P + p) * KOUT + kk] = acc[tt] + bias;
        }
    }
}

// ---------------- launch ----------------
extern "C" void kernel_launch(void* const* d_in, const int* in_sizes, int n_in,
                              void* d_out, int out_size) {
    const float* joint  = (const float*)d_in[0];
    const float* curvat = (const float*)d_in[1];
    const float* entrop = (const float*)d_in[2];
    const float* Wq     = (const float*)d_in[3];
    const float* Wk     = (const float*)d_in[4];
    const float* Wv     = (const float*)d_in[5];
    const float* Wbw    = (const float*)d_in[6];
    const float* Wbb    = (const float*)d_in[7];
    const float* Waw    = (const float*)d_in[8];
    const float* Wab    = (const float*)d_in[9];
    const float* curv_w = (const float*)d_in[10];
    const float* ent_w  = (const float*)d_in[11];
    const float* out_w  = (const float*)d_in[12];
    const float* out_b  = (const float*)d_in[13];
    const float* lnqw   = (const float*)d_in[14];
    const float* lnqb   = (const float*)d_in[15];
    const float* lnkw   = (const float*)d_in[16];
    const float* lnkb   = (const float*)d_in[17];
    float* out = (float*)d_out;

    constexpr int OW_HALF = KOUT * MEMD / 2;
    pack_wbf<<<(256 * 128 + 255) / 256, 256>>>(Wq, Wk, Wv, Wbw, Waw);
    pack_outw<<<(OW_HALF + 255) / 256, 256>>>(out_w, 0);
    pack_outw<<<(OW_HALF + 255) / 256, 256>>>(out_w, OW_HALF);
    // gemm is launch index 3 -> lands in ncu's captured slot next profile
    gemm_tc2<<<dim3(NT / 64, 2), 256>>>(joint, curvat, entrop, Wbb, Wab,
                                        curv_w, ent_w, lnqw, lnqb, lnkw, lnkb);
    scan_phase1<<<NGRP / 8, 128>>>();
    scan_combine<<<NREC / 8, 128>>>();
    scan_phase3<<<NGRP / 8, 128>>>();
    final_proj<<<dim3(NSEQ, SEQ_T / 128), 192>>>(out_b, out);
}

// round 7
// speedup vs baseline: 1.7255x; 1.0840x over previous
#include <cuda_runtime.h>
#include <cuda_bf16.h>
#include <math.h>

// Problem constants
constexpr int N_B   = 4;
constexpr int SEQ_T = 2048;
constexpr int N_P   = 16;
constexpr int JD    = 256;
constexpr int NH    = 4;
constexpr int DH    = 16;
constexpr int MEMD  = 64;
constexpr int KOUT  = 192;
constexpr int NSEQ  = N_B * N_P;        // 64
constexpr int NT    = NSEQ * SEQ_T;     // 131072 tokens
constexpr float EPS_LN = 1e-5f;

// chunked-scan constants
constexpr int CH   = 128;
constexpr int NCH  = SEQ_T / CH;        // 16
constexpr int NREC = NSEQ * NH;         // 256
constexpr int NGRP = NREC * NCH;        // 4096

// GEMM constants
constexpr int ABS = 20;                     // padded word stride for smem rows
constexpr int B_BUF_W = 2 * 128 * ABS;      // words per B buffer (hi+lo) = 5120
constexpr int GEMM_SMEM = (2 * 64 * ABS + 2 * B_BUF_W) * 4;  // 51200 B

// ---------------- scratch (device globals; allocation-free) ----------------
__device__ unsigned int g_wh[256 * 128];     // W hi bf16 pairs, [n][c] (k=2c,2c+1)
__device__ unsigned int g_wl[256 * 128];     // W lo bf16 pairs
__device__ float g_wtr[MEMD * KOUT];
__device__ float g_q[(size_t)NREC * SEQ_T * DH];
__device__ float g_k[(size_t)NREC * SEQ_T * DH];
__device__ float g_v[(size_t)NREC * SEQ_T * DH];
__device__ float g_o[(size_t)NREC * SEQ_T * DH];
__device__ float g_beta[NREC * SEQ_T];
__device__ float g_alpha[NREC * SEQ_T];
__device__ float g_P[(size_t)NGRP * 256];
__device__ float g_R[(size_t)NGRP * 256];
__device__ float g_S[(size_t)NGRP * 256];

// ---------------- f32x2 helpers ----------------
__device__ __forceinline__ unsigned long long dup2(float x) {
    unsigned long long r;
    unsigned int xi = __float_as_uint(x);
    asm("mov.b64 %0, {%1, %1};" : "=l"(r) : "r"(xi));
    return r;
}
__device__ __forceinline__ unsigned long long pack2(float lo, float hi) {
    unsigned long long r;
    asm("mov.b64 %0, {%1, %2};" : "=l"(r) : "f"(lo), "f"(hi));
    return r;
}
__device__ __forceinline__ void fma2(unsigned long long& acc, unsigned long long a,
                                     unsigned long long b) {
    asm("fma.rn.f32x2 %0, %1, %2, %0;" : "+l"(acc) : "l"(a), "l"(b));
}
__device__ __forceinline__ unsigned long long mul2(unsigned long long a, unsigned long long b) {
    unsigned long long r;
    asm("mul.rn.f32x2 %0, %1, %2;" : "=l"(r) : "l"(a), "l"(b));
    return r;
}
__device__ __forceinline__ unsigned long long add2(unsigned long long a, unsigned long long b) {
    unsigned long long r;
    asm("add.rn.f32x2 %0, %1, %2;" : "=l"(r) : "l"(a), "l"(b));
    return r;
}
__device__ __forceinline__ float lo32(unsigned long long v) {
    return __uint_as_float((unsigned int)(v & 0xffffffffull));
}
__device__ __forceinline__ float hi32(unsigned long long v) {
    return __uint_as_float((unsigned int)(v >> 32));
}
__device__ __forceinline__ float dot16(const unsigned long long* A, const unsigned long long* k) {
    unsigned long long c0 = mul2(A[0], k[0]);
    unsigned long long c1 = mul2(A[1], k[1]);
    unsigned long long c2 = mul2(A[2], k[2]);
    unsigned long long c3 = mul2(A[3], k[3]);
    fma2(c0, A[4], k[4]);
    fma2(c1, A[5], k[5]);
    fma2(c2, A[6], k[6]);
    fma2(c3, A[7], k[7]);
    unsigned long long d0 = add2(c0, c1);
    unsigned long long d1 = add2(c2, c3);
    unsigned long long e = add2(d0, d1);
    return lo32(e) + hi32(e);
}
__device__ __forceinline__ float sigm(float x) { return 1.0f / (1.0f + expf(-x)); }

// ---------------- bf16 split ----------------
__device__ __forceinline__ void split_pair(float x, float y,
                                           unsigned int& hw, unsigned int& lw) {
    __nv_bfloat16 hx = __float2bfloat16(x);
    __nv_bfloat16 hy = __float2bfloat16(y);
    float rx = x - __bfloat162float(hx);
    float ry = y - __bfloat162float(hy);
    __nv_bfloat16 lx = __float2bfloat16(rx);
    __nv_bfloat16 ly = __float2bfloat16(ry);
    hw = ((unsigned int)__bfloat16_as_ushort(hy) << 16) | __bfloat16_as_ushort(hx);
    lw = ((unsigned int)__bfloat16_as_ushort(ly) << 16) | __bfloat16_as_ushort(lx);
}

// ---------------- mma m16n8k16 bf16 ----------------
__device__ __forceinline__ void mma_bf16(float* c, const unsigned int* a,
                                         unsigned int b0, unsigned int b1) {
    asm volatile(
        "mma.sync.aligned.m16n8k16.row.col.f32.bf16.bf16.f32 "
        "{%0,%1,%2,%3}, {%4,%5,%6,%7}, {%8,%9}, {%0,%1,%2,%3};"
        : "+f"(c[0]), "+f"(c[1]), "+f"(c[2]), "+f"(c[3])
        : "r"(a[0]), "r"(a[1]), "r"(a[2]), "r"(a[3]), "r"(b0), "r"(b1));
}

// ---------------- cp.async helpers ----------------
__device__ __forceinline__ void cp_async16(unsigned int saddr, const void* g) {
    asm volatile("cp.async.cg.shared.global [%0], [%1], 16;"
                 :: "r"(saddr), "l"(__cvta_generic_to_global(g)) : "memory");
}
#define CP_COMMIT() asm volatile("cp.async.commit_group;" ::: "memory")
#define CP_WAIT(n)  asm volatile("cp.async.wait_group %0;" :: "n"(n) : "memory")

// ---------------- kernel 0a: split projection weights to bf16 hi/lo ----------------
__global__ void pack_wbf(const float* __restrict__ Wq, const float* __restrict__ Wk,
                         const float* __restrict__ Wv, const float* __restrict__ Wbw,
                         const float* __restrict__ Waw) {
    int idx = blockIdx.x * blockDim.x + threadIdx.x;
    if (idx >= 256 * 128) return;
    int n = idx >> 7;
    int c = idx & 127;
    int k0 = 2 * c;
    float x = 0.0f, y = 0.0f;
    if (n < 64)        { x = Wq[n * JD + k0];        y = Wq[n * JD + k0 + 1]; }
    else if (n < 128)  { x = Wk[(n-64) * JD + k0];   y = Wk[(n-64) * JD + k0 + 1]; }
    else if (n < 192)  { x = Wv[(n-128) * JD + k0];  y = Wv[(n-128) * JD + k0 + 1]; }
    else if (n < 196)  { x = Wbw[(n-192) * JD + k0]; y = Wbw[(n-192) * JD + k0 + 1]; }
    else if (n < 200)  { x = Waw[(n-196) * JD + k0]; y = Waw[(n-196) * JD + k0 + 1]; }
    unsigned int hw, lw;
    split_pair(x, y, hw, lw);
    g_wh[idx] = hw;
    g_wl[idx] = lw;
}

// ---------------- kernel 0b: transpose out_w (half range; launched twice) --------
__global__ void pack_outw(const float* __restrict__ out_w, int off) {
    int idx = off + blockIdx.x * blockDim.x + threadIdx.x;
    if (idx >= KOUT * MEMD) return;
    int k = idx / MEMD;
    int m = idx % MEMD;
    g_wtr[m * KOUT + k] = out_w[idx];
}

// ---------------- kernel 1: pipelined tensor-core GEMM + fused epilogue ----------
// BM=64, BN=128 (grid.y), BK=32 x 8 chunks, 128 threads = 4 warps.
// Warp tile 32x64 (wm 0-1, wn 0-1). 3 bf16-split chains into one fp32 acc.
// A: register prefetch + in-flight fp32->bf16hi/lo conversion (single smem buf).
// B: cp.async double-buffered raw copy of pre-converted g_wh/g_wl.
__global__ __launch_bounds__(128, 3) void gemm_tc2(
        const float* __restrict__ X,
        const float* __restrict__ curv, const float* __restrict__ ent,
        const float* __restrict__ Wbb,  const float* __restrict__ Wab,
        const float* __restrict__ curv_w, const float* __restrict__ ent_w,
        const float* __restrict__ lnqw, const float* __restrict__ lnqb,
        const float* __restrict__ lnkw, const float* __restrict__ lnkb) {
    extern __shared__ __align__(16) char dsm[];
    unsigned int* As = (unsigned int*)dsm;            // [2][64][ABS] hi/lo
    unsigned int* Bs = As + 2 * 64 * ABS;             // [2 bufs][2][128][ABS]
    float* Cs = (float*)dsm;                          // [64][132] (aliases)

    int tid = threadIdx.x;
    int lane = tid & 31;
    int warp = tid >> 5;
    int wm = warp & 1;
    int wn = warp >> 1;          // 0-1
    int g = lane >> 2;
    int tg = lane & 3;
    int m0 = blockIdx.x * 64;
    int n0 = blockIdx.y * 128;

    unsigned int sb_bs = (unsigned int)__cvta_generic_to_shared(Bs);

    float acc[2][8][4];
#pragma unroll
    for (int mt = 0; mt < 2; mt++)
#pragma unroll
        for (int nt = 0; nt < 8; nt++)
#pragma unroll
            for (int i = 0; i < 4; i++) acc[mt][nt][i] = 0.0f;

    // A prefetch mapping: f = tid + 128r -> m = f>>3, q = f&7
    int am = tid >> 3;           // base row for r=0; r adds 16 rows
    int aq = tid & 7;

    float4 pa[4];
#pragma unroll
    for (int r = 0; r < 4; r++)
        pa[r] = *(const float4*)(X + (size_t)(m0 + am + 16 * r) * JD + aq * 4);
    // B chunk 0 -> buf 0
    {
        unsigned int bbase = sb_bs;
        int n = tid >> 2, cq = tid & 3;
#pragma unroll
        for (int r = 0; r < 4; r++)
            cp_async16(bbase + ((n + 32 * r) * ABS + cq * 4) * 4,
                       g_wh + (n0 + n + 32 * r) * 128 + cq * 4);
#pragma unroll
        for (int r = 0; r < 4; r++)
            cp_async16(bbase + (128 * ABS + (n + 32 * r) * ABS + cq * 4) * 4,
                       g_wl + (n0 + n + 32 * r) * 128 + cq * 4);
        CP_COMMIT();
    }

    for (int kc = 0; kc < 8; kc++) {
        // STS A (convert) from prefetch regs
#pragma unroll
        for (int r = 0; r < 4; r++) {
            int m = am + 16 * r;
            unsigned int h0, l0, h1, l1;
            split_pair(pa[r].x, pa[r].y, h0, l0);
            split_pair(pa[r].z, pa[r].w, h1, l1);
            *(uint2*)(&As[m * ABS + 2 * aq]) = make_uint2(h0, h1);
            *(uint2*)(&As[64 * ABS + m * ABS + 2 * aq]) = make_uint2(l0, l1);
        }
        if (kc < 7) {
            // prefetch A(kc+1)
#pragma unroll
            for (int r = 0; r < 4; r++)
                pa[r] = *(const float4*)(X + (size_t)(m0 + am + 16 * r) * JD +
                                         (kc + 1) * 32 + aq * 4);
            // cp.async B(kc+1) -> buf[(kc+1)&1]
            unsigned int bbase = sb_bs + ((kc + 1) & 1) * B_BUF_W * 4;
            int n = tid >> 2, cq = tid & 3;
#pragma unroll
            for (int r = 0; r < 4; r++)
                cp_async16(bbase + ((n + 32 * r) * ABS + cq * 4) * 4,
                           g_wh + (n0 + n + 32 * r) * 128 + (kc + 1) * 16 + cq * 4);
#pragma unroll
            for (int r = 0; r < 4; r++)
                cp_async16(bbase + (128 * ABS + (n + 32 * r) * ABS + cq * 4) * 4,
                           g_wl + (n0 + n + 32 * r) * 128 + (kc + 1) * 16 + cq * 4);
            CP_COMMIT();
            CP_WAIT(1);          // B(kc) complete
        } else {
            CP_WAIT(0);
        }
        __syncthreads();

        const unsigned int* Bb = Bs + (kc & 1) * B_BUF_W;
#pragma unroll
        for (int kt = 0; kt < 2; kt++) {
            int c0 = kt * 8 + tg;
            unsigned int ah[2][4], al[2][4];
#pragma unroll
            for (int mt = 0; mt < 2; mt++) {
                int mrow = wm * 32 + mt * 16 + g;
                ah[mt][0] = As[mrow * ABS + c0];
                ah[mt][1] = As[(mrow + 8) * ABS + c0];
                ah[mt][2] = As[mrow * ABS + c0 + 4];
                ah[mt][3] = As[(mrow + 8) * ABS + c0 + 4];
                al[mt][0] = As[64 * ABS + mrow * ABS + c0];
                al[mt][1] = As[64 * ABS + (mrow + 8) * ABS + c0];
                al[mt][2] = As[64 * ABS + mrow * ABS + c0 + 4];
                al[mt][3] = As[64 * ABS + (mrow + 8) * ABS + c0 + 4];
            }
#pragma unroll
            for (int nt = 0; nt < 8; nt++) {
                int ncol = wn * 64 + nt * 8 + g;
                unsigned int bh0 = Bb[ncol * ABS + c0];
                unsigned int bh1 = Bb[ncol * ABS + c0 + 4];
                unsigned int bl0 = Bb[128 * ABS + ncol * ABS + c0];
                unsigned int bl1 = Bb[128 * ABS + ncol * ABS + c0 + 4];
#pragma unroll
                for (int mt = 0; mt < 2; mt++) {
                    mma_bf16(acc[mt][nt], ah[mt], bh0, bh1);
                    mma_bf16(acc[mt][nt], ah[mt], bl0, bl1);
                    mma_bf16(acc[mt][nt], al[mt], bh0, bh1);
                }
            }
        }
        __syncthreads();
    }

    // stage C into smem (aliases staging buffers)
#pragma unroll
    for (int mt = 0; mt < 2; mt++) {
#pragma unroll
        for (int nt = 0; nt < 8; nt++) {
            int row = wm * 32 + mt * 16 + g;
            int col = wn * 64 + nt * 8 + 2 * tg;
            Cs[row * 132 + col]           = acc[mt][nt][0];
            Cs[row * 132 + col + 1]       = acc[mt][nt][1];
            Cs[(row + 8) * 132 + col]     = acc[mt][nt][2];
            Cs[(row + 8) * 132 + col + 1] = acc[mt][nt][3];
        }
    }
    __syncthreads();

    // ---------------- fused epilogue ----------------
    // 128 threads: tx = col slice (8 x 16 cols), ty = row group (16 x 4 rows)
    int tx = tid & 7;
    int ty = tid >> 3;

#pragma unroll
    for (int rr = 0; rr < 4; rr++) {
        int row = ty * 4 + rr;
        int mtok = m0 + row;
        int n = mtok >> 11, t = mtok & 2047;
        const float* crow = Cs + row * 132 + tx * 16;

        if (blockIdx.y == 0) {
            float y[16];
            *(float4*)&y[0]  = *(const float4*)(crow + 0);
            *(float4*)&y[4]  = *(const float4*)(crow + 4);
            *(float4*)&y[8]  = *(const float4*)(crow + 8);
            *(float4*)&y[12] = *(const float4*)(crow + 12);
            float s = 0.0f;
#pragma unroll
            for (int i = 0; i < 16; i++) s += y[i];
            float mean = s * 0.0625f;
            float var = 0.0f;
#pragma unroll
            for (int i = 0; i < 16; i++) { float d = y[i] - mean; var = fmaf(d, d, var); }
            var *= 0.0625f;
            float inv = rsqrtf(var + EPS_LN);
            if (tx < 4) {
#pragma unroll
                for (int i = 0; i < 16; i++)
                    y[i] = fmaf((y[i] - mean) * inv, __ldg(lnqw + i), __ldg(lnqb + i));
                size_t base = ((size_t)(n * NH + tx) * SEQ_T + t) * DH;
                *(float4*)(g_q + base + 0)  = *(float4*)&y[0];
                *(float4*)(g_q + base + 4)  = *(float4*)&y[4];
                *(float4*)(g_q + base + 8)  = *(float4*)&y[8];
                *(float4*)(g_q + base + 12) = *(float4*)&y[12];
            } else {
                int h = tx - 4;
#pragma unroll
                for (int i = 0; i < 16; i++)
                    y[i] = fmaf((y[i] - mean) * inv, __ldg(lnkw + i), __ldg(lnkb + i));
                float nrm = 0.0f;
#pragma unroll
                for (int i = 0; i < 16; i++) nrm = fmaf(y[i], y[i], nrm);
                float rinv = 1.0f / fmaxf(sqrtf(nrm), 1e-12f);
#pragma unroll
                for (int i = 0; i < 16; i++) y[i] *= rinv;
                size_t base = ((size_t)(n * NH + h) * SEQ_T + t) * DH;
                *(float4*)(g_k + base + 0)  = *(float4*)&y[0];
                *(float4*)(g_k + base + 4)  = *(float4*)&y[4];
                *(float4*)(g_k + base + 8)  = *(float4*)&y[8];
                *(float4*)(g_k + base + 12) = *(float4*)&y[12];
            }
        } else {
            if (tx < 4) {
                float y[16];
                *(float4*)&y[0]  = *(const float4*)(crow + 0);
                *(float4*)&y[4]  = *(const float4*)(crow + 4);
                *(float4*)&y[8]  = *(const float4*)(crow + 8);
                *(float4*)&y[12] = *(const float4*)(crow + 12);
                size_t base = ((size_t)(n * NH + tx) * SEQ_T + t) * DH;
                *(float4*)(g_v + base + 0)  = *(float4*)&y[0];
                *(float4*)(g_v + base + 4)  = *(float4*)&y[4];
                *(float4*)(g_v + base + 8)  = *(float4*)&y[8];
                *(float4*)(g_v + base + 12) = *(float4*)&y[12];
            } else if (tx == 4) {
                float y[8];
                *(float4*)&y[0] = *(const float4*)(crow + 0);
                *(float4*)&y[4] = *(const float4*)(crow + 4);
                int b = n >> 4;
                float Kv = fminf(fabsf(__ldg(curv + b)), 10.0f);
                float Sv = fminf(fmaxf(__ldg(ent + b), 0.0f), 5.0f);
#pragma unroll
                for (int h = 0; h < 4; h++) {
                    float be = sigm(y[h] + __ldg(Wbb + h));
                    be = sigm(fmaf(Kv, __ldg(curv_w + h), be));
                    float al = sigm(y[4 + h] + __ldg(Wab + h));
                    al = sigm(fmaf(Sv, __ldg(ent_w + h), al));
                    g_beta[(n * NH + h) * SEQ_T + t] = be;
                    g_alpha[(n * NH + h) * SEQ_T + t] = al;
                }
            }
        }
    }
}

// ---------------- kernel 2a: chunked scan phase1 ----------------
__global__ __launch_bounds__(128) void scan_phase1() {
    __shared__ float sk[8][512];
    __shared__ float sv[8][512];
    __shared__ float sb[8][32];
    __shared__ float sa[8][32];

    int warp = threadIdx.x >> 5;
    int lane = threadIdx.x & 31;
    int g = lane >> 4;
    int row = lane & 15;
    int wg = warp * 2 + g;
    int grp = blockIdx.x * 8 + wg;

    unsigned long long P[8], R[8];
#pragma unroll
    for (int j = 0; j < 8; j++) { P[j] = 0ull; R[j] = 0ull; }
    P[row >> 1] = (row & 1) ? pack2(0.0f, 1.0f) : pack2(1.0f, 0.0f);

    for (int sub = 0; sub < CH / 32; sub++) {
        __syncwarp();
#pragma unroll
        for (int r = 0; r < 8; r++) {
            int f = lane + 32 * r;
            int gg = f >> 7;
            int e = f & 127;
            int grp2 = blockIdx.x * 8 + warp * 2 + gg;
            int rec2 = grp2 >> 4, ch2 = grp2 & 15;
            size_t base4 = ((size_t)rec2 * SEQ_T + ch2 * CH + sub * 32) * 4;
            ((float4*)sk[warp * 2 + gg])[e] = ((const float4*)g_k)[base4 + e];
            ((float4*)sv[warp * 2 + gg])[e] = ((const float4*)g_v)[base4 + e];
        }
#pragma unroll
        for (int r = 0; r < 2; r++) {
            int f = lane + 32 * r;
            int gg = f >> 5;
            int e = f & 31;
            int grp2 = blockIdx.x * 8 + warp * 2 + gg;
            int rec2 = grp2 >> 4, ch2 = grp2 & 15;
            int src = rec2 * SEQ_T + ch2 * CH + sub * 32 + e;
            sb[warp * 2 + gg][e] = g_beta[src];
            sa[warp * 2 + gg][e] = g_alpha[src];
        }
        __syncwarp();

        for (int s = 0; s < 32; s++) {
            unsigned long long kp[8];
            const unsigned long long* kptr = (const unsigned long long*)&sk[wg][s * 16];
#pragma unroll
            for (int j = 0; j < 8; j++) kp[j] = kptr[j];
            float vi = sv[wg][s * 16 + row];
            float be = sb[wg][s];
            float al = sa[wg][s];

            float u = dot16(P, kp);
            float w = dot16(R, kp);
            unsigned long long cu = dup2(-al * u);
            unsigned long long cr = dup2(fmaf(be, vi, -al * w));
#pragma unroll
            for (int j = 0; j < 8; j++) {
                fma2(P[j], cu, kp[j]);
                fma2(R[j], cr, kp[j]);
            }
        }
    }

    size_t obase = ((size_t)grp * 16 + row) * 16;
    unsigned long long* gp = (unsigned long long*)(g_P + obase);
    unsigned long long* gr = (unsigned long long*)(g_R + obase);
#pragma unroll
    for (int j = 0; j < 8; j++) { gp[j] = P[j]; gr[j] = R[j]; }
}

// ---------------- kernel 2b: serial combine ----------------
__global__ __launch_bounds__(128) void scan_combine() {
    __shared__ float sp[8][256];
    __shared__ float sr[8][256];

    int warp = threadIdx.x >> 5;
    int lane = threadIdx.x & 31;
    int g = lane >> 4;
    int row = lane & 15;
    int wg = warp * 2 + g;
    int rec = blockIdx.x * 8 + wg;

    unsigned long long S[8];
#pragma unroll
    for (int j = 0; j < 8; j++) S[j] = 0ull;

    for (int c = 0; c < NCH; c++) {
        size_t sbase = (((size_t)rec * NCH + c) * 16 + row) * 16;
        unsigned long long* gs = (unsigned long long*)(g_S + sbase);
#pragma unroll
        for (int j = 0; j < 8; j++) gs[j] = S[j];

        __syncwarp();
#pragma unroll
        for (int r = 0; r < 4; r++) {
            int f = lane + 32 * r;
            int gg = f >> 6;
            int e = f & 63;
            int rec2 = blockIdx.x * 8 + warp * 2 + gg;
            size_t base4 = ((size_t)rec2 * NCH + c) * 64;
            ((float4*)sp[warp * 2 + gg])[e] = ((const float4*)g_P)[base4 + e];
            ((float4*)sr[warp * 2 + gg])[e] = ((const float4*)g_R)[base4 + e];
        }
        __syncwarp();

        unsigned long long accm[8];
        const unsigned long long* rrow = (const unsigned long long*)&sr[wg][row * 16];
#pragma unroll
        for (int j = 0; j < 8; j++) accm[j] = rrow[j];
#pragma unroll
        for (int l = 0; l < 16; l++) {
            float sl = (l & 1) ? hi32(S[l >> 1]) : lo32(S[l >> 1]);
            unsigned long long sd = dup2(sl);
            const unsigned long long* prow = (const unsigned long long*)&sp[wg][l * 16];
#pragma unroll
            for (int j = 0; j < 8; j++) fma2(accm[j], sd, prow[j]);
        }
#pragma unroll
        for (int j = 0; j < 8; j++) S[j] = accm[j];
    }
}

// ---------------- kernel 2c: chunked scan phase3 ----------------
__global__ __launch_bounds__(128) void scan_phase3() {
    __shared__ float sk[8][512];
    __shared__ float sq[8][512];
    __shared__ float sv[8][512];
    __shared__ float sb[8][32];
    __shared__ float sa[8][32];

    int warp = threadIdx.x >> 5;
    int lane = threadIdx.x & 31;
    int g = lane >> 4;
    int row = lane & 15;
    int wg = warp * 2 + g;
    int grp = blockIdx.x * 8 + wg;

    unsigned long long M[8];
    {
        size_t sbase = ((size_t)grp * 16 + row) * 16;
        const unsigned long long* gs = (const unsigned long long*)(g_S + sbase);
#pragma unroll
        for (int j = 0; j < 8; j++) M[j] = gs[j];
    }

    for (int sub = 0; sub < CH / 32; sub++) {
        __syncwarp();
#pragma unroll
        for (int r = 0; r < 8; r++) {
            int f = lane + 32 * r;
            int gg = f >> 7;
            int e = f & 127;
            int grp2 = blockIdx.x * 8 + warp * 2 + gg;
            int rec2 = grp2 >> 4, ch2 = grp2 & 15;
            size_t base4 = ((size_t)rec2 * SEQ_T + ch2 * CH + sub * 32) * 4;
            ((float4*)sk[warp * 2 + gg])[e] = ((const float4*)g_k)[base4 + e];
            ((float4*)sq[warp * 2 + gg])[e] = ((const float4*)g_q)[base4 + e];
            ((float4*)sv[warp * 2 + gg])[e] = ((const float4*)g_v)[base4 + e];
        }
#pragma unroll
        for (int r = 0; r < 2; r++) {
            int f = lane + 32 * r;
            int gg = f >> 5;
            int e = f & 31;
            int grp2 = blockIdx.x * 8 + warp * 2 + gg;
            int rec2 = grp2 >> 4, ch2 = grp2 & 15;
            int src = rec2 * SEQ_T + ch2 * CH + sub * 32 + e;
            sb[warp * 2 + gg][e] = g_beta[src];
            sa[warp * 2 + gg][e] = g_alpha[src];
        }
        __syncwarp();

        for (int s = 0; s < 32; s++) {
            unsigned long long kp[8], qp[8];
            const unsigned long long* kptr = (const unsigned long long*)&sk[wg][s * 16];
            const unsigned long long* qptr = (const unsigned long long*)&sq[wg][s * 16];
#pragma unroll
            for (int j = 0; j < 8; j++) { kp[j] = kptr[j]; qp[j] = qptr[j]; }
            float vi = sv[wg][s * 16 + row];
            float be = sb[wg][s];
            float al = sa[wg][s];

            float mk = dot16(M, kp);
            unsigned long long cd = dup2(fmaf(be, vi, -al * mk));
#pragma unroll
            for (int j = 0; j < 8; j++) fma2(M[j], cd, kp[j]);
            float o = dot16(M, qp);
            sv[wg][s * 16 + row] = o;
        }
        __syncwarp();
#pragma unroll
        for (int r = 0; r < 8; r++) {
            int f = lane + 32 * r;
            int gg = f >> 7;
            int e = f & 127;
            int grp2 = blockIdx.x * 8 + warp * 2 + gg;
            int rec2 = grp2 >> 4, ch2 = grp2 & 15;
            size_t base4 = ((size_t)rec2 * SEQ_T + ch2 * CH + sub * 32) * 4;
            ((float4*)g_o)[base4 + e] = ((const float4*)sv[warp * 2 + gg])[e];
        }
    }
}

// ---------------- kernel 4: output projection (f32x2) + permuted write ----------
__global__ __launch_bounds__(192) void final_proj(const float* __restrict__ out_b,
                                                  float* __restrict__ out) {
    __shared__ float so[64][20];
    int n = blockIdx.x;
    int tbase = blockIdx.y * 128;
    int kk = threadIdx.x;
    float bias = out_b[kk];
    int b = n >> 4;
    int p = n & 15;

    for (int tile = 0; tile < 8; tile++) {
        int t0 = tbase + tile * 16;
        __syncthreads();
#pragma unroll
        for (int r = 0; r < 6; r++) {
            int e = kk + 192 * r;
            if (e < 1024) {
                int h = e >> 8;
                int tt = (e >> 4) & 15;
                int i = e & 15;
                so[h * 16 + i][tt] =
                    g_o[((size_t)(n * NH + h) * SEQ_T + t0 + tt) * DH + i];
            }
        }
        __syncthreads();

        unsigned long long a8[8];
#pragma unroll
        for (int j = 0; j < 8; j++) a8[j] = 0ull;
#pragma unroll 4
        for (int m = 0; m < 64; m++) {
            unsigned long long wd = dup2(g_wtr[m * KOUT + kk]);
            const unsigned long long* op = (const unsigned long long*)&so[m][0];
#pragma unroll
            for (int j = 0; j < 8; j++) fma2(a8[j], wd, op[j]);
        }
#pragma unroll
        for (int j = 0; j < 8; j++) {
            size_t ob = (((size_t)b * SEQ_T + t0 + 2 * j) * N_P + p) * KOUT + kk;
            out[ob] = lo32(a8[j]) + bias;
            out[ob + (size_t)N_P * KOUT] = hi32(a8[j]) + bias;
        }
    }
}

// ---------------- launch ----------------
extern "C" void kernel_launch(void* const* d_in, const int* in_sizes, int n_in,
                              void* d_out, int out_size) {
    const float* joint  = (const float*)d_in[0];
    const float* curvat = (const float*)d_in[1];
    const float* entrop = (const float*)d_in[2];
    const float* Wq     = (const float*)d_in[3];
    const float* Wk     = (const float*)d_in[4];
    const float* Wv     = (const float*)d_in[5];
    const float* Wbw    = (const float*)d_in[6];
    const float* Wbb    = (const float*)d_in[7];
    const float* Waw    = (const float*)d_in[8];
    const float* Wab    = (const float*)d_in[9];
    const float* curv_w = (const float*)d_in[10];
    const float* ent_w  = (const float*)d_in[11];
    const float* out_w  = (const float*)d_in[12];
    const float* out_b  = (const float*)d_in[13];
    const float* lnqw   = (const float*)d_in[14];
    const float* lnqb   = (const float*)d_in[15];
    const float* lnkw   = (const float*)d_in[16];
    const float* lnkb   = (const float*)d_in[17];
    float* out = (float*)d_out;

    cudaFuncSetAttribute(gemm_tc2, cudaFuncAttributeMaxDynamicSharedMemorySize,
                         GEMM_SMEM);

    constexpr int OW_HALF = KOUT * MEMD / 2;
    pack_wbf<<<(256 * 128 + 255) / 256, 256>>>(Wq, Wk, Wv, Wbw, Waw);
    pack_outw<<<(OW_HALF + 255) / 256, 256>>>(out_w, 0);
    pack_outw<<<(OW_HALF + 255) / 256, 256>>>(out_w, OW_HALF);
    gemm_tc2<<<dim3(NT / 64, 2), 128, GEMM_SMEM>>>(joint, curvat, entrop, Wbb, Wab,
                                                   curv_w, ent_w, lnqw, lnqb,
                                                   lnkw, lnkb);
    scan_phase1<<<NGRP / 8, 128>>>();
    scan_combine<<<NREC / 8, 128>>>();
    scan_phase3<<<NGRP / 8, 128>>>();
    final_proj<<<dim3(NSEQ, SEQ_T / 128), 192>>>(out_b, out);
}

// round 8
// speedup vs baseline: 1.8792x; 1.0891x over previous
#include <cuda_runtime.h>
#include <cuda_fp16.h>
#include <math.h>

// Problem constants
constexpr int N_B   = 4;
constexpr int SEQ_T = 2048;
constexpr int N_P   = 16;
constexpr int JD    = 256;
constexpr int NH    = 4;
constexpr int DH    = 16;
constexpr int MEMD  = 64;
constexpr int KOUT  = 192;
constexpr int NSEQ  = N_B * N_P;        // 64
constexpr int NT    = NSEQ * SEQ_T;     // 131072 tokens
constexpr float EPS_LN = 1e-5f;

// chunked-scan constants
constexpr int CH   = 128;
constexpr int NCH  = SEQ_T / CH;        // 16
constexpr int NREC = NSEQ * NH;         // 256
constexpr int NGRP = NREC * NCH;        // 4096

// GEMM constants
constexpr int ABS = 20;                     // padded word stride for smem rows
constexpr int B_BUF_W = 2 * 128 * ABS;      // words per B buffer (hi+lo) = 5120
constexpr int GEMM_SMEM = (64 * ABS + 2 * B_BUF_W) * 4;  // 46080 B
constexpr float WSCALE = 16384.0f;          // 2^14 pre-scale for B split
constexpr float DESC   = 1.0f / 16384.0f;

// ---------------- scratch (device globals; allocation-free) ----------------
__device__ unsigned int g_wh[256 * 128];     // W hi fp16 pairs (scaled), [n][c]
__device__ unsigned int g_wl[256 * 128];     // W lo fp16 pairs (scaled)
__device__ float g_wtr[MEMD * KOUT];
__device__ float g_q[(size_t)NREC * SEQ_T * DH];
__device__ float g_k[(size_t)NREC * SEQ_T * DH];
__device__ float g_v[(size_t)NREC * SEQ_T * DH];
__device__ float g_o[(size_t)NREC * SEQ_T * DH];
__device__ float g_beta[NREC * SEQ_T];
__device__ float g_alpha[NREC * SEQ_T];
__device__ float g_P[(size_t)NGRP * 256];
__device__ float g_R[(size_t)NGRP * 256];
__device__ float g_S[(size_t)NGRP * 256];

// ---------------- f32x2 helpers ----------------
__device__ __forceinline__ unsigned long long dup2(float x) {
    unsigned long long r;
    unsigned int xi = __float_as_uint(x);
    asm("mov.b64 %0, {%1, %1};" : "=l"(r) : "r"(xi));
    return r;
}
__device__ __forceinline__ unsigned long long pack2(float lo, float hi) {
    unsigned long long r;
    asm("mov.b64 %0, {%1, %2};" : "=l"(r) : "f"(lo), "f"(hi));
    return r;
}
__device__ __forceinline__ void fma2(unsigned long long& acc, unsigned long long a,
                                     unsigned long long b) {
    asm("fma.rn.f32x2 %0, %1, %2, %0;" : "+l"(acc) : "l"(a), "l"(b));
}
__device__ __forceinline__ unsigned long long mul2(unsigned long long a, unsigned long long b) {
    unsigned long long r;
    asm("mul.rn.f32x2 %0, %1, %2;" : "=l"(r) : "l"(a), "l"(b));
    return r;
}
__device__ __forceinline__ unsigned long long add2(unsigned long long a, unsigned long long b) {
    unsigned long long r;
    asm("add.rn.f32x2 %0, %1, %2;" : "=l"(r) : "l"(a), "l"(b));
    return r;
}
__device__ __forceinline__ float lo32(unsigned long long v) {
    return __uint_as_float((unsigned int)(v & 0xffffffffull));
}
__device__ __forceinline__ float hi32(unsigned long long v) {
    return __uint_as_float((unsigned int)(v >> 32));
}
__device__ __forceinline__ float dot16(const unsigned long long* A, const unsigned long long* k) {
    unsigned long long c0 = mul2(A[0], k[0]);
    unsigned long long c1 = mul2(A[1], k[1]);
    unsigned long long c2 = mul2(A[2], k[2]);
    unsigned long long c3 = mul2(A[3], k[3]);
    fma2(c0, A[4], k[4]);
    fma2(c1, A[5], k[5]);
    fma2(c2, A[6], k[6]);
    fma2(c3, A[7], k[7]);
    unsigned long long d0 = add2(c0, c1);
    unsigned long long d1 = add2(c2, c3);
    unsigned long long e = add2(d0, d1);
    return lo32(e) + hi32(e);
}
__device__ __forceinline__ float sigm(float x) { return 1.0f / (1.0f + expf(-x)); }

// ---------------- fp16 helpers ----------------
__device__ __forceinline__ unsigned int h2u(__half2 h) {
    return *(unsigned int*)&h;
}

// ---------------- mma m16n8k16 fp16 ----------------
__device__ __forceinline__ void mma_f16(float* c, const unsigned int* a,
                                        unsigned int b0, unsigned int b1) {
    asm volatile(
        "mma.sync.aligned.m16n8k16.row.col.f32.f16.f16.f32 "
        "{%0,%1,%2,%3}, {%4,%5,%6,%7}, {%8,%9}, {%0,%1,%2,%3};"
        : "+f"(c[0]), "+f"(c[1]), "+f"(c[2]), "+f"(c[3])
        : "r"(a[0]), "r"(a[1]), "r"(a[2]), "r"(a[3]), "r"(b0), "r"(b1));
}

// ---------------- cp.async helpers ----------------
__device__ __forceinline__ void cp_async16(unsigned int saddr, const void* g) {
    asm volatile("cp.async.cg.shared.global [%0], [%1], 16;"
                 :: "r"(saddr), "l"(__cvta_generic_to_global(g)) : "memory");
}
#define CP_COMMIT() asm volatile("cp.async.commit_group;" ::: "memory")
#define CP_WAIT(n)  asm volatile("cp.async.wait_group %0;" :: "n"(n) : "memory")

// ---------------- kernel 0a: split scaled weights to fp16 hi/lo ----------------
__global__ void pack_wbf(const float* __restrict__ Wq, const float* __restrict__ Wk,
                         const float* __restrict__ Wv, const float* __restrict__ Wbw,
                         const float* __restrict__ Waw) {
    int idx = blockIdx.x * blockDim.x + threadIdx.x;
    if (idx >= 256 * 128) return;
    int n = idx >> 7;
    int c = idx & 127;
    int k0 = 2 * c;
    float x = 0.0f, y = 0.0f;
    if (n < 64)        { x = Wq[n * JD + k0];        y = Wq[n * JD + k0 + 1]; }
    else if (n < 128)  { x = Wk[(n-64) * JD + k0];   y = Wk[(n-64) * JD + k0 + 1]; }
    else if (n < 192)  { x = Wv[(n-128) * JD + k0];  y = Wv[(n-128) * JD + k0 + 1]; }
    else if (n < 196)  { x = Wbw[(n-192) * JD + k0]; y = Wbw[(n-192) * JD + k0 + 1]; }
    else if (n < 200)  { x = Waw[(n-196) * JD + k0]; y = Waw[(n-196) * JD + k0 + 1]; }
    x *= WSCALE;
    y *= WSCALE;
    __half hx = __float2half_rn(x);
    __half hy = __float2half_rn(y);
    __half lx = __float2half_rn(x - __half2float(hx));
    __half ly = __float2half_rn(y - __half2float(hy));
    g_wh[idx] = ((unsigned int)__half_as_ushort(hy) << 16) | __half_as_ushort(hx);
    g_wl[idx] = ((unsigned int)__half_as_ushort(ly) << 16) | __half_as_ushort(lx);
}

// ---------------- kernel 0b: transpose out_w (half range; launched twice) --------
__global__ void pack_outw(const float* __restrict__ out_w, int off) {
    int idx = off + blockIdx.x * blockDim.x + threadIdx.x;
    if (idx >= KOUT * MEMD) return;
    int k = idx / MEMD;
    int m = idx % MEMD;
    g_wtr[m * KOUT + k] = out_w[idx];
}

// ---------------- kernel 1: pipelined fp16 tensor-core GEMM + fused epilogue ------
// BM=64, BN=128 (grid.y), BK=32 x 8 chunks, 128 threads = 4 warps.
// Warp tile 32x64. A single fp16 (converted in-flight); B fp16 hi/lo (scaled 2^14).
// 2 mma chains into one fp32 acc: C = A*Bh + A*Bl, descaled in epilogue.
__global__ __launch_bounds__(128, 4) void gemm_tc2(
        const float* __restrict__ X,
        const float* __restrict__ curv, const float* __restrict__ ent,
        const float* __restrict__ Wbb,  const float* __restrict__ Wab,
        const float* __restrict__ curv_w, const float* __restrict__ ent_w,
        const float* __restrict__ lnqw, const float* __restrict__ lnqb,
        const float* __restrict__ lnkw, const float* __restrict__ lnkb) {
    extern __shared__ __align__(16) char dsm[];
    unsigned int* As = (unsigned int*)dsm;            // [64][ABS] fp16 pairs
    unsigned int* Bs = As + 64 * ABS;                 // [2 bufs][2][128][ABS]
    float* Cs = (float*)dsm;                          // [64][132] (aliases)

    int tid = threadIdx.x;
    int lane = tid & 31;
    int warp = tid >> 5;
    int wm = warp & 1;
    int wn = warp >> 1;          // 0-1
    int g = lane >> 2;
    int tg = lane & 3;
    int m0 = blockIdx.x * 64;
    int n0 = blockIdx.y * 128;

    unsigned int sb_bs = (unsigned int)__cvta_generic_to_shared(Bs);

    float acc[2][8][4];
#pragma unroll
    for (int mt = 0; mt < 2; mt++)
#pragma unroll
        for (int nt = 0; nt < 8; nt++)
#pragma unroll
            for (int i = 0; i < 4; i++) acc[mt][nt][i] = 0.0f;

    int am = tid >> 3;           // base row; r adds 16 rows
    int aq = tid & 7;

    float4 pa[4];
#pragma unroll
    for (int r = 0; r < 4; r++)
        pa[r] = *(const float4*)(X + (size_t)(m0 + am + 16 * r) * JD + aq * 4);
    // B chunk 0 -> buf 0
    {
        unsigned int bbase = sb_bs;
        int n = tid >> 2, cq = tid & 3;
#pragma unroll
        for (int r = 0; r < 4; r++)
            cp_async16(bbase + ((n + 32 * r) * ABS + cq * 4) * 4,
                       g_wh + (n0 + n + 32 * r) * 128 + cq * 4);
#pragma unroll
        for (int r = 0; r < 4; r++)
            cp_async16(bbase + (128 * ABS + (n + 32 * r) * ABS + cq * 4) * 4,
                       g_wl + (n0 + n + 32 * r) * 128 + cq * 4);
        CP_COMMIT();
    }

    for (int kc = 0; kc < 8; kc++) {
        // STS A (fp16 convert) from prefetch regs
#pragma unroll
        for (int r = 0; r < 4; r++) {
            int m = am + 16 * r;
            unsigned int w0 = h2u(__floats2half2_rn(pa[r].x, pa[r].y));
            unsigned int w1 = h2u(__floats2half2_rn(pa[r].z, pa[r].w));
            *(uint2*)(&As[m * ABS + 2 * aq]) = make_uint2(w0, w1);
        }
        if (kc < 7) {
#pragma unroll
            for (int r = 0; r < 4; r++)
                pa[r] = *(const float4*)(X + (size_t)(m0 + am + 16 * r) * JD +
                                         (kc + 1) * 32 + aq * 4);
            unsigned int bbase = sb_bs + ((kc + 1) & 1) * B_BUF_W * 4;
            int n = tid >> 2, cq = tid & 3;
#pragma unroll
            for (int r = 0; r < 4; r++)
                cp_async16(bbase + ((n + 32 * r) * ABS + cq * 4) * 4,
                           g_wh + (n0 + n + 32 * r) * 128 + (kc + 1) * 16 + cq * 4);
#pragma unroll
            for (int r = 0; r < 4; r++)
                cp_async16(bbase + (128 * ABS + (n + 32 * r) * ABS + cq * 4) * 4,
                           g_wl + (n0 + n + 32 * r) * 128 + (kc + 1) * 16 + cq * 4);
            CP_COMMIT();
            CP_WAIT(1);
        } else {
            CP_WAIT(0);
        }
        __syncthreads();

        const unsigned int* Bb = Bs + (kc & 1) * B_BUF_W;
#pragma unroll
        for (int kt = 0; kt < 2; kt++) {
            int c0 = kt * 8 + tg;
            unsigned int ah[2][4];
#pragma unroll
            for (int mt = 0; mt < 2; mt++) {
                int mrow = wm * 32 + mt * 16 + g;
                ah[mt][0] = As[mrow * ABS + c0];
                ah[mt][1] = As[(mrow + 8) * ABS + c0];
                ah[mt][2] = As[mrow * ABS + c0 + 4];
                ah[mt][3] = As[(mrow + 8) * ABS + c0 + 4];
            }
#pragma unroll
            for (int nt = 0; nt < 8; nt++) {
                int ncol = wn * 64 + nt * 8 + g;
                unsigned int bh0 = Bb[ncol * ABS + c0];
                unsigned int bh1 = Bb[ncol * ABS + c0 + 4];
                unsigned int bl0 = Bb[128 * ABS + ncol * ABS + c0];
                unsigned int bl1 = Bb[128 * ABS + ncol * ABS + c0 + 4];
#pragma unroll
                for (int mt = 0; mt < 2; mt++) {
                    mma_f16(acc[mt][nt], ah[mt], bh0, bh1);
                    mma_f16(acc[mt][nt], ah[mt], bl0, bl1);
                }
            }
        }
        __syncthreads();
    }

    // stage C into smem (aliases staging buffers)
#pragma unroll
    for (int mt = 0; mt < 2; mt++) {
#pragma unroll
        for (int nt = 0; nt < 8; nt++) {
            int row = wm * 32 + mt * 16 + g;
            int col = wn * 64 + nt * 8 + 2 * tg;
            Cs[row * 132 + col]           = acc[mt][nt][0];
            Cs[row * 132 + col + 1]       = acc[mt][nt][1];
            Cs[(row + 8) * 132 + col]     = acc[mt][nt][2];
            Cs[(row + 8) * 132 + col + 1] = acc[mt][nt][3];
        }
    }
    __syncthreads();

    // ---------------- fused epilogue (with 2^-14 descale) ----------------
    int tx = tid & 7;
    int ty = tid >> 3;

#pragma unroll
    for (int rr = 0; rr < 4; rr++) {
        int row = ty * 4 + rr;
        int mtok = m0 + row;
        int n = mtok >> 11, t = mtok & 2047;
        const float* crow = Cs + row * 132 + tx * 16;

        if (blockIdx.y == 0) {
            float y[16];
            *(float4*)&y[0]  = *(const float4*)(crow + 0);
            *(float4*)&y[4]  = *(const float4*)(crow + 4);
            *(float4*)&y[8]  = *(const float4*)(crow + 8);
            *(float4*)&y[12] = *(const float4*)(crow + 12);
#pragma unroll
            for (int i = 0; i < 16; i++) y[i] *= DESC;
            float s = 0.0f;
#pragma unroll
            for (int i = 0; i < 16; i++) s += y[i];
            float mean = s * 0.0625f;
            float var = 0.0f;
#pragma unroll
            for (int i = 0; i < 16; i++) { float d = y[i] - mean; var = fmaf(d, d, var); }
            var *= 0.0625f;
            float inv = rsqrtf(var + EPS_LN);
            if (tx < 4) {
#pragma unroll
                for (int i = 0; i < 16; i++)
                    y[i] = fmaf((y[i] - mean) * inv, __ldg(lnqw + i), __ldg(lnqb + i));
                size_t base = ((size_t)(n * NH + tx) * SEQ_T + t) * DH;
                *(float4*)(g_q + base + 0)  = *(float4*)&y[0];
                *(float4*)(g_q + base + 4)  = *(float4*)&y[4];
                *(float4*)(g_q + base + 8)  = *(float4*)&y[8];
                *(float4*)(g_q + base + 12) = *(float4*)&y[12];
            } else {
                int h = tx - 4;
#pragma unroll
                for (int i = 0; i < 16; i++)
                    y[i] = fmaf((y[i] - mean) * inv, __ldg(lnkw + i), __ldg(lnkb + i));
                float nrm = 0.0f;
#pragma unroll
                for (int i = 0; i < 16; i++) nrm = fmaf(y[i], y[i], nrm);
                float rinv = 1.0f / fmaxf(sqrtf(nrm), 1e-12f);
#pragma unroll
                for (int i = 0; i < 16; i++) y[i] *= rinv;
                size_t base = ((size_t)(n * NH + h) * SEQ_T + t) * DH;
                *(float4*)(g_k + base + 0)  = *(float4*)&y[0];
                *(float4*)(g_k + base + 4)  = *(float4*)&y[4];
                *(float4*)(g_k + base + 8)  = *(float4*)&y[8];
                *(float4*)(g_k + base + 12) = *(float4*)&y[12];
            }
        } else {
            if (tx < 4) {
                float y[16];
                *(float4*)&y[0]  = *(const float4*)(crow + 0);
                *(float4*)&y[4]  = *(const float4*)(crow + 4);
                *(float4*)&y[8]  = *(const float4*)(crow + 8);
                *(float4*)&y[12] = *(const float4*)(crow + 12);
#pragma unroll
                for (int i = 0; i < 16; i++) y[i] *= DESC;
                size_t base = ((size_t)(n * NH + tx) * SEQ_T + t) * DH;
                *(float4*)(g_v + base + 0)  = *(float4*)&y[0];
                *(float4*)(g_v + base + 4)  = *(float4*)&y[4];
                *(float4*)(g_v + base + 8)  = *(float4*)&y[8];
                *(float4*)(g_v + base + 12) = *(float4*)&y[12];
            } else if (tx == 4) {
                float y[8];
                *(float4*)&y[0] = *(const float4*)(crow + 0);
                *(float4*)&y[4] = *(const float4*)(crow + 4);
#pragma unroll
                for (int i = 0; i < 8; i++) y[i] *= DESC;
                int b = n >> 4;
                float Kv = fminf(fabsf(__ldg(curv + b)), 10.0f);
                float Sv = fminf(fmaxf(__ldg(ent + b), 0.0f), 5.0f);
#pragma unroll
                for (int h = 0; h < 4; h++) {
                    float be = sigm(y[h] + __ldg(Wbb + h));
                    be = sigm(fmaf(Kv, __ldg(curv_w + h), be));
                    float al = sigm(y[4 + h] + __ldg(Wab + h));
                    al = sigm(fmaf(Sv, __ldg(ent_w + h), al));
                    g_beta[(n * NH + h) * SEQ_T + t] = be;
                    g_alpha[(n * NH + h) * SEQ_T + t] = al;
                }
            }
        }
    }
}

// ---------------- kernel 2a: chunked scan phase1 ----------------
__global__ __launch_bounds__(128) void scan_phase1() {
    __shared__ float sk[8][512];
    __shared__ float sv[8][512];
    __shared__ float sb[8][32];
    __shared__ float sa[8][32];

    int warp = threadIdx.x >> 5;
    int lane = threadIdx.x & 31;
    int g = lane >> 4;
    int row = lane & 15;
    int wg = warp * 2 + g;
    int grp = blockIdx.x * 8 + wg;

    unsigned long long P[8], R[8];
#pragma unroll
    for (int j = 0; j < 8; j++) { P[j] = 0ull; R[j] = 0ull; }
    P[row >> 1] = (row & 1) ? pack2(0.0f, 1.0f) : pack2(1.0f, 0.0f);

    for (int sub = 0; sub < CH / 32; sub++) {
        __syncwarp();
#pragma unroll
        for (int r = 0; r < 8; r++) {
            int f = lane + 32 * r;
            int gg = f >> 7;
            int e = f & 127;
            int grp2 = blockIdx.x * 8 + warp * 2 + gg;
            int rec2 = grp2 >> 4, ch2 = grp2 & 15;
            size_t base4 = ((size_t)rec2 * SEQ_T + ch2 * CH + sub * 32) * 4;
            ((float4*)sk[warp * 2 + gg])[e] = ((const float4*)g_k)[base4 + e];
            ((float4*)sv[warp * 2 + gg])[e] = ((const float4*)g_v)[base4 + e];
        }
#pragma unroll
        for (int r = 0; r < 2; r++) {
            int f = lane + 32 * r;
            int gg = f >> 5;
            int e = f & 31;
            int grp2 = blockIdx.x * 8 + warp * 2 + gg;
            int rec2 = grp2 >> 4, ch2 = grp2 & 15;
            int src = rec2 * SEQ_T + ch2 * CH + sub * 32 + e;
            sb[warp * 2 + gg][e] = g_beta[src];
            sa[warp * 2 + gg][e] = g_alpha[src];
        }
        __syncwarp();

        for (int s = 0; s < 32; s++) {
            unsigned long long kp[8];
            const unsigned long long* kptr = (const unsigned long long*)&sk[wg][s * 16];
#pragma unroll
            for (int j = 0; j < 8; j++) kp[j] = kptr[j];
            float vi = sv[wg][s * 16 + row];
            float be = sb[wg][s];
            float al = sa[wg][s];

            float u = dot16(P, kp);
            float w = dot16(R, kp);
            unsigned long long cu = dup2(-al * u);
            unsigned long long cr = dup2(fmaf(be, vi, -al * w));
#pragma unroll
            for (int j = 0; j < 8; j++) {
                fma2(P[j], cu, kp[j]);
                fma2(R[j], cr, kp[j]);
            }
        }
    }

    size_t obase = ((size_t)grp * 16 + row) * 16;
    unsigned long long* gp = (unsigned long long*)(g_P + obase);
    unsigned long long* gr = (unsigned long long*)(g_R + obase);
#pragma unroll
    for (int j = 0; j < 8; j++) { gp[j] = P[j]; gr[j] = R[j]; }
}

// ---------------- kernel 2b: serial combine ----------------
__global__ __launch_bounds__(128) void scan_combine() {
    __shared__ float sp[8][256];
    __shared__ float sr[8][256];

    int warp = threadIdx.x >> 5;
    int lane = threadIdx.x & 31;
    int g = lane >> 4;
    int row = lane & 15;
    int wg = warp * 2 + g;
    int rec = blockIdx.x * 8 + wg;

    unsigned long long S[8];
#pragma unroll
    for (int j = 0; j < 8; j++) S[j] = 0ull;

    for (int c = 0; c < NCH; c++) {
        size_t sbase = (((size_t)rec * NCH + c) * 16 + row) * 16;
        unsigned long long* gs = (unsigned long long*)(g_S + sbase);
#pragma unroll
        for (int j = 0; j < 8; j++) gs[j] = S[j];

        __syncwarp();
#pragma unroll
        for (int r = 0; r < 4; r++) {
            int f = lane + 32 * r;
            int gg = f >> 6;
            int e = f & 63;
            int rec2 = blockIdx.x * 8 + warp * 2 + gg;
            size_t base4 = ((size_t)rec2 * NCH + c) * 64;
            ((float4*)sp[warp * 2 + gg])[e] = ((const float4*)g_P)[base4 + e];
            ((float4*)sr[warp * 2 + gg])[e] = ((const float4*)g_R)[base4 + e];
        }
        __syncwarp();

        unsigned long long accm[8];
        const unsigned long long* rrow = (const unsigned long long*)&sr[wg][row * 16];
#pragma unroll
        for (int j = 0; j < 8; j++) accm[j] = rrow[j];
#pragma unroll
        for (int l = 0; l < 16; l++) {
            float sl = (l & 1) ? hi32(S[l >> 1]) : lo32(S[l >> 1]);
            unsigned long long sd = dup2(sl);
            const unsigned long long* prow = (const unsigned long long*)&sp[wg][l * 16];
#pragma unroll
            for (int j = 0; j < 8; j++) fma2(accm[j], sd, prow[j]);
        }
#pragma unroll
        for (int j = 0; j < 8; j++) S[j] = accm[j];
    }
}

// ---------------- kernel 2c: chunked scan phase3 ----------------
__global__ __launch_bounds__(128) void scan_phase3() {
    __shared__ float sk[8][512];
    __shared__ float sq[8][512];
    __shared__ float sv[8][512];
    __shared__ float sb[8][32];
    __shared__ float sa[8][32];

    int warp = threadIdx.x >> 5;
    int lane = threadIdx.x & 31;
    int g = lane >> 4;
    int row = lane & 15;
    int wg = warp * 2 + g;
    int grp = blockIdx.x * 8 + wg;

    unsigned long long M[8];
    {
        size_t sbase = ((size_t)grp * 16 + row) * 16;
        const unsigned long long* gs = (const unsigned long long*)(g_S + sbase);
#pragma unroll
        for (int j = 0; j < 8; j++) M[j] = gs[j];
    }

    for (int sub = 0; sub < CH / 32; sub++) {
        __syncwarp();
#pragma unroll
        for (int r = 0; r < 8; r++) {
            int f = lane + 32 * r;
            int gg = f >> 7;
            int e = f & 127;
            int grp2 = blockIdx.x * 8 + warp * 2 + gg;
            int rec2 = grp2 >> 4, ch2 = grp2 & 15;
            size_t base4 = ((size_t)rec2 * SEQ_T + ch2 * CH + sub * 32) * 4;
            ((float4*)sk[warp * 2 + gg])[e] = ((const float4*)g_k)[base4 + e];
            ((float4*)sq[warp * 2 + gg])[e] = ((const float4*)g_q)[base4 + e];
            ((float4*)sv[warp * 2 + gg])[e] = ((const float4*)g_v)[base4 + e];
        }
#pragma unroll
        for (int r = 0; r < 2; r++) {
            int f = lane + 32 * r;
            int gg = f >> 5;
            int e = f & 31;
            int grp2 = blockIdx.x * 8 + warp * 2 + gg;
            int rec2 = grp2 >> 4, ch2 = grp2 & 15;
            int src = rec2 * SEQ_T + ch2 * CH + sub * 32 + e;
            sb[warp * 2 + gg][e] = g_beta[src];
            sa[warp * 2 + gg][e] = g_alpha[src];
        }
        __syncwarp();

        for (int s = 0; s < 32; s++) {
            unsigned long long kp[8], qp[8];
            const unsigned long long* kptr = (const unsigned long long*)&sk[wg][s * 16];
            const unsigned long long* qptr = (const unsigned long long*)&sq[wg][s * 16];
#pragma unroll
            for (int j = 0; j < 8; j++) { kp[j] = kptr[j]; qp[j] = qptr[j]; }
            float vi = sv[wg][s * 16 + row];
            float be = sb[wg][s];
            float al = sa[wg][s];

            float mk = dot16(M, kp);
            unsigned long long cd = dup2(fmaf(be, vi, -al * mk));
#pragma unroll
            for (int j = 0; j < 8; j++) fma2(M[j], cd, kp[j]);
            float o = dot16(M, qp);
            sv[wg][s * 16 + row] = o;
        }
        __syncwarp();
#pragma unroll
        for (int r = 0; r < 8; r++) {
            int f = lane + 32 * r;
            int gg = f >> 7;
            int e = f & 127;
            int grp2 = blockIdx.x * 8 + warp * 2 + gg;
            int rec2 = grp2 >> 4, ch2 = grp2 & 15;
            size_t base4 = ((size_t)rec2 * SEQ_T + ch2 * CH + sub * 32) * 4;
            ((float4*)g_o)[base4 + e] = ((const float4*)sv[warp * 2 + gg])[e];
        }
    }
}

// ---------------- kernel 4: output projection (f32x2) + permuted write ----------
__global__ __launch_bounds__(192) void final_proj(const float* __restrict__ out_b,
                                                  float* __restrict__ out) {
    __shared__ float so[64][20];
    int n = blockIdx.x;
    int tbase = blockIdx.y * 128;
    int kk = threadIdx.x;
    float bias = out_b[kk];
    int b = n >> 4;
    int p = n & 15;

    for (int tile = 0; tile < 8; tile++) {
        int t0 = tbase + tile * 16;
        __syncthreads();
#pragma unroll
        for (int r = 0; r < 6; r++) {
            int e = kk + 192 * r;
            if (e < 1024) {
                int h = e >> 8;
                int tt = (e >> 4) & 15;
                int i = e & 15;
                so[h * 16 + i][tt] =
                    g_o[((size_t)(n * NH + h) * SEQ_T + t0 + tt) * DH + i];
            }
        }
        __syncthreads();

        unsigned long long a8[8];
#pragma unroll
        for (int j = 0; j < 8; j++) a8[j] = 0ull;
#pragma unroll 4
        for (int m = 0; m < 64; m++) {
            unsigned long long wd = dup2(g_wtr[m * KOUT + kk]);
            const unsigned long long* op = (const unsigned long long*)&so[m][0];
#pragma unroll
            for (int j = 0; j < 8; j++) fma2(a8[j], wd, op[j]);
        }
#pragma unroll
        for (int j = 0; j < 8; j++) {
            size_t ob = (((size_t)b * SEQ_T + t0 + 2 * j) * N_P + p) * KOUT + kk;
            out[ob] = lo32(a8[j]) + bias;
            out[ob + (size_t)N_P * KOUT] = hi32(a8[j]) + bias;
        }
    }
}

// ---------------- launch ----------------
extern "C" void kernel_launch(void* const* d_in, const int* in_sizes, int n_in,
                              void* d_out, int out_size) {
    const float* joint  = (const float*)d_in[0];
    const float* curvat = (const float*)d_in[1];
    const float* entrop = (const float*)d_in[2];
    const float* Wq     = (const float*)d_in[3];
    const float* Wk     = (const float*)d_in[4];
    const float* Wv     = (const float*)d_in[5];
    const float* Wbw    = (const float*)d_in[6];
    const float* Wbb    = (const float*)d_in[7];
    const float* Waw    = (const float*)d_in[8];
    const float* Wab    = (const float*)d_in[9];
    const float* curv_w = (const float*)d_in[10];
    const float* ent_w  = (const float*)d_in[11];
    const float* out_w  = (const float*)d_in[12];
    const float* out_b  = (const float*)d_in[13];
    const float* lnqw   = (const float*)d_in[14];
    const float* lnqb   = (const float*)d_in[15];
    const float* lnkw   = (const float*)d_in[16];
    const float* lnkb   = (const float*)d_in[17];
    float* out = (float*)d_out;

    cudaFuncSetAttribute(gemm_tc2, cudaFuncAttributeMaxDynamicSharedMemorySize,
                         GEMM_SMEM);

    constexpr int OW_HALF = KOUT * MEMD / 2;
    pack_wbf<<<(256 * 128 + 255) / 256, 256>>>(Wq, Wk, Wv, Wbw, Waw);
    pack_outw<<<(OW_HALF + 255) / 256, 256>>>(out_w, 0);
    pack_outw<<<(OW_HALF + 255) / 256, 256>>>(out_w, OW_HALF);
    gemm_tc2<<<dim3(NT / 64, 2), 128, GEMM_SMEM>>>(joint, curvat, entrop, Wbb, Wab,
                                                   curv_w, ent_w, lnqw, lnqb,
                                                   lnkw, lnkb);
    scan_phase1<<<NGRP / 8, 128>>>();
    scan_combine<<<NREC / 8, 128>>>();
    scan_phase3<<<NGRP / 8, 128>>>();
    final_proj<<<dim3(NSEQ, SEQ_T / 128), 192>>>(out_b, out);
}

// round 9
// speedup vs baseline: 2.0026x; 1.0657x over previous
#include <cuda_runtime.h>
#include <cuda_fp16.h>
#include <math.h>

// Problem constants
constexpr int N_B   = 4;
constexpr int SEQ_T = 2048;
constexpr int N_P   = 16;
constexpr int JD    = 256;
constexpr int NH    = 4;
constexpr int DH    = 16;
constexpr int MEMD  = 64;
constexpr int KOUT  = 192;
constexpr int NSEQ  = N_B * N_P;        // 64
constexpr int NT    = NSEQ * SEQ_T;     // 131072 tokens
constexpr float EPS_LN = 1e-5f;

// chunked-scan constants
constexpr int CH   = 128;
constexpr int NCH  = SEQ_T / CH;        // 16
constexpr int NREC = NSEQ * NH;         // 256
constexpr int NGRP = NREC * NCH;        // 4096

// GEMM constants
constexpr int ABS = 20;                     // padded word stride for smem rows
constexpr int B_BUF_W = 2 * 128 * ABS;      // words per B buffer (hi+lo) = 5120
constexpr int GEMM_SMEM = (64 * ABS + 2 * B_BUF_W) * 4;  // 46080 B
constexpr float WSCALE = 16384.0f;          // 2^14 pre-scale for B split
constexpr float DESC   = 1.0f / 16384.0f;

// final_proj constants
constexpr int FP_TT   = 64;                 // t-tile per block
constexpr int FP_SOW  = 66;                 // so row stride (t dim)
constexpr int FP_SMEM = (64 * 192 + 64 * FP_SOW) * 4;   // 66048 B

// ---------------- scratch (device globals; allocation-free) ----------------
__device__ unsigned int g_wh[256 * 128];     // W hi fp16 pairs (scaled), [n][c]
__device__ unsigned int g_wl[256 * 128];     // W lo fp16 pairs (scaled)
__device__ float g_wtr[MEMD * KOUT];
__device__ float g_q[(size_t)NREC * SEQ_T * DH];
__device__ float g_k[(size_t)NREC * SEQ_T * DH];
__device__ float g_v[(size_t)NREC * SEQ_T * DH];
__device__ float g_o[(size_t)NREC * SEQ_T * DH];
__device__ float g_beta[NREC * SEQ_T];
__device__ float g_alpha[NREC * SEQ_T];
__device__ float g_P[(size_t)NGRP * 256];
__device__ float g_R[(size_t)NGRP * 256];
__device__ float g_S[(size_t)NGRP * 256];

// ---------------- f32x2 helpers ----------------
__device__ __forceinline__ unsigned long long dup2(float x) {
    unsigned long long r;
    unsigned int xi = __float_as_uint(x);
    asm("mov.b64 %0, {%1, %1};" : "=l"(r) : "r"(xi));
    return r;
}
__device__ __forceinline__ unsigned long long pack2(float lo, float hi) {
    unsigned long long r;
    asm("mov.b64 %0, {%1, %2};" : "=l"(r) : "f"(lo), "f"(hi));
    return r;
}
__device__ __forceinline__ void fma2(unsigned long long& acc, unsigned long long a,
                                     unsigned long long b) {
    asm("fma.rn.f32x2 %0, %1, %2, %0;" : "+l"(acc) : "l"(a), "l"(b));
}
__device__ __forceinline__ unsigned long long mul2(unsigned long long a, unsigned long long b) {
    unsigned long long r;
    asm("mul.rn.f32x2 %0, %1, %2;" : "=l"(r) : "l"(a), "l"(b));
    return r;
}
__device__ __forceinline__ unsigned long long add2(unsigned long long a, unsigned long long b) {
    unsigned long long r;
    asm("add.rn.f32x2 %0, %1, %2;" : "=l"(r) : "l"(a), "l"(b));
    return r;
}
__device__ __forceinline__ float lo32(unsigned long long v) {
    return __uint_as_float((unsigned int)(v & 0xffffffffull));
}
__device__ __forceinline__ float hi32(unsigned long long v) {
    return __uint_as_float((unsigned int)(v >> 32));
}
__device__ __forceinline__ float dot16(const unsigned long long* A, const unsigned long long* k) {
    unsigned long long c0 = mul2(A[0], k[0]);
    unsigned long long c1 = mul2(A[1], k[1]);
    unsigned long long c2 = mul2(A[2], k[2]);
    unsigned long long c3 = mul2(A[3], k[3]);
    fma2(c0, A[4], k[4]);
    fma2(c1, A[5], k[5]);
    fma2(c2, A[6], k[6]);
    fma2(c3, A[7], k[7]);
    unsigned long long d0 = add2(c0, c1);
    unsigned long long d1 = add2(c2, c3);
    unsigned long long e = add2(d0, d1);
    return lo32(e) + hi32(e);
}
__device__ __forceinline__ float sigm(float x) { return 1.0f / (1.0f + expf(-x)); }

// ---------------- fp16 helpers ----------------
__device__ __forceinline__ unsigned int h2u(__half2 h) {
    return *(unsigned int*)&h;
}

// ---------------- mma m16n8k16 fp16 ----------------
__device__ __forceinline__ void mma_f16(float* c, const unsigned int* a,
                                        unsigned int b0, unsigned int b1) {
    asm volatile(
        "mma.sync.aligned.m16n8k16.row.col.f32.f16.f16.f32 "
        "{%0,%1,%2,%3}, {%4,%5,%6,%7}, {%8,%9}, {%0,%1,%2,%3};"
        : "+f"(c[0]), "+f"(c[1]), "+f"(c[2]), "+f"(c[3])
        : "r"(a[0]), "r"(a[1]), "r"(a[2]), "r"(a[3]), "r"(b0), "r"(b1));
}

// ---------------- cp.async helpers ----------------
__device__ __forceinline__ void cp_async16(unsigned int saddr, const void* g) {
    asm volatile("cp.async.cg.shared.global [%0], [%1], 16;"
                 :: "r"(saddr), "l"(__cvta_generic_to_global(g)) : "memory");
}
#define CP_COMMIT() asm volatile("cp.async.commit_group;" ::: "memory")
#define CP_WAIT(n)  asm volatile("cp.async.wait_group %0;" :: "n"(n) : "memory")

// ---------------- kernel 0a: split scaled weights to fp16 hi/lo ----------------
__global__ void pack_wbf(const float* __restrict__ Wq, const float* __restrict__ Wk,
                         const float* __restrict__ Wv, const float* __restrict__ Wbw,
                         const float* __restrict__ Waw) {
    int idx = blockIdx.x * blockDim.x + threadIdx.x;
    if (idx >= 256 * 128) return;
    int n = idx >> 7;
    int c = idx & 127;
    int k0 = 2 * c;
    float x = 0.0f, y = 0.0f;
    if (n < 64)        { x = Wq[n * JD + k0];        y = Wq[n * JD + k0 + 1]; }
    else if (n < 128)  { x = Wk[(n-64) * JD + k0];   y = Wk[(n-64) * JD + k0 + 1]; }
    else if (n < 192)  { x = Wv[(n-128) * JD + k0];  y = Wv[(n-128) * JD + k0 + 1]; }
    else if (n < 196)  { x = Wbw[(n-192) * JD + k0]; y = Wbw[(n-192) * JD + k0 + 1]; }
    else if (n < 200)  { x = Waw[(n-196) * JD + k0]; y = Waw[(n-196) * JD + k0 + 1]; }
    x *= WSCALE;
    y *= WSCALE;
    __half hx = __float2half_rn(x);
    __half hy = __float2half_rn(y);
    __half lx = __float2half_rn(x - __half2float(hx));
    __half ly = __float2half_rn(y - __half2float(hy));
    g_wh[idx] = ((unsigned int)__half_as_ushort(hy) << 16) | __half_as_ushort(hx);
    g_wl[idx] = ((unsigned int)__half_as_ushort(ly) << 16) | __half_as_ushort(lx);
}

// ---------------- kernel 0b: transpose out_w (half range; launched twice) --------
__global__ void pack_outw(const float* __restrict__ out_w, int off) {
    int idx = off + blockIdx.x * blockDim.x + threadIdx.x;
    if (idx >= KOUT * MEMD) return;
    int k = idx / MEMD;
    int m = idx % MEMD;
    g_wtr[m * KOUT + k] = out_w[idx];
}

// ---------------- kernel 1: pipelined fp16 tensor-core GEMM + fused epilogue ------
__global__ __launch_bounds__(128, 4) void gemm_tc2(
        const float* __restrict__ X,
        const float* __restrict__ curv, const float* __restrict__ ent,
        const float* __restrict__ Wbb,  const float* __restrict__ Wab,
        const float* __restrict__ curv_w, const float* __restrict__ ent_w,
        const float* __restrict__ lnqw, const float* __restrict__ lnqb,
        const float* __restrict__ lnkw, const float* __restrict__ lnkb) {
    extern __shared__ __align__(16) char dsm[];
    unsigned int* As = (unsigned int*)dsm;            // [64][ABS] fp16 pairs
    unsigned int* Bs = As + 64 * ABS;                 // [2 bufs][2][128][ABS]
    float* Cs = (float*)dsm;                          // [64][132] (aliases)

    int tid = threadIdx.x;
    int lane = tid & 31;
    int warp = tid >> 5;
    int wm = warp & 1;
    int wn = warp >> 1;          // 0-1
    int g = lane >> 2;
    int tg = lane & 3;
    int m0 = blockIdx.x * 64;
    int n0 = blockIdx.y * 128;

    unsigned int sb_bs = (unsigned int)__cvta_generic_to_shared(Bs);

    float acc[2][8][4];
#pragma unroll
    for (int mt = 0; mt < 2; mt++)
#pragma unroll
        for (int nt = 0; nt < 8; nt++)
#pragma unroll
            for (int i = 0; i < 4; i++) acc[mt][nt][i] = 0.0f;

    int am = tid >> 3;           // base row; r adds 16 rows
    int aq = tid & 7;

    float4 pa[4];
#pragma unroll
    for (int r = 0; r < 4; r++)
        pa[r] = *(const float4*)(X + (size_t)(m0 + am + 16 * r) * JD + aq * 4);
    {
        unsigned int bbase = sb_bs;
        int n = tid >> 2, cq = tid & 3;
#pragma unroll
        for (int r = 0; r < 4; r++)
            cp_async16(bbase + ((n + 32 * r) * ABS + cq * 4) * 4,
                       g_wh + (n0 + n + 32 * r) * 128 + cq * 4);
#pragma unroll
        for (int r = 0; r < 4; r++)
            cp_async16(bbase + (128 * ABS + (n + 32 * r) * ABS + cq * 4) * 4,
                       g_wl + (n0 + n + 32 * r) * 128 + cq * 4);
        CP_COMMIT();
    }

    for (int kc = 0; kc < 8; kc++) {
#pragma unroll
        for (int r = 0; r < 4; r++) {
            int m = am + 16 * r;
            unsigned int w0 = h2u(__floats2half2_rn(pa[r].x, pa[r].y));
            unsigned int w1 = h2u(__floats2half2_rn(pa[r].z, pa[r].w));
            *(uint2*)(&As[m * ABS + 2 * aq]) = make_uint2(w0, w1);
        }
        if (kc < 7) {
#pragma unroll
            for (int r = 0; r < 4; r++)
                pa[r] = *(const float4*)(X + (size_t)(m0 + am + 16 * r) * JD +
                                         (kc + 1) * 32 + aq * 4);
            unsigned int bbase = sb_bs + ((kc + 1) & 1) * B_BUF_W * 4;
            int n = tid >> 2, cq = tid & 3;
#pragma unroll
            for (int r = 0; r < 4; r++)
                cp_async16(bbase + ((n + 32 * r) * ABS + cq * 4) * 4,
                           g_wh + (n0 + n + 32 * r) * 128 + (kc + 1) * 16 + cq * 4);
#pragma unroll
            for (int r = 0; r < 4; r++)
                cp_async16(bbase + (128 * ABS + (n + 32 * r) * ABS + cq * 4) * 4,
                           g_wl + (n0 + n + 32 * r) * 128 + (kc + 1) * 16 + cq * 4);
            CP_COMMIT();
            CP_WAIT(1);
        } else {
            CP_WAIT(0);
        }
        __syncthreads();

        const unsigned int* Bb = Bs + (kc & 1) * B_BUF_W;
#pragma unroll
        for (int kt = 0; kt < 2; kt++) {
            int c0 = kt * 8 + tg;
            unsigned int ah[2][4];
#pragma unroll
            for (int mt = 0; mt < 2; mt++) {
                int mrow = wm * 32 + mt * 16 + g;
                ah[mt][0] = As[mrow * ABS + c0];
                ah[mt][1] = As[(mrow + 8) * ABS + c0];
                ah[mt][2] = As[mrow * ABS + c0 + 4];
                ah[mt][3] = As[(mrow + 8) * ABS + c0 + 4];
            }
#pragma unroll
            for (int nt = 0; nt < 8; nt++) {
                int ncol = wn * 64 + nt * 8 + g;
                unsigned int bh0 = Bb[ncol * ABS + c0];
                unsigned int bh1 = Bb[ncol * ABS + c0 + 4];
                unsigned int bl0 = Bb[128 * ABS + ncol * ABS + c0];
                unsigned int bl1 = Bb[128 * ABS + ncol * ABS + c0 + 4];
#pragma unroll
                for (int mt = 0; mt < 2; mt++) {
                    mma_f16(acc[mt][nt], ah[mt], bh0, bh1);
                    mma_f16(acc[mt][nt], ah[mt], bl0, bl1);
                }
            }
        }
        __syncthreads();
    }

#pragma unroll
    for (int mt = 0; mt < 2; mt++) {
#pragma unroll
        for (int nt = 0; nt < 8; nt++) {
            int row = wm * 32 + mt * 16 + g;
            int col = wn * 64 + nt * 8 + 2 * tg;
            Cs[row * 132 + col]           = acc[mt][nt][0];
            Cs[row * 132 + col + 1]       = acc[mt][nt][1];
            Cs[(row + 8) * 132 + col]     = acc[mt][nt][2];
            Cs[(row + 8) * 132 + col + 1] = acc[mt][nt][3];
        }
    }
    __syncthreads();

    int tx = tid & 7;
    int ty = tid >> 3;

#pragma unroll
    for (int rr = 0; rr < 4; rr++) {
        int row = ty * 4 + rr;
        int mtok = m0 + row;
        int n = mtok >> 11, t = mtok & 2047;
        const float* crow = Cs + row * 132 + tx * 16;

        if (blockIdx.y == 0) {
            float y[16];
            *(float4*)&y[0]  = *(const float4*)(crow + 0);
            *(float4*)&y[4]  = *(const float4*)(crow + 4);
            *(float4*)&y[8]  = *(const float4*)(crow + 8);
            *(float4*)&y[12] = *(const float4*)(crow + 12);
#pragma unroll
            for (int i = 0; i < 16; i++) y[i] *= DESC;
            float s = 0.0f;
#pragma unroll
            for (int i = 0; i < 16; i++) s += y[i];
            float mean = s * 0.0625f;
            float var = 0.0f;
#pragma unroll
            for (int i = 0; i < 16; i++) { float d = y[i] - mean; var = fmaf(d, d, var); }
            var *= 0.0625f;
            float inv = rsqrtf(var + EPS_LN);
            if (tx < 4) {
#pragma unroll
                for (int i = 0; i < 16; i++)
                    y[i] = fmaf((y[i] - mean) * inv, __ldg(lnqw + i), __ldg(lnqb + i));
                size_t base = ((size_t)(n * NH + tx) * SEQ_T + t) * DH;
                *(float4*)(g_q + base + 0)  = *(float4*)&y[0];
                *(float4*)(g_q + base + 4)  = *(float4*)&y[4];
                *(float4*)(g_q + base + 8)  = *(float4*)&y[8];
                *(float4*)(g_q + base + 12) = *(float4*)&y[12];
            } else {
                int h = tx - 4;
#pragma unroll
                for (int i = 0; i < 16; i++)
                    y[i] = fmaf((y[i] - mean) * inv, __ldg(lnkw + i), __ldg(lnkb + i));
                float nrm = 0.0f;
#pragma unroll
                for (int i = 0; i < 16; i++) nrm = fmaf(y[i], y[i], nrm);
                float rinv = 1.0f / fmaxf(sqrtf(nrm), 1e-12f);
#pragma unroll
                for (int i = 0; i < 16; i++) y[i] *= rinv;
                size_t base = ((size_t)(n * NH + h) * SEQ_T + t) * DH;
                *(float4*)(g_k + base + 0)  = *(float4*)&y[0];
                *(float4*)(g_k + base + 4)  = *(float4*)&y[4];
                *(float4*)(g_k + base + 8)  = *(float4*)&y[8];
                *(float4*)(g_k + base + 12) = *(float4*)&y[12];
            }
        } else {
            if (tx < 4) {
                float y[16];
                *(float4*)&y[0]  = *(const float4*)(crow + 0);
                *(float4*)&y[4]  = *(const float4*)(crow + 4);
                *(float4*)&y[8]  = *(const float4*)(crow + 8);
                *(float4*)&y[12] = *(const float4*)(crow + 12);
#pragma unroll
                for (int i = 0; i < 16; i++) y[i] *= DESC;
                size_t base = ((size_t)(n * NH + tx) * SEQ_T + t) * DH;
                *(float4*)(g_v + base + 0)  = *(float4*)&y[0];
                *(float4*)(g_v + base + 4)  = *(float4*)&y[4];
                *(float4*)(g_v + base + 8)  = *(float4*)&y[8];
                *(float4*)(g_v + base + 12) = *(float4*)&y[12];
            } else if (tx == 4) {
                float y[8];
                *(float4*)&y[0] = *(const float4*)(crow + 0);
                *(float4*)&y[4] = *(const float4*)(crow + 4);
#pragma unroll
                for (int i = 0; i < 8; i++) y[i] *= DESC;
                int b = n >> 4;
                float Kv = fminf(fabsf(__ldg(curv + b)), 10.0f);
                float Sv = fminf(fmaxf(__ldg(ent + b), 0.0f), 5.0f);
#pragma unroll
                for (int h = 0; h < 4; h++) {
                    float be = sigm(y[h] + __ldg(Wbb + h));
                    be = sigm(fmaf(Kv, __ldg(curv_w + h), be));
                    float al = sigm(y[4 + h] + __ldg(Wab + h));
                    al = sigm(fmaf(Sv, __ldg(ent_w + h), al));
                    g_beta[(n * NH + h) * SEQ_T + t] = be;
                    g_alpha[(n * NH + h) * SEQ_T + t] = al;
                }
            }
        }
    }
}

// ---------------- kernel 2a: chunked scan phase1 ----------------
__global__ __launch_bounds__(128) void scan_phase1() {
    __shared__ float sk[8][512];
    __shared__ float sv[8][512];
    __shared__ float sb[8][32];
    __shared__ float sa[8][32];

    int warp = threadIdx.x >> 5;
    int lane = threadIdx.x & 31;
    int g = lane >> 4;
    int row = lane & 15;
    int wg = warp * 2 + g;
    int grp = blockIdx.x * 8 + wg;

    unsigned long long P[8], R[8];
#pragma unroll
    for (int j = 0; j < 8; j++) { P[j] = 0ull; R[j] = 0ull; }
    P[row >> 1] = (row & 1) ? pack2(0.0f, 1.0f) : pack2(1.0f, 0.0f);

    for (int sub = 0; sub < CH / 32; sub++) {
        __syncwarp();
#pragma unroll
        for (int r = 0; r < 8; r++) {
            int f = lane + 32 * r;
            int gg = f >> 7;
            int e = f & 127;
            int grp2 = blockIdx.x * 8 + warp * 2 + gg;
            int rec2 = grp2 >> 4, ch2 = grp2 & 15;
            size_t base4 = ((size_t)rec2 * SEQ_T + ch2 * CH + sub * 32) * 4;
            ((float4*)sk[warp * 2 + gg])[e] = ((const float4*)g_k)[base4 + e];
            ((float4*)sv[warp * 2 + gg])[e] = ((const float4*)g_v)[base4 + e];
        }
#pragma unroll
        for (int r = 0; r < 2; r++) {
            int f = lane + 32 * r;
            int gg = f >> 5;
            int e = f & 31;
            int grp2 = blockIdx.x * 8 + warp * 2 + gg;
            int rec2 = grp2 >> 4, ch2 = grp2 & 15;
            int src = rec2 * SEQ_T + ch2 * CH + sub * 32 + e;
            sb[warp * 2 + gg][e] = g_beta[src];
            sa[warp * 2 + gg][e] = g_alpha[src];
        }
        __syncwarp();

        for (int s = 0; s < 32; s++) {
            unsigned long long kp[8];
            const unsigned long long* kptr = (const unsigned long long*)&sk[wg][s * 16];
#pragma unroll
            for (int j = 0; j < 8; j++) kp[j] = kptr[j];
            float vi = sv[wg][s * 16 + row];
            float be = sb[wg][s];
            float al = sa[wg][s];

            float u = dot16(P, kp);
            float w = dot16(R, kp);
            unsigned long long cu = dup2(-al * u);
            unsigned long long cr = dup2(fmaf(be, vi, -al * w));
#pragma unroll
            for (int j = 0; j < 8; j++) {
                fma2(P[j], cu, kp[j]);
                fma2(R[j], cr, kp[j]);
            }
        }
    }

    size_t obase = ((size_t)grp * 16 + row) * 16;
    unsigned long long* gp = (unsigned long long*)(g_P + obase);
    unsigned long long* gr = (unsigned long long*)(g_R + obase);
#pragma unroll
    for (int j = 0; j < 8; j++) { gp[j] = P[j]; gr[j] = R[j]; }
}

// ---------------- kernel 2b: serial combine ----------------
__global__ __launch_bounds__(128) void scan_combine() {
    __shared__ float sp[8][256];
    __shared__ float sr[8][256];

    int warp = threadIdx.x >> 5;
    int lane = threadIdx.x & 31;
    int g = lane >> 4;
    int row = lane & 15;
    int wg = warp * 2 + g;
    int rec = blockIdx.x * 8 + wg;

    unsigned long long S[8];
#pragma unroll
    for (int j = 0; j < 8; j++) S[j] = 0ull;

    for (int c = 0; c < NCH; c++) {
        size_t sbase = (((size_t)rec * NCH + c) * 16 + row) * 16;
        unsigned long long* gs = (unsigned long long*)(g_S + sbase);
#pragma unroll
        for (int j = 0; j < 8; j++) gs[j] = S[j];

        __syncwarp();
#pragma unroll
        for (int r = 0; r < 4; r++) {
            int f = lane + 32 * r;
            int gg = f >> 6;
            int e = f & 63;
            int rec2 = blockIdx.x * 8 + warp * 2 + gg;
            size_t base4 = ((size_t)rec2 * NCH + c) * 64;
            ((float4*)sp[warp * 2 + gg])[e] = ((const float4*)g_P)[base4 + e];
            ((float4*)sr[warp * 2 + gg])[e] = ((const float4*)g_R)[base4 + e];
        }
        __syncwarp();

        unsigned long long accm[8];
        const unsigned long long* rrow = (const unsigned long long*)&sr[wg][row * 16];
#pragma unroll
        for (int j = 0; j < 8; j++) accm[j] = rrow[j];
#pragma unroll
        for (int l = 0; l < 16; l++) {
            float sl = (l & 1) ? hi32(S[l >> 1]) : lo32(S[l >> 1]);
            unsigned long long sd = dup2(sl);
            const unsigned long long* prow = (const unsigned long long*)&sp[wg][l * 16];
#pragma unroll
            for (int j = 0; j < 8; j++) fma2(accm[j], sd, prow[j]);
        }
#pragma unroll
        for (int j = 0; j < 8; j++) S[j] = accm[j];
    }
}

// ---------------- kernel 2c: chunked scan phase3 ----------------
__global__ __launch_bounds__(128) void scan_phase3() {
    __shared__ float sk[8][512];
    __shared__ float sq[8][512];
    __shared__ float sv[8][512];
    __shared__ float sb[8][32];
    __shared__ float sa[8][32];

    int warp = threadIdx.x >> 5;
    int lane = threadIdx.x & 31;
    int g = lane >> 4;
    int row = lane & 15;
    int wg = warp * 2 + g;
    int grp = blockIdx.x * 8 + wg;

    unsigned long long M[8];
    {
        size_t sbase = ((size_t)grp * 16 + row) * 16;
        const unsigned long long* gs = (const unsigned long long*)(g_S + sbase);
#pragma unroll
        for (int j = 0; j < 8; j++) M[j] = gs[j];
    }

    for (int sub = 0; sub < CH / 32; sub++) {
        __syncwarp();
#pragma unroll
        for (int r = 0; r < 8; r++) {
            int f = lane + 32 * r;
            int gg = f >> 7;
            int e = f & 127;
            int grp2 = blockIdx.x * 8 + warp * 2 + gg;
            int rec2 = grp2 >> 4, ch2 = grp2 & 15;
            size_t base4 = ((size_t)rec2 * SEQ_T + ch2 * CH + sub * 32) * 4;
            ((float4*)sk[warp * 2 + gg])[e] = ((const float4*)g_k)[base4 + e];
            ((float4*)sq[warp * 2 + gg])[e] = ((const float4*)g_q)[base4 + e];
            ((float4*)sv[warp * 2 + gg])[e] = ((const float4*)g_v)[base4 + e];
        }
#pragma unroll
        for (int r = 0; r < 2; r++) {
            int f = lane + 32 * r;
            int gg = f >> 5;
            int e = f & 31;
            int grp2 = blockIdx.x * 8 + warp * 2 + gg;
            int rec2 = grp2 >> 4, ch2 = grp2 & 15;
            int src = rec2 * SEQ_T + ch2 * CH + sub * 32 + e;
            sb[warp * 2 + gg][e] = g_beta[src];
            sa[warp * 2 + gg][e] = g_alpha[src];
        }
        __syncwarp();

        for (int s = 0; s < 32; s++) {
            unsigned long long kp[8], qp[8];
            const unsigned long long* kptr = (const unsigned long long*)&sk[wg][s * 16];
            const unsigned long long* qptr = (const unsigned long long*)&sq[wg][s * 16];
#pragma unroll
            for (int j = 0; j < 8; j++) { kp[j] = kptr[j]; qp[j] = qptr[j]; }
            float vi = sv[wg][s * 16 + row];
            float be = sb[wg][s];
            float al = sa[wg][s];

            float mk = dot16(M, kp);
            unsigned long long cd = dup2(fmaf(be, vi, -al * mk));
#pragma unroll
            for (int j = 0; j < 8; j++) fma2(M[j], cd, kp[j]);
            float o = dot16(M, qp);
            sv[wg][s * 16 + row] = o;
        }
        __syncwarp();
#pragma unroll
        for (int r = 0; r < 8; r++) {
            int f = lane + 32 * r;
            int gg = f >> 7;
            int e = f & 127;
            int grp2 = blockIdx.x * 8 + warp * 2 + gg;
            int rec2 = grp2 >> 4, ch2 = grp2 & 15;
            size_t base4 = ((size_t)rec2 * SEQ_T + ch2 * CH + sub * 32) * 4;
            ((float4*)g_o)[base4 + e] = ((const float4*)sv[warp * 2 + gg])[e];
        }
    }
}

// ---------------- kernel 4: register-tiled output projection ----------------
// Block: one n, 64 t's. 256 threads: tx (0-31) -> 6 k's, ty (0-7) -> 8 t's.
// acc[8 t][3 k-pairs] f32x2. w staged [m][k] (192 stride), o restaged [m][t].
__global__ __launch_bounds__(256) void final_proj(const float* __restrict__ out_b,
                                                  float* __restrict__ out) {
    extern __shared__ __align__(16) float fsm[];
    float* sw = fsm;                       // [64][192]
    float* so = fsm + 64 * 192;            // [64][FP_SOW] (m-major, t inner)

    int tid = threadIdx.x;
    int tx = tid & 31;
    int ty = tid >> 5;
    int n = blockIdx.x;
    int t0 = blockIdx.y * FP_TT;
    int b = n >> 4;
    int p = n & 15;

    // stage w: 64 rows x 192 (rows of 64 threads x 3 chunks)
    {
        int rr = tid >> 6;          // 0-3
        int cc = tid & 63;
#pragma unroll
        for (int m = 0; m < 16; m++) {
            int mr = m * 4 + rr;
#pragma unroll
            for (int j = 0; j < 3; j++)
                sw[mr * 192 + cc + 64 * j] = g_wtr[mr * 192 + cc + 64 * j];
        }
    }
    // stage so[m][t'] from g_o
#pragma unroll
    for (int r = 0; r < 16; r++) {
        int e = tid + 256 * r;              // [0,4096)
        int i = e & 15;
        int tt = (e >> 4) & 63;
        int h = e >> 10;
        so[(h * 16 + i) * FP_SOW + tt] =
            g_o[((size_t)(n * NH + h) * SEQ_T + t0 + tt) * DH + i];
    }
    __syncthreads();

    unsigned long long acc[8][3];
#pragma unroll
    for (int t = 0; t < 8; t++)
#pragma unroll
        for (int kp = 0; kp < 3; kp++) acc[t][kp] = 0ull;

#pragma unroll 4
    for (int m = 0; m < 64; m++) {
        const unsigned long long* wp = (const unsigned long long*)(sw + m * 192 + tx * 6);
        unsigned long long w0 = wp[0], w1 = wp[1], w2 = wp[2];
        const float* sop = so + m * FP_SOW + ty * 8;
#pragma unroll
        for (int t = 0; t < 8; t++) {
            unsigned long long sd = dup2(sop[t]);
            fma2(acc[t][0], sd, w0);
            fma2(acc[t][1], sd, w1);
            fma2(acc[t][2], sd, w2);
        }
    }

    // bias + store (k pairs adjacent -> float2 stores, coalesced across tx)
    float2 bias[3];
#pragma unroll
    for (int j = 0; j < 3; j++)
        bias[j] = *(const float2*)(out_b + tx * 6 + 2 * j);
#pragma unroll
    for (int t = 0; t < 8; t++) {
        int tt = t0 + ty * 8 + t;
        float* op = out + (((size_t)b * SEQ_T + tt) * N_P + p) * KOUT + tx * 6;
#pragma unroll
        for (int j = 0; j < 3; j++) {
            float2 v = make_float2(lo32(acc[t][j]) + bias[j].x,
                                   hi32(acc[t][j]) + bias[j].y);
            *(float2*)(op + 2 * j) = v;
        }
    }
}

// ---------------- launch ----------------
extern "C" void kernel_launch(void* const* d_in, const int* in_sizes, int n_in,
                              void* d_out, int out_size) {
    const float* joint  = (const float*)d_in[0];
    const float* curvat = (const float*)d_in[1];
    const float* entrop = (const float*)d_in[2];
    const float* Wq     = (const float*)d_in[3];
    const float* Wk     = (const float*)d_in[4];
    const float* Wv     = (const float*)d_in[5];
    const float* Wbw    = (const float*)d_in[6];
    const float* Wbb    = (const float*)d_in[7];
    const float* Waw    = (const float*)d_in[8];
    const float* Wab    = (const float*)d_in[9];
    const float* curv_w = (const float*)d_in[10];
    const float* ent_w  = (const float*)d_in[11];
    const float* out_w  = (const float*)d_in[12];
    const float* out_b  = (const float*)d_in[13];
    const float* lnqw   = (const float*)d_in[14];
    const float* lnqb   = (const float*)d_in[15];
    const float* lnkw   = (const float*)d_in[16];
    const float* lnkb   = (const float*)d_in[17];
    float* out = (float*)d_out;

    cudaFuncSetAttribute(gemm_tc2, cudaFuncAttributeMaxDynamicSharedMemorySize,
                         GEMM_SMEM);
    cudaFuncSetAttribute(final_proj, cudaFuncAttributeMaxDynamicSharedMemorySize,
                         FP_SMEM);

    constexpr int OW_HALF = KOUT * MEMD / 2;
    pack_wbf<<<(256 * 128 + 255) / 256, 256>>>(Wq, Wk, Wv, Wbw, Waw);
    pack_outw<<<(OW_HALF + 255) / 256, 256>>>(out_w, 0);
    pack_outw<<<(OW_HALF + 255) / 256, 256>>>(out_w, OW_HALF);
    gemm_tc2<<<dim3(NT / 64, 2), 128, GEMM_SMEM>>>(joint, curvat, entrop, Wbb, Wab,
                                                   curv_w, ent_w, lnqw, lnqb,
                                                   lnkw, lnkb);
    scan_phase1<<<NGRP / 8, 128>>>();
    scan_combine<<<NREC / 8, 128>>>();
    scan_phase3<<<NGRP / 8, 128>>>();
    final_proj<<<dim3(NSEQ, SEQ_T / FP_TT), 256, FP_SMEM>>>(out_b, out);
}